// round 5
// baseline (speedup 1.0000x reference)
#include <cuda_runtime.h>
#include <cstdint>

// Problem constants
#define NH   8
#define DM   512
#define FFD  2048
#define BB   8
#define TT   512
#define SS   1024
#define LAYER 5

// ---------------- scratch (device globals) ------------------------------------
__device__ float g_n  [BB*TT*DM];
__device__ float g_q  [BB*TT*DM];
__device__ float g_k  [BB*SS*DM];
__device__ float g_v  [BB*SS*DM];
__device__ float g_vt [DM*BB*SS];            // transposed V  [D][B*S]
__device__ float g_at [BB*TT*DM];
__device__ float g_x  [BB*TT*DM];
__device__ float g_ff [BB*TT*FFD];           // FFN hidden; early reuse: rounded memory
__device__ float g_wt [8*DM*DM];             // 8 transposed 512x512 weights
__device__ float g_w1t[FFD*DM];              // [2048][512]
__device__ float g_w2t[DM*FFD];              // [512][2048]

// ---------------- helpers ------------------------------------------------------
__device__ __forceinline__ uint32_t smem_u32(const void* p) {
    uint32_t a;
    asm("{ .reg .u64 t; cvta.to.shared.u64 t, %1; cvt.u32.u64 %0, t; }" : "=r"(a) : "l"(p));
    return a;
}
__device__ __forceinline__ uint32_t f2tf(float f) {
    uint32_t u;
    asm("cvt.rna.tf32.f32 %0, %1;" : "=r"(u) : "f"(f));
    return u;
}
__device__ __forceinline__ float rnd_tf(float f) { return __uint_as_float(f2tf(f)); }

#define CP16(dst, src) \
    asm volatile("cp.async.cg.shared.global [%0], [%1], 16;" :: "r"(dst), "l"(src))
#define CP_COMMIT() asm volatile("cp.async.commit_group;" ::: "memory")
#define CP_WAIT1()  asm volatile("cp.async.wait_group 1;" ::: "memory")
#define CP_WAIT0()  asm volatile("cp.async.wait_group 0;" ::: "memory")

#define MMA_TF32(c, a, b) \
    asm volatile("mma.sync.aligned.m16n8k8.row.col.f32.tf32.tf32.f32 " \
        "{%0,%1,%2,%3}, {%4,%5,%6,%7}, {%8,%9}, {%0,%1,%2,%3};" \
        : "+f"((c)[0]), "+f"((c)[1]), "+f"((c)[2]), "+f"((c)[3]) \
        : "r"((a)[0]), "r"((a)[1]), "r"((a)[2]), "r"((a)[3]), "r"((b)[0]), "r"((b)[1]))

// swizzled smem word index for a [rows][32] panel
__device__ __forceinline__ int swz(int r, int c) {
    return r * 32 + ((((c >> 2) ^ (r & 7)) << 2) | (c & 3));
}

// ============ mma.sync tf32 GEMM ===============================================
// Inputs A and B are PRE-ROUNDED tf32 bits stored as float.
// C = epi( A[M,K] @ B[N,K]^T );  EPI: 0=+bias 1=relu(+bias) 2=+bias+res
// RND: round stored C to tf32 (when C feeds another MMA).
template<int BN, int EPI, int RND>
__global__ __launch_bounds__(256) void mma_gemm(
    const float* __restrict__ A, int lda,
    const float* __restrict__ B, int ldb,
    const float* __restrict__ bias, const float* __restrict__ res,
    float* __restrict__ C, int ldc, int K)
{
    constexpr int WTM = 64;
    constexpr int MW  = 2;
    constexpr int MF  = WTM / 16;
    constexpr int NF  = 4;

    const int m0 = blockIdx.y * 128;
    const int n0 = blockIdx.x * BN;

    extern __shared__ float smem[];
    float* bufA[2] = { smem,            smem + 128 * 32 };
    float* bufB[2] = { smem + 2*128*32, smem + 2*128*32 + BN * 32 };
    const uint32_t uA[2] = { smem_u32(bufA[0]), smem_u32(bufA[1]) };
    const uint32_t uB[2] = { smem_u32(bufB[0]), smem_u32(bufB[1]) };

    const int tid  = threadIdx.x;
    const int lane = tid & 31;
    const int wid  = tid >> 5;
    const int wm   = wid & (MW - 1);
    const int wn   = wid / MW;
    const int laneR = lane >> 2, laneC = lane & 3;

    const int nch = K >> 5;

    auto load_chunk = [&](int c) {
        const int buf = c & 1;
        const int k0 = c << 5;
#pragma unroll
        for (int i = 0; i < 4; i++) {
            int idx = tid + i * 256; int r = idx >> 3, f = idx & 7;
            CP16(uA[buf] + r * 128 + ((f ^ (r & 7)) << 4),
                 A + (size_t)(m0 + r) * lda + k0 + f * 4);
        }
#pragma unroll
        for (int i = 0; i < BN / 32; i++) {
            int idx = tid + i * 256; int r = idx >> 3, f = idx & 7;
            CP16(uB[buf] + r * 128 + ((f ^ (r & 7)) << 4),
                 B + (size_t)(n0 + r) * ldb + k0 + f * 4);
        }
        CP_COMMIT();
    };

    float acc[MF][NF][4] = {};

    load_chunk(0);
    for (int c = 0; c < nch; c++) {
        if (c + 1 < nch) { load_chunk(c + 1); CP_WAIT1(); }
        else             { CP_WAIT0(); }
        __syncthreads();
        const uint32_t* sA = (const uint32_t*)bufA[c & 1];
        const uint32_t* sB = (const uint32_t*)bufB[c & 1];
#pragma unroll
        for (int ks = 0; ks < 4; ks++) {
            uint32_t af[MF][4];
#pragma unroll
            for (int mf = 0; mf < MF; mf++) {
                int r = wm * WTM + mf * 16 + laneR;
                int cc = ks * 8 + laneC;
                af[mf][0] = sA[swz(r,     cc)];
                af[mf][1] = sA[swz(r + 8, cc)];
                af[mf][2] = sA[swz(r,     cc + 4)];
                af[mf][3] = sA[swz(r + 8, cc + 4)];
            }
            uint32_t bf[NF][2];
#pragma unroll
            for (int nf = 0; nf < NF; nf++) {
                int n = wn * 32 + nf * 8 + laneR;
                int cc = ks * 8 + laneC;
                bf[nf][0] = sB[swz(n, cc)];
                bf[nf][1] = sB[swz(n, cc + 4)];
            }
#pragma unroll
            for (int mf = 0; mf < MF; mf++)
#pragma unroll
                for (int nf = 0; nf < NF; nf++)
                    MMA_TF32(acc[mf][nf], af[mf], bf[nf]);
        }
        __syncthreads();
    }

#pragma unroll
    for (int mf = 0; mf < MF; mf++) {
#pragma unroll
        for (int nf = 0; nf < NF; nf++) {
            int r  = m0 + wm * WTM + mf * 16 + laneR;
            int cc = n0 + wn * 32 + nf * 8 + laneC * 2;
            float v0 = acc[mf][nf][0], v1 = acc[mf][nf][1];
            float v2 = acc[mf][nf][2], v3 = acc[mf][nf][3];
            float2 bb = *(const float2*)(bias + cc);
            v0 += bb.x; v1 += bb.y; v2 += bb.x; v3 += bb.y;
            if (EPI == 1) {
                v0 = fmaxf(v0, 0.f); v1 = fmaxf(v1, 0.f);
                v2 = fmaxf(v2, 0.f); v3 = fmaxf(v3, 0.f);
            }
            if (EPI == 2) {
                float2 r0 = *(const float2*)(res + (size_t)r * ldc + cc);
                float2 r1 = *(const float2*)(res + (size_t)(r + 8) * ldc + cc);
                v0 += r0.x; v1 += r0.y; v2 += r1.x; v3 += r1.y;
            }
            if (RND) {
                v0 = rnd_tf(v0); v1 = rnd_tf(v1);
                v2 = rnd_tf(v2); v3 = rnd_tf(v3);
            }
            *(float2*)(C + (size_t)r * ldc + cc)       = make_float2(v0, v1);
            *(float2*)(C + (size_t)(r + 8) * ldc + cc) = make_float2(v2, v3);
        }
    }
}

// ============ fused flash attention (tf32 mma, online softmax) =================
// Q/K pre-rounded tf32 in gmem; Vt pre-rounded transposed V [512][B*S].
template<int CAUSAL>
__global__ __launch_bounds__(256) void flash_attn(
    const float* __restrict__ Q, const float* __restrict__ Kg,
    const float* __restrict__ Vt, float* __restrict__ O, int Slen)
{
    extern __shared__ float sm[];
    float* sQ = sm;                 // 2 panels x 128x32
    float* sK = sm + 8192;
    float* sV = sm + 16384;
    float* sP = sm + 24576;

    const int mt = blockIdx.x, bh = blockIdx.y;
    const int b = bh >> 3, h = bh & 7;
    const int m0 = mt * 128;
    const int tid = threadIdx.x, lane = tid & 31, wid = tid >> 5;
    const int laneR = lane >> 2, laneC = lane & 3;

    const float* Qp = Q + ((size_t)b * TT + m0) * DM + h * 64;
    const float* Kp = Kg + (size_t)b * Slen * DM + h * 64;
    const float* Vp = Vt + (size_t)(h * 64) * (BB * Slen) + (size_t)b * Slen;
    float* Op = O + ((size_t)b * TT + m0) * DM + h * 64;

    const uint32_t uQ = smem_u32(sQ), uK = smem_u32(sK), uV = smem_u32(sV);

#pragma unroll
    for (int i = 0; i < 8; i++) {
        int idx = tid + i * 256;
        int r = idx >> 4, f = idx & 15;
        int panel = f >> 3, fo = f & 7;
        CP16(uQ + (panel * 4096 + r * 32 + ((fo ^ (r & 7)) << 2)) * 4,
             Qp + (size_t)r * DM + f * 4);
    }

    auto load_kv = [&](int c) {
        const int buf = c & 1;
        const int s0 = c * 64;
#pragma unroll
        for (int i = 0; i < 4; i++) {
            int idx = tid + i * 256;
            int r = idx >> 4, f = idx & 15;
            int panel = f >> 3, fo = f & 7;
            CP16(uK + (buf * 4096 + panel * 2048 + r * 32 + ((fo ^ (r & 7)) << 2)) * 4,
                 Kp + (size_t)(s0 + r) * DM + f * 4);
        }
#pragma unroll
        for (int i = 0; i < 4; i++) {
            int idx = tid + i * 256;
            int r = idx >> 4, f = idx & 15;
            int panel = f >> 3, fo = f & 7;
            CP16(uV + (buf * 4096 + panel * 2048 + r * 32 + ((fo ^ (r & 7)) << 2)) * 4,
                 Vp + (size_t)r * (BB * Slen) + s0 + f * 4);
        }
        CP_COMMIT();
    };

    const int nch = CAUSAL ? (m0 + 128) / 64 : Slen / 64;
    const int wr0 = wid * 16;
    float mr0 = -1e30f, mr1 = -1e30f, l0 = 0.f, l1 = 0.f;
    float oacc[8][4] = {};
    float* sPw = sP + wid * 1024;

    load_kv(0);
    for (int c = 0; c < nch; c++) {
        if (c + 1 < nch) { load_kv(c + 1); CP_WAIT1(); }
        else             { CP_WAIT0(); }
        __syncthreads();
        const int s0 = c * 64;
        const bool active = !CAUSAL || (s0 <= m0 + wr0 + 15);
        if (active) {
            const uint32_t* cK = (const uint32_t*)(sK + (c & 1) * 4096);
            const uint32_t* cV = (const uint32_t*)(sV + (c & 1) * 4096);
            const uint32_t* uQw = (const uint32_t*)sQ;

            // ---- S = Q @ K^T ----
            float sacc[8][4] = {};
#pragma unroll
            for (int ks = 0; ks < 8; ks++) {
                int kk = ks * 8 + laneC;
                int pa = kk >> 5, ca = kk & 31;
                uint32_t af[4];
                {
                    const uint32_t* qp = uQw + pa * 4096;
                    int r0 = wr0 + laneR;
                    af[0] = qp[swz(r0,     ca)];
                    af[1] = qp[swz(r0 + 8, ca)];
                    af[2] = qp[swz(r0,     ca + 4)];
                    af[3] = qp[swz(r0 + 8, ca + 4)];
                }
                const uint32_t* kp = cK + pa * 2048;
#pragma unroll
                for (int nf = 0; nf < 8; nf++) {
                    uint32_t bf[2];
                    int n = nf * 8 + laneR;
                    bf[0] = kp[swz(n, ca)];
                    bf[1] = kp[swz(n, ca + 4)];
                    MMA_TF32(sacc[nf], af, bf);
                }
            }

            // ---- scale + mask + online softmax ----
            const float SCL = 0.125f;
            const int t0g = m0 + wr0 + laneR;
            float rmax0 = -1e30f, rmax1 = -1e30f;
#pragma unroll
            for (int nf = 0; nf < 8; nf++) {
                int sg = s0 + nf * 8 + 2 * laneC;
                float v0 = sacc[nf][0] * SCL, v1 = sacc[nf][1] * SCL;
                float v2 = sacc[nf][2] * SCL, v3 = sacc[nf][3] * SCL;
                if (CAUSAL) {
                    if (sg     > t0g)     v0 = -1e30f;
                    if (sg + 1 > t0g)     v1 = -1e30f;
                    if (sg     > t0g + 8) v2 = -1e30f;
                    if (sg + 1 > t0g + 8) v3 = -1e30f;
                }
                sacc[nf][0] = v0; sacc[nf][1] = v1;
                sacc[nf][2] = v2; sacc[nf][3] = v3;
                rmax0 = fmaxf(rmax0, fmaxf(v0, v1));
                rmax1 = fmaxf(rmax1, fmaxf(v2, v3));
            }
            rmax0 = fmaxf(rmax0, __shfl_xor_sync(0xffffffffu, rmax0, 1));
            rmax0 = fmaxf(rmax0, __shfl_xor_sync(0xffffffffu, rmax0, 2));
            rmax1 = fmaxf(rmax1, __shfl_xor_sync(0xffffffffu, rmax1, 1));
            rmax1 = fmaxf(rmax1, __shfl_xor_sync(0xffffffffu, rmax1, 2));
            float mn0 = fmaxf(mr0, rmax0), mn1 = fmaxf(mr1, rmax1);
            float al0 = __expf(mr0 - mn0), al1 = __expf(mr1 - mn1);
            mr0 = mn0; mr1 = mn1;

            float rs0 = 0.f, rs1 = 0.f;
            uint32_t* sPu = (uint32_t*)sPw;
#pragma unroll
            for (int nf = 0; nf < 8; nf++) {
                float e0 = __expf(sacc[nf][0] - mn0);
                float e1 = __expf(sacc[nf][1] - mn0);
                float e2 = __expf(sacc[nf][2] - mn1);
                float e3 = __expf(sacc[nf][3] - mn1);
                rs0 += e0 + e1; rs1 += e2 + e3;
                int cc = nf * 8 + 2 * laneC;
                int pa = cc >> 5, ca = cc & 31;
                *(uint2*)&sPu[pa * 512 + swz(laneR,     ca)] = make_uint2(f2tf(e0), f2tf(e1));
                *(uint2*)&sPu[pa * 512 + swz(laneR + 8, ca)] = make_uint2(f2tf(e2), f2tf(e3));
            }
            rs0 += __shfl_xor_sync(0xffffffffu, rs0, 1);
            rs0 += __shfl_xor_sync(0xffffffffu, rs0, 2);
            rs1 += __shfl_xor_sync(0xffffffffu, rs1, 1);
            rs1 += __shfl_xor_sync(0xffffffffu, rs1, 2);
            l0 = l0 * al0 + rs0;
            l1 = l1 * al1 + rs1;
#pragma unroll
            for (int nf = 0; nf < 8; nf++) {
                oacc[nf][0] *= al0; oacc[nf][1] *= al0;
                oacc[nf][2] *= al1; oacc[nf][3] *= al1;
            }
            __syncwarp();

            // ---- O += P @ V ----
#pragma unroll
            for (int ks = 0; ks < 8; ks++) {
                int kk = ks * 8 + laneC;
                int pa = kk >> 5, ca = kk & 31;
                uint32_t af[4];
                const uint32_t* pp = sPu + pa * 512;
                af[0] = pp[swz(laneR,     ca)];
                af[1] = pp[swz(laneR + 8, ca)];
                af[2] = pp[swz(laneR,     ca + 4)];
                af[3] = pp[swz(laneR + 8, ca + 4)];
                const uint32_t* vp = cV + pa * 2048;
#pragma unroll
                for (int nf = 0; nf < 8; nf++) {
                    uint32_t bf[2];
                    int n = nf * 8 + laneR;
                    bf[0] = vp[swz(n, ca)];
                    bf[1] = vp[swz(n, ca + 4)];
                    MMA_TF32(oacc[nf], af, bf);
                }
            }
        }
        __syncthreads();
    }

    const float inv0 = 1.f / l0, inv1 = 1.f / l1;
#pragma unroll
    for (int nf = 0; nf < 8; nf++) {
        int cc = nf * 8 + 2 * laneC;
        int r = wr0 + laneR;
        *(float2*)(Op + (size_t)r * DM + cc) =
            make_float2(rnd_tf(oacc[nf][0] * inv0), rnd_tf(oacc[nf][1] * inv0));
        *(float2*)(Op + (size_t)(r + 8) * DM + cc) =
            make_float2(rnd_tf(oacc[nf][2] * inv1), rnd_tf(oacc[nf][3] * inv1));
    }
}

// ---------------- transpose kernels (round to tf32 at store) -------------------
__global__ __launch_bounds__(256) void transpose_one(
    const float* __restrict__ src, float* __restrict__ dst, int R, int C)
{
    __shared__ float t[32][33];
    int tx = threadIdx.x, ty = threadIdx.y;
    int x = blockIdx.x * 32 + tx;
    int y = blockIdx.y * 32;
#pragma unroll
    for (int i = 0; i < 4; i++)
        t[ty + i * 8][tx] = src[(size_t)(y + ty + i * 8) * C + x];
    __syncthreads();
    int x2 = blockIdx.y * 32 + tx;
    int y2 = blockIdx.x * 32;
#pragma unroll
    for (int i = 0; i < 4; i++)
        dst[(size_t)(y2 + ty + i * 8) * R + x2] = rnd_tf(t[tx][ty + i * 8]);
}

struct TP8 { const float* s[8]; float* d[8]; };
__global__ __launch_bounds__(256) void transpose8(TP8 p)
{
    __shared__ float t[32][33];
    const float* src = p.s[blockIdx.z];
    float* dst = p.d[blockIdx.z];
    int tx = threadIdx.x, ty = threadIdx.y;
    int x = blockIdx.x * 32 + tx;
    int y = blockIdx.y * 32;
#pragma unroll
    for (int i = 0; i < 4; i++)
        t[ty + i * 8][tx] = src[(size_t)(y + ty + i * 8) * DM + x];
    __syncthreads();
    int x2 = blockIdx.y * 32 + tx;
    int y2 = blockIdx.x * 32;
#pragma unroll
    for (int i = 0; i < 4; i++)
        dst[(size_t)(y2 + ty + i * 8) * DM + x2] = rnd_tf(t[tx][ty + i * 8]);
}

// ---------------- tf32 round-copy ----------------------------------------------
__global__ __launch_bounds__(256) void round_copy(
    const float* __restrict__ src, float* __restrict__ dst, int n4)
{
    int i = blockIdx.x * 256 + threadIdx.x;
    if (i < n4) {
        float4 v = ((const float4*)src)[i];
        v.x = rnd_tf(v.x); v.y = rnd_tf(v.y);
        v.z = rnd_tf(v.z); v.w = rnd_tf(v.w);
        ((float4*)dst)[i] = v;
    }
}

// ---------------- LayerNorm ---------------------------------------------------
template<int RND>
__global__ __launch_bounds__(128) void ln_kernel(
    const float* __restrict__ x, const float* __restrict__ g,
    const float* __restrict__ b, float* __restrict__ out)
{
    int row = blockIdx.x;
    const float* xr = x + (size_t)row * DM;
    float* orow = out + (size_t)row * DM;
    int tid = threadIdx.x;

    float vals[4];
    float s = 0.f, s2 = 0.f;
#pragma unroll
    for (int i = 0; i < 4; i++) {
        float v = xr[tid + i * 128];
        vals[i] = v; s += v; s2 += v * v;
    }
#pragma unroll
    for (int o = 16; o; o >>= 1) {
        s  += __shfl_down_sync(0xffffffffu, s,  o);
        s2 += __shfl_down_sync(0xffffffffu, s2, o);
    }
    __shared__ float rs[4], rs2[4];
    int wid = tid >> 5, lane = tid & 31;
    if (lane == 0) { rs[wid] = s; rs2[wid] = s2; }
    __syncthreads();
    if (tid == 0) {
        float a = 0.f, a2 = 0.f;
#pragma unroll
        for (int w = 0; w < 4; w++) { a += rs[w]; a2 += rs2[w]; }
        rs[0] = a; rs2[0] = a2;
    }
    __syncthreads();
    float mean = rs[0] * (1.0f / DM);
    float var  = rs2[0] * (1.0f / DM) - mean * mean;
    float inv  = rsqrtf(var + 1e-5f);
#pragma unroll
    for (int i = 0; i < 4; i++) {
        int c = tid + i * 128;
        float o = (vals[i] - mean) * inv * g[c] + b[c];
        orow[c] = RND ? rnd_tf(o) : o;
    }
}

// ---------------- launch -------------------------------------------------------
extern "C" void kernel_launch(void* const* d_in, const int* in_sizes, int n_in,
                              void* d_out, int out_size)
{
    const float* tgt    = (const float*)d_in[0];
    const float* memory = (const float*)d_in[1];

    const size_t OW = (size_t)LAYER * DM * DM;
    const size_t OB = (size_t)LAYER * DM;
    const float* sa_wq = (const float*)d_in[4]  + OW;
    const float* sa_wk = (const float*)d_in[5]  + OW;
    const float* sa_wv = (const float*)d_in[6]  + OW;
    const float* sa_wo = (const float*)d_in[7]  + OW;
    const float* sa_bq = (const float*)d_in[8]  + OB;
    const float* sa_bk = (const float*)d_in[9]  + OB;
    const float* sa_bv = (const float*)d_in[10] + OB;
    const float* sa_bo = (const float*)d_in[11] + OB;
    const float* ca_wq = (const float*)d_in[12] + OW;
    const float* ca_wk = (const float*)d_in[13] + OW;
    const float* ca_wv = (const float*)d_in[14] + OW;
    const float* ca_wo = (const float*)d_in[15] + OW;
    const float* ca_bq = (const float*)d_in[16] + OB;
    const float* ca_bk = (const float*)d_in[17] + OB;
    const float* ca_bv = (const float*)d_in[18] + OB;
    const float* ca_bo = (const float*)d_in[19] + OB;
    const float* ff_w1 = (const float*)d_in[20] + (size_t)LAYER * DM * FFD;
    const float* ff_b1 = (const float*)d_in[21] + (size_t)LAYER * FFD;
    const float* ff_w2 = (const float*)d_in[22] + (size_t)LAYER * FFD * DM;
    const float* ff_b2 = (const float*)d_in[23] + OB;
    const float* ln_g  = (const float*)d_in[24];
    const float* ln_b  = (const float*)d_in[25];

    float *n_, *q_, *k_, *v_, *vt_, *at_, *x_, *ff_, *wt_, *w1t_, *w2t_;
    cudaGetSymbolAddress((void**)&n_,   g_n);
    cudaGetSymbolAddress((void**)&q_,   g_q);
    cudaGetSymbolAddress((void**)&k_,   g_k);
    cudaGetSymbolAddress((void**)&v_,   g_v);
    cudaGetSymbolAddress((void**)&vt_,  g_vt);
    cudaGetSymbolAddress((void**)&at_,  g_at);
    cudaGetSymbolAddress((void**)&x_,   g_x);
    cudaGetSymbolAddress((void**)&ff_,  g_ff);
    cudaGetSymbolAddress((void**)&wt_,  g_wt);
    cudaGetSymbolAddress((void**)&w1t_, g_w1t);
    cudaGetSymbolAddress((void**)&w2t_, g_w2t);

    const int S128 = 2 * (128 * 32 + 128 * 32) * 4;   // 65536
    const int SFL  = 32768 * 4;                       // 131072
    cudaFuncSetAttribute(mma_gemm<128,0,1>, cudaFuncAttributeMaxDynamicSharedMemorySize, S128);
    cudaFuncSetAttribute(mma_gemm<128,1,1>, cudaFuncAttributeMaxDynamicSharedMemorySize, S128);
    cudaFuncSetAttribute(mma_gemm<128,2,0>, cudaFuncAttributeMaxDynamicSharedMemorySize, S128);
    cudaFuncSetAttribute(flash_attn<1>,     cudaFuncAttributeMaxDynamicSharedMemorySize, SFL);
    cudaFuncSetAttribute(flash_attn<0>,     cudaFuncAttributeMaxDynamicSharedMemorySize, SFL);

    const int M = BB * TT;                          // 4096

    float* wqT = wt_ + 0 * DM * DM;
    float* wkT = wt_ + 1 * DM * DM;
    float* wvT = wt_ + 2 * DM * DM;
    float* woT = wt_ + 3 * DM * DM;
    float* cqT = wt_ + 4 * DM * DM;
    float* ckT = wt_ + 5 * DM * DM;
    float* cvT = wt_ + 6 * DM * DM;
    float* coT = wt_ + 7 * DM * DM;

    TP8 tp;
    tp.s[0]=sa_wq; tp.d[0]=wqT;  tp.s[1]=sa_wk; tp.d[1]=wkT;
    tp.s[2]=sa_wv; tp.d[2]=wvT;  tp.s[3]=sa_wo; tp.d[3]=woT;
    tp.s[4]=ca_wq; tp.d[4]=cqT;  tp.s[5]=ca_wk; tp.d[5]=ckT;
    tp.s[6]=ca_wv; tp.d[6]=cvT;  tp.s[7]=ca_wo; tp.d[7]=coT;
    transpose8<<<dim3(16,16,8), dim3(32,8)>>>(tp);
    transpose_one<<<dim3(FFD/32, DM/32),  dim3(32,8)>>>(ff_w1, w1t_, DM,  FFD);
    transpose_one<<<dim3(DM/32,  FFD/32), dim3(32,8)>>>(ff_w2, w2t_, FFD, DM);
    // rounded copy of memory into g_ff (dead until FFN) for CA K/V projections
    round_copy<<<(BB*SS*DM/4 + 255)/256, 256>>>(memory, ff_, BB*SS*DM/4);

    // ---- self-attention: x = tgt + SA(LN(tgt)) ----
    ln_kernel<1><<<M, 128>>>(tgt, ln_g, ln_b, n_);
    mma_gemm<128,0,1><<<dim3(4,32),256,S128>>>(n_,DM, wqT,DM, sa_bq,nullptr, q_,DM, DM);
    mma_gemm<128,0,1><<<dim3(4,32),256,S128>>>(n_,DM, wkT,DM, sa_bk,nullptr, k_,DM, DM);
    mma_gemm<128,0,1><<<dim3(4,32),256,S128>>>(n_,DM, wvT,DM, sa_bv,nullptr, v_,DM, DM);
    transpose_one<<<dim3(DM/32, M/32), dim3(32,8)>>>(v_, vt_, M, DM);
    flash_attn<1><<<dim3(4,64),256,SFL>>>(q_, k_, vt_, at_, TT);
    mma_gemm<128,2,0><<<dim3(4,32),256,S128>>>(at_,DM, woT,DM, sa_bo,tgt, x_,DM, DM);

    // ---- cross-attention: x += CA(LN(x), memory) ----
    ln_kernel<1><<<M, 128>>>(x_, ln_g, ln_b, n_);
    mma_gemm<128,0,1><<<dim3(4,32),256,S128>>>(n_,DM, cqT,DM, ca_bq,nullptr, q_,DM, DM);
    mma_gemm<128,0,1><<<dim3(4,64),256,S128>>>(ff_,DM, ckT,DM, ca_bk,nullptr, k_,DM, DM);
    mma_gemm<128,0,1><<<dim3(4,64),256,S128>>>(ff_,DM, cvT,DM, ca_bv,nullptr, v_,DM, DM);
    transpose_one<<<dim3(DM/32, (BB*SS)/32), dim3(32,8)>>>(v_, vt_, BB*SS, DM);
    flash_attn<0><<<dim3(4,64),256,SFL>>>(q_, k_, vt_, at_, SS);
    mma_gemm<128,2,0><<<dim3(4,32),256,S128>>>(at_,DM, coT,DM, ca_bo,x_, x_,DM, DM);

    // ---- FFN: x += W2 relu(W1 LN(x)) ----
    ln_kernel<1><<<M, 128>>>(x_, ln_g, ln_b, n_);
    mma_gemm<128,1,1><<<dim3(16,32),256,S128>>>(n_,DM,  w1t_,DM,  ff_b1,nullptr, ff_,FFD, DM);
    mma_gemm<128,2,0><<<dim3(4,32),256,S128>>>(ff_,FFD, w2t_,FFD, ff_b2,x_,      x_,DM,  FFD);

    // ---- final LN -> out ----
    ln_kernel<0><<<M, 128>>>(x_, ln_g, ln_b, (float*)d_out);
}

// round 6
// speedup vs baseline: 1.1672x; 1.1672x over previous
#include <cuda_runtime.h>
#include <cstdint>

// Problem constants
#define NH   8
#define DM   512
#define FFD  2048
#define BB   8
#define TT   512
#define SS   1024
#define LAYER 5

// ---------------- scratch (device globals) ------------------------------------
__device__ float g_n   [BB*TT*DM];
__device__ float g_q   [BB*TT*DM];
__device__ float g_qkv [BB*TT*3*DM];          // fused SA QKV  [4096][1536]
__device__ float g_kv  [BB*SS*2*DM];          // fused CA KV   [8192][1024]
__device__ float g_vt  [DM*BB*SS];            // transposed V  [512][B*S]
__device__ float g_at  [BB*TT*DM];
__device__ float g_x   [BB*TT*DM];
__device__ float g_ff  [BB*TT*FFD];
__device__ float g_wt  [8*DM*DM];             // 8 transposed 512x512 weights
__device__ float g_w1t [FFD*DM];
__device__ float g_w2t [DM*FFD];
__device__ float g_bc1 [3*DM];                // concat sa_bq|bk|bv
__device__ float g_bc2 [2*DM];                // concat ca_bk|bv

// ---------------- helpers ------------------------------------------------------
__device__ __forceinline__ uint32_t smem_u32(const void* p) {
    uint32_t a;
    asm("{ .reg .u64 t; cvta.to.shared.u64 t, %1; cvt.u32.u64 %0, t; }" : "=r"(a) : "l"(p));
    return a;
}
__device__ __forceinline__ uint32_t f2tf(float f) {
    uint32_t u;
    asm("cvt.rna.tf32.f32 %0, %1;" : "=r"(u) : "f"(f));
    return u;
}
#define CP16(dst, src) \
    asm volatile("cp.async.cg.shared.global [%0], [%1], 16;" :: "r"(dst), "l"(src))
#define CP_COMMIT() asm volatile("cp.async.commit_group;" ::: "memory")
#define CP_WAIT1()  asm volatile("cp.async.wait_group 1;" ::: "memory")
#define CP_WAIT0()  asm volatile("cp.async.wait_group 0;" ::: "memory")

#define MMA_TF32(c, a, b) \
    asm volatile("mma.sync.aligned.m16n8k8.row.col.f32.tf32.tf32.f32 " \
        "{%0,%1,%2,%3}, {%4,%5,%6,%7}, {%8,%9}, {%0,%1,%2,%3};" \
        : "+f"((c)[0]), "+f"((c)[1]), "+f"((c)[2]), "+f"((c)[3]) \
        : "r"((a)[0]), "r"((a)[1]), "r"((a)[2]), "r"((a)[3]), "r"((b)[0]), "r"((b)[1]))

// swizzled smem float index for a [rows][32] panel
__device__ __forceinline__ int swz(int r, int c) {
    return r * 32 + ((((c >> 2) ^ (r & 7)) << 2) | (c & 3));
}

// ============ mma.sync tf32 GEMM, 3-stage pipeline =============================
// C = epi( A[M,K] @ B[N,K]^T );  B row-major [N][K].
// EPI: 0=+bias  1=relu(+bias)  2=+bias+res
template<int BN, int EPI>
__global__ __launch_bounds__(256) void mma_gemm(
    const float* __restrict__ A, int lda,
    const float* __restrict__ B, int ldb,
    const float* __restrict__ bias, const float* __restrict__ res,
    float* __restrict__ C, int ldc, int K)
{
    constexpr int WTM = (BN == 128) ? 64 : 32;
    constexpr int MW  = 128 / WTM;
    constexpr int MF  = WTM / 16;
    constexpr int NF  = 4;
    constexpr int SSZ = 128 * 32 + BN * 32;      // floats per stage

    const int m0 = blockIdx.y * 128;
    const int n0 = blockIdx.x * BN;

    extern __shared__ float smem[];
    const uint32_t uS = smem_u32(smem);

    const int tid  = threadIdx.x;
    const int lane = tid & 31;
    const int wid  = tid >> 5;
    const int wm   = wid & (MW - 1);
    const int wn   = wid / MW;
    const int laneR = lane >> 2, laneC = lane & 3;

    const int nch = K >> 5;

    auto load_chunk = [&](int c) {
        const int st = c % 3;
        const uint32_t ua = uS + st * SSZ * 4;
        const uint32_t ub = ua + 128 * 32 * 4;
        const int k0 = c << 5;
#pragma unroll
        for (int i = 0; i < 4; i++) {
            int idx = tid + i * 256; int r = idx >> 3, f = idx & 7;
            CP16(ua + r * 128 + ((f ^ (r & 7)) << 4),
                 A + (size_t)(m0 + r) * lda + k0 + f * 4);
        }
#pragma unroll
        for (int i = 0; i < BN / 32; i++) {
            int idx = tid + i * 256; int r = idx >> 3, f = idx & 7;
            CP16(ub + r * 128 + ((f ^ (r & 7)) << 4),
                 B + (size_t)(n0 + r) * ldb + k0 + f * 4);
        }
        CP_COMMIT();
    };

    float acc[MF][NF][4] = {};

    load_chunk(0);
    load_chunk(1);
    for (int c = 0; c < nch; c++) {
        if (c + 1 < nch) CP_WAIT1(); else CP_WAIT0();
        __syncthreads();
        if (c + 2 < nch) load_chunk(c + 2);
        const int st = c % 3;
        const float* sA = smem + st * SSZ;
        const float* sB = sA + 128 * 32;
#pragma unroll
        for (int ks = 0; ks < 4; ks++) {
            uint32_t af[MF][4];
#pragma unroll
            for (int mf = 0; mf < MF; mf++) {
                int r = wm * WTM + mf * 16 + laneR;
                int cc = ks * 8 + laneC;
                af[mf][0] = f2tf(sA[swz(r,     cc)]);
                af[mf][1] = f2tf(sA[swz(r + 8, cc)]);
                af[mf][2] = f2tf(sA[swz(r,     cc + 4)]);
                af[mf][3] = f2tf(sA[swz(r + 8, cc + 4)]);
            }
            uint32_t bf[NF][2];
#pragma unroll
            for (int nf = 0; nf < NF; nf++) {
                int n = wn * 32 + nf * 8 + laneR;
                int cc = ks * 8 + laneC;
                bf[nf][0] = f2tf(sB[swz(n, cc)]);
                bf[nf][1] = f2tf(sB[swz(n, cc + 4)]);
            }
#pragma unroll
            for (int mf = 0; mf < MF; mf++)
#pragma unroll
                for (int nf = 0; nf < NF; nf++)
                    MMA_TF32(acc[mf][nf], af[mf], bf[nf]);
        }
    }

#pragma unroll
    for (int mf = 0; mf < MF; mf++) {
#pragma unroll
        for (int nf = 0; nf < NF; nf++) {
            int r  = m0 + wm * WTM + mf * 16 + laneR;
            int cc = n0 + wn * 32 + nf * 8 + laneC * 2;
            float v0 = acc[mf][nf][0], v1 = acc[mf][nf][1];
            float v2 = acc[mf][nf][2], v3 = acc[mf][nf][3];
            float2 bb = *(const float2*)(bias + cc);
            v0 += bb.x; v1 += bb.y; v2 += bb.x; v3 += bb.y;
            if (EPI == 1) {
                v0 = fmaxf(v0, 0.f); v1 = fmaxf(v1, 0.f);
                v2 = fmaxf(v2, 0.f); v3 = fmaxf(v3, 0.f);
            }
            if (EPI == 2) {
                float2 r0 = *(const float2*)(res + (size_t)r * ldc + cc);
                float2 r1 = *(const float2*)(res + (size_t)(r + 8) * ldc + cc);
                v0 += r0.x; v1 += r0.y; v2 += r1.x; v3 += r1.y;
            }
            *(float2*)(C + (size_t)r * ldc + cc)       = make_float2(v0, v1);
            *(float2*)(C + (size_t)(r + 8) * ldc + cc) = make_float2(v2, v3);
        }
    }
}

// ============ fused flash attention (single-buffer KV, 2 CTA/SM) ===============
// Q rows stride ldq (head h at col h*64); K rows stride ldk; Vt [512][B*Slen].
template<int CAUSAL>
__global__ __launch_bounds__(256) void flash_attn(
    const float* __restrict__ Q, int ldq,
    const float* __restrict__ Kg, int ldk,
    const float* __restrict__ Vt, float* __restrict__ O, int Slen)
{
    extern __shared__ float sm[];
    float* sQ = sm;                 // 2 panels x 128x32 = 8192
    float* sK = sm + 8192;          // 2 panels x 64x32  = 4096
    float* sV = sm + 12288;         // 4096
    float* sP = sm + 16384;         // 8 warps x 16x64   = 8192

    const int mt = blockIdx.x, bh = blockIdx.y;
    const int b = bh >> 3, h = bh & 7;
    const int m0 = mt * 128;
    const int tid = threadIdx.x, lane = tid & 31, wid = tid >> 5;
    const int laneR = lane >> 2, laneC = lane & 3;

    const float* Qp = Q + ((size_t)b * TT + m0) * ldq + h * 64;
    const float* Kp = Kg + (size_t)b * Slen * ldk + h * 64;
    const float* Vp = Vt + (size_t)(h * 64) * (BB * Slen) + (size_t)b * Slen;
    float* Op = O + ((size_t)b * TT + m0) * DM + h * 64;

    const uint32_t uQ = smem_u32(sQ), uK = smem_u32(sK), uV = smem_u32(sV);

    // Q tile (joins first commit group)
#pragma unroll
    for (int i = 0; i < 8; i++) {
        int idx = tid + i * 256;
        int r = idx >> 4, f = idx & 15;
        int panel = f >> 3, fo = f & 7;
        CP16(uQ + (panel * 4096 + r * 32 + ((fo ^ (r & 7)) << 2)) * 4,
             Qp + (size_t)r * ldq + f * 4);
    }

    auto load_kv = [&](int c) {
        const int s0 = c * 64;
#pragma unroll
        for (int i = 0; i < 4; i++) {
            int idx = tid + i * 256;
            int r = idx >> 4, f = idx & 15;
            int panel = f >> 3, fo = f & 7;
            CP16(uK + (panel * 2048 + r * 32 + ((fo ^ (r & 7)) << 2)) * 4,
                 Kp + (size_t)(s0 + r) * ldk + f * 4);
        }
#pragma unroll
        for (int i = 0; i < 4; i++) {
            int idx = tid + i * 256;
            int r = idx >> 4, f = idx & 15;
            int panel = f >> 3, fo = f & 7;
            CP16(uV + (panel * 2048 + r * 32 + ((fo ^ (r & 7)) << 2)) * 4,
                 Vp + (size_t)r * (BB * Slen) + s0 + f * 4);
        }
        CP_COMMIT();
    };

    const int nch = CAUSAL ? (m0 + 128) / 64 : Slen / 64;
    const int wr0 = wid * 16;
    float mr0 = -1e30f, mr1 = -1e30f, l0 = 0.f, l1 = 0.f;
    float oacc[8][4] = {};
    float* sPw = sP + wid * 1024;

    for (int c = 0; c < nch; c++) {
        load_kv(c);
        CP_WAIT0();
        __syncthreads();
        const int s0 = c * 64;
        const bool active = !CAUSAL || (s0 <= m0 + wr0 + 15);
        if (active) {
            const float* cK = sK;
            const float* cV = sV;

            // ---- S = Q @ K^T ----
            float sacc[8][4] = {};
#pragma unroll
            for (int ks = 0; ks < 8; ks++) {
                int kk = ks * 8 + laneC;
                int pa = kk >> 5, ca = kk & 31;
                uint32_t af[4];
                {
                    const float* qp = sQ + pa * 4096;
                    int r0 = wr0 + laneR;
                    af[0] = f2tf(qp[swz(r0,     ca)]);
                    af[1] = f2tf(qp[swz(r0 + 8, ca)]);
                    af[2] = f2tf(qp[swz(r0,     ca + 4)]);
                    af[3] = f2tf(qp[swz(r0 + 8, ca + 4)]);
                }
                const float* kp = cK + pa * 2048;
#pragma unroll
                for (int nf = 0; nf < 8; nf++) {
                    uint32_t bf[2];
                    int n = nf * 8 + laneR;
                    bf[0] = f2tf(kp[swz(n, ca)]);
                    bf[1] = f2tf(kp[swz(n, ca + 4)]);
                    MMA_TF32(sacc[nf], af, bf);
                }
            }

            // ---- scale + mask + online softmax ----
            const float SCL = 0.125f;
            const int t0g = m0 + wr0 + laneR;
            float rmax0 = -1e30f, rmax1 = -1e30f;
#pragma unroll
            for (int nf = 0; nf < 8; nf++) {
                int sg = s0 + nf * 8 + 2 * laneC;
                float v0 = sacc[nf][0] * SCL, v1 = sacc[nf][1] * SCL;
                float v2 = sacc[nf][2] * SCL, v3 = sacc[nf][3] * SCL;
                if (CAUSAL) {
                    if (sg     > t0g)     v0 = -1e30f;
                    if (sg + 1 > t0g)     v1 = -1e30f;
                    if (sg     > t0g + 8) v2 = -1e30f;
                    if (sg + 1 > t0g + 8) v3 = -1e30f;
                }
                sacc[nf][0] = v0; sacc[nf][1] = v1;
                sacc[nf][2] = v2; sacc[nf][3] = v3;
                rmax0 = fmaxf(rmax0, fmaxf(v0, v1));
                rmax1 = fmaxf(rmax1, fmaxf(v2, v3));
            }
            rmax0 = fmaxf(rmax0, __shfl_xor_sync(0xffffffffu, rmax0, 1));
            rmax0 = fmaxf(rmax0, __shfl_xor_sync(0xffffffffu, rmax0, 2));
            rmax1 = fmaxf(rmax1, __shfl_xor_sync(0xffffffffu, rmax1, 1));
            rmax1 = fmaxf(rmax1, __shfl_xor_sync(0xffffffffu, rmax1, 2));
            float mn0 = fmaxf(mr0, rmax0), mn1 = fmaxf(mr1, rmax1);
            float al0 = __expf(mr0 - mn0), al1 = __expf(mr1 - mn1);
            mr0 = mn0; mr1 = mn1;

            float rs0 = 0.f, rs1 = 0.f;
#pragma unroll
            for (int nf = 0; nf < 8; nf++) {
                float e0 = __expf(sacc[nf][0] - mn0);
                float e1 = __expf(sacc[nf][1] - mn0);
                float e2 = __expf(sacc[nf][2] - mn1);
                float e3 = __expf(sacc[nf][3] - mn1);
                rs0 += e0 + e1; rs1 += e2 + e3;
                int cc = nf * 8 + 2 * laneC;
                int pa = cc >> 5, ca = cc & 31;
                *(float2*)&sPw[pa * 512 + swz(laneR,     ca)] = make_float2(e0, e1);
                *(float2*)&sPw[pa * 512 + swz(laneR + 8, ca)] = make_float2(e2, e3);
            }
            rs0 += __shfl_xor_sync(0xffffffffu, rs0, 1);
            rs0 += __shfl_xor_sync(0xffffffffu, rs0, 2);
            rs1 += __shfl_xor_sync(0xffffffffu, rs1, 1);
            rs1 += __shfl_xor_sync(0xffffffffu, rs1, 2);
            l0 = l0 * al0 + rs0;
            l1 = l1 * al1 + rs1;
#pragma unroll
            for (int nf = 0; nf < 8; nf++) {
                oacc[nf][0] *= al0; oacc[nf][1] *= al0;
                oacc[nf][2] *= al1; oacc[nf][3] *= al1;
            }
            __syncwarp();

            // ---- O += P @ V ----
#pragma unroll
            for (int ks = 0; ks < 8; ks++) {
                int kk = ks * 8 + laneC;
                int pa = kk >> 5, ca = kk & 31;
                uint32_t af[4];
                const float* pp = sPw + pa * 512;
                af[0] = f2tf(pp[swz(laneR,     ca)]);
                af[1] = f2tf(pp[swz(laneR + 8, ca)]);
                af[2] = f2tf(pp[swz(laneR,     ca + 4)]);
                af[3] = f2tf(pp[swz(laneR + 8, ca + 4)]);
                const float* vp = cV + pa * 2048;
#pragma unroll
                for (int nf = 0; nf < 8; nf++) {
                    uint32_t bf[2];
                    int n = nf * 8 + laneR;
                    bf[0] = f2tf(vp[swz(n, ca)]);
                    bf[1] = f2tf(vp[swz(n, ca + 4)]);
                    MMA_TF32(oacc[nf], af, bf);
                }
            }
        }
        __syncthreads();
    }

    const float inv0 = 1.f / l0, inv1 = 1.f / l1;
#pragma unroll
    for (int nf = 0; nf < 8; nf++) {
        int cc = nf * 8 + 2 * laneC;
        int r = wr0 + laneR;
        *(float2*)(Op + (size_t)r * DM + cc) =
            make_float2(oacc[nf][0] * inv0, oacc[nf][1] * inv0);
        *(float2*)(Op + (size_t)(r + 8) * DM + cc) =
            make_float2(oacc[nf][2] * inv1, oacc[nf][3] * inv1);
    }
}

// ---------------- transpose kernels -------------------------------------------
// dst[c][r] = src[r*sld + c] for r in [0,R), c in [0,C). dst ld = R.
__global__ __launch_bounds__(256) void transpose_one(
    const float* __restrict__ src, int sld, float* __restrict__ dst, int R, int C)
{
    __shared__ float t[32][33];
    int tx = threadIdx.x, ty = threadIdx.y;
    int x = blockIdx.x * 32 + tx;
    int y = blockIdx.y * 32;
#pragma unroll
    for (int i = 0; i < 4; i++)
        t[ty + i * 8][tx] = src[(size_t)(y + ty + i * 8) * sld + x];
    __syncthreads();
    int x2 = blockIdx.y * 32 + tx;
    int y2 = blockIdx.x * 32;
#pragma unroll
    for (int i = 0; i < 4; i++)
        dst[(size_t)(y2 + ty + i * 8) * R + x2] = t[tx][ty + i * 8];
}

struct TP8 { const float* s[8]; float* d[8]; };
__global__ __launch_bounds__(256) void transpose8(TP8 p)
{
    __shared__ float t[32][33];
    const float* src = p.s[blockIdx.z];
    float* dst = p.d[blockIdx.z];
    int tx = threadIdx.x, ty = threadIdx.y;
    int x = blockIdx.x * 32 + tx;
    int y = blockIdx.y * 32;
#pragma unroll
    for (int i = 0; i < 4; i++)
        t[ty + i * 8][tx] = src[(size_t)(y + ty + i * 8) * DM + x];
    __syncthreads();
    int x2 = blockIdx.y * 32 + tx;
    int y2 = blockIdx.x * 32;
#pragma unroll
    for (int i = 0; i < 4; i++)
        dst[(size_t)(y2 + ty + i * 8) * DM + x2] = t[tx][ty + i * 8];
}

__global__ void bias_concat(
    const float* q, const float* k, const float* v,
    const float* ck, const float* cv, float* b1, float* b2)
{
    int i = threadIdx.x;  // 512
    b1[i] = q[i]; b1[512 + i] = k[i]; b1[1024 + i] = v[i];
    b2[i] = ck[i]; b2[512 + i] = cv[i];
}

// ---------------- LayerNorm ---------------------------------------------------
__global__ __launch_bounds__(128) void ln_kernel(
    const float* __restrict__ x, const float* __restrict__ g,
    const float* __restrict__ b, float* __restrict__ out)
{
    int row = blockIdx.x;
    const float* xr = x + (size_t)row * DM;
    float* orow = out + (size_t)row * DM;
    int tid = threadIdx.x;

    float vals[4];
    float s = 0.f, s2 = 0.f;
#pragma unroll
    for (int i = 0; i < 4; i++) {
        float v = xr[tid + i * 128];
        vals[i] = v; s += v; s2 += v * v;
    }
#pragma unroll
    for (int o = 16; o; o >>= 1) {
        s  += __shfl_down_sync(0xffffffffu, s,  o);
        s2 += __shfl_down_sync(0xffffffffu, s2, o);
    }
    __shared__ float rs[4], rs2[4];
    int wid = tid >> 5, lane = tid & 31;
    if (lane == 0) { rs[wid] = s; rs2[wid] = s2; }
    __syncthreads();
    if (tid == 0) {
        float a = 0.f, a2 = 0.f;
#pragma unroll
        for (int w = 0; w < 4; w++) { a += rs[w]; a2 += rs2[w]; }
        rs[0] = a; rs2[0] = a2;
    }
    __syncthreads();
    float mean = rs[0] * (1.0f / DM);
    float var  = rs2[0] * (1.0f / DM) - mean * mean;
    float inv  = rsqrtf(var + 1e-5f);
#pragma unroll
    for (int i = 0; i < 4; i++) {
        int c = tid + i * 128;
        orow[c] = (vals[i] - mean) * inv * g[c] + b[c];
    }
}

// ---------------- launch -------------------------------------------------------
extern "C" void kernel_launch(void* const* d_in, const int* in_sizes, int n_in,
                              void* d_out, int out_size)
{
    const float* tgt    = (const float*)d_in[0];
    const float* memory = (const float*)d_in[1];

    const size_t OW = (size_t)LAYER * DM * DM;
    const size_t OB = (size_t)LAYER * DM;
    const float* sa_wq = (const float*)d_in[4]  + OW;
    const float* sa_wk = (const float*)d_in[5]  + OW;
    const float* sa_wv = (const float*)d_in[6]  + OW;
    const float* sa_wo = (const float*)d_in[7]  + OW;
    const float* sa_bq = (const float*)d_in[8]  + OB;
    const float* sa_bk = (const float*)d_in[9]  + OB;
    const float* sa_bv = (const float*)d_in[10] + OB;
    const float* sa_bo = (const float*)d_in[11] + OB;
    const float* ca_wq = (const float*)d_in[12] + OW;
    const float* ca_wk = (const float*)d_in[13] + OW;
    const float* ca_wv = (const float*)d_in[14] + OW;
    const float* ca_wo = (const float*)d_in[15] + OW;
    const float* ca_bq = (const float*)d_in[16] + OB;
    const float* ca_bk = (const float*)d_in[17] + OB;
    const float* ca_bv = (const float*)d_in[18] + OB;
    const float* ca_bo = (const float*)d_in[19] + OB;
    const float* ff_w1 = (const float*)d_in[20] + (size_t)LAYER * DM * FFD;
    const float* ff_b1 = (const float*)d_in[21] + (size_t)LAYER * FFD;
    const float* ff_w2 = (const float*)d_in[22] + (size_t)LAYER * FFD * DM;
    const float* ff_b2 = (const float*)d_in[23] + OB;
    const float* ln_g  = (const float*)d_in[24];
    const float* ln_b  = (const float*)d_in[25];

    float *n_, *q_, *qkv_, *kv_, *vt_, *at_, *x_, *ff_, *wt_, *w1t_, *w2t_, *bc1_, *bc2_;
    cudaGetSymbolAddress((void**)&n_,   g_n);
    cudaGetSymbolAddress((void**)&q_,   g_q);
    cudaGetSymbolAddress((void**)&qkv_, g_qkv);
    cudaGetSymbolAddress((void**)&kv_,  g_kv);
    cudaGetSymbolAddress((void**)&vt_,  g_vt);
    cudaGetSymbolAddress((void**)&at_,  g_at);
    cudaGetSymbolAddress((void**)&x_,   g_x);
    cudaGetSymbolAddress((void**)&ff_,  g_ff);
    cudaGetSymbolAddress((void**)&wt_,  g_wt);
    cudaGetSymbolAddress((void**)&w1t_, g_w1t);
    cudaGetSymbolAddress((void**)&w2t_, g_w2t);
    cudaGetSymbolAddress((void**)&bc1_, g_bc1);
    cudaGetSymbolAddress((void**)&bc2_, g_bc2);

    const int S128 = 3 * (128 * 32 + 128 * 32) * 4;   // 98304
    const int S64  = 3 * (128 * 32 + 64  * 32) * 4;   // 73728
    const int SFL  = 24576 * 4;                       // 98304
    cudaFuncSetAttribute(mma_gemm<128,0>, cudaFuncAttributeMaxDynamicSharedMemorySize, S128);
    cudaFuncSetAttribute(mma_gemm<128,1>, cudaFuncAttributeMaxDynamicSharedMemorySize, S128);
    cudaFuncSetAttribute(mma_gemm<64,0>,  cudaFuncAttributeMaxDynamicSharedMemorySize, S64);
    cudaFuncSetAttribute(mma_gemm<64,2>,  cudaFuncAttributeMaxDynamicSharedMemorySize, S64);
    cudaFuncSetAttribute(flash_attn<1>,   cudaFuncAttributeMaxDynamicSharedMemorySize, SFL);
    cudaFuncSetAttribute(flash_attn<0>,   cudaFuncAttributeMaxDynamicSharedMemorySize, SFL);

    const int M = BB * TT;   // 4096

    // transposed weight slots: SA q,k,v contiguous (fused QKV B), CA k,v contiguous
    float* wqkvT = wt_ + 0 * DM * DM;    // slots 0,1,2
    float* woT   = wt_ + 3 * DM * DM;
    float* cqT   = wt_ + 4 * DM * DM;
    float* ckvT  = wt_ + 5 * DM * DM;    // slots 5,6
    float* coT   = wt_ + 7 * DM * DM;

    TP8 tp;
    tp.s[0]=sa_wq; tp.d[0]=wt_ + 0*DM*DM;
    tp.s[1]=sa_wk; tp.d[1]=wt_ + 1*DM*DM;
    tp.s[2]=sa_wv; tp.d[2]=wt_ + 2*DM*DM;
    tp.s[3]=sa_wo; tp.d[3]=woT;
    tp.s[4]=ca_wq; tp.d[4]=cqT;
    tp.s[5]=ca_wk; tp.d[5]=wt_ + 5*DM*DM;
    tp.s[6]=ca_wv; tp.d[6]=wt_ + 6*DM*DM;
    tp.s[7]=ca_wo; tp.d[7]=coT;
    transpose8<<<dim3(16,16,8), dim3(32,8)>>>(tp);
    transpose_one<<<dim3(FFD/32, DM/32),  dim3(32,8)>>>(ff_w1, FFD, w1t_, DM,  FFD);
    transpose_one<<<dim3(DM/32,  FFD/32), dim3(32,8)>>>(ff_w2, DM,  w2t_, FFD, DM);
    bias_concat<<<1, 512>>>(sa_bq, sa_bk, sa_bv, ca_bk, ca_bv, bc1_, bc2_);

    // ---- self-attention: x = tgt + SA(LN(tgt)) ----
    ln_kernel<<<M, 128>>>(tgt, ln_g, ln_b, n_);
    mma_gemm<128,0><<<dim3(12,32),256,S128>>>(n_,DM, wqkvT,DM, bc1_,nullptr, qkv_,3*DM, DM);
    transpose_one<<<dim3(DM/32, M/32), dim3(32,8)>>>(qkv_ + 2*DM, 3*DM, vt_, M, DM);
    flash_attn<1><<<dim3(4,64),256,SFL>>>(qkv_,3*DM, qkv_+DM,3*DM, vt_, at_, TT);
    mma_gemm<64,2><<<dim3(8,32),256,S64>>>(at_,DM, woT,DM, sa_bo,tgt, x_,DM, DM);

    // ---- cross-attention: x += CA(LN(x), memory) ----
    ln_kernel<<<M, 128>>>(x_, ln_g, ln_b, n_);
    mma_gemm<64,0><<<dim3(8,32),256,S64>>>(n_,DM, cqT,DM, ca_bq,nullptr, q_,DM, DM);
    mma_gemm<128,0><<<dim3(8,64),256,S128>>>(memory,DM, ckvT,DM, bc2_,nullptr, kv_,2*DM, DM);
    transpose_one<<<dim3(DM/32, (BB*SS)/32), dim3(32,8)>>>(kv_ + DM, 2*DM, vt_, BB*SS, DM);
    flash_attn<0><<<dim3(4,64),256,SFL>>>(q_,DM, kv_,2*DM, vt_, at_, SS);
    mma_gemm<64,2><<<dim3(8,32),256,S64>>>(at_,DM, coT,DM, ca_bo,x_, x_,DM, DM);

    // ---- FFN: x += W2 relu(W1 LN(x)) ----
    ln_kernel<<<M, 128>>>(x_, ln_g, ln_b, n_);
    mma_gemm<128,1><<<dim3(16,32),256,S128>>>(n_,DM,  w1t_,DM,  ff_b1,nullptr, ff_,FFD, DM);
    mma_gemm<64,2><<<dim3(8,32),256,S64>>>(ff_,FFD, w2t_,FFD, ff_b2,x_, x_,DM, FFD);

    // ---- final LN -> out ----
    ln_kernel<<<M, 128>>>(x_, ln_g, ln_b, (float*)d_out);
}

// round 7
// speedup vs baseline: 1.2213x; 1.0463x over previous
#include <cuda_runtime.h>
#include <cstdint>

// Problem constants
#define NH   8
#define DM   512
#define FFD  2048
#define BB   8
#define TT   512
#define SS   1024
#define LAYER 5

// ---------------- scratch (device globals) ------------------------------------
__device__ float g_n   [BB*TT*DM];
__device__ float g_q   [BB*TT*DM];
__device__ float g_qkv [BB*TT*3*DM];          // fused SA QKV  [4096][1536] (V region unused)
__device__ float g_kv  [BB*SS*2*DM];          // fused CA KV   [8192][1024] (V region unused)
__device__ float g_vt  [DM*BB*SS];            // transposed V  [512][B*S]
__device__ float g_at  [BB*TT*DM];
__device__ float g_x   [BB*TT*DM];
__device__ float g_ff  [BB*TT*FFD];
__device__ float g_wt  [8*DM*DM];             // 8 transposed 512x512 weights
__device__ float g_w1t [FFD*DM];
__device__ float g_w2t [DM*FFD];
__device__ float g_bc1 [3*DM];                // concat sa_bq|bk|bv
__device__ float g_bc2 [2*DM];                // concat ca_bk|bv

// ---------------- helpers ------------------------------------------------------
__device__ __forceinline__ uint32_t smem_u32(const void* p) {
    uint32_t a;
    asm("{ .reg .u64 t; cvta.to.shared.u64 t, %1; cvt.u32.u64 %0, t; }" : "=r"(a) : "l"(p));
    return a;
}
__device__ __forceinline__ uint32_t f2tf(float f) {
    uint32_t u;
    asm("cvt.rna.tf32.f32 %0, %1;" : "=r"(u) : "f"(f));
    return u;
}
#define CP16(dst, src) \
    asm volatile("cp.async.cg.shared.global [%0], [%1], 16;" :: "r"(dst), "l"(src))
#define CP_COMMIT() asm volatile("cp.async.commit_group;" ::: "memory")
#define CP_WAIT1()  asm volatile("cp.async.wait_group 1;" ::: "memory")
#define CP_WAIT0()  asm volatile("cp.async.wait_group 0;" ::: "memory")

#define MMA_TF32(c, a, b) \
    asm volatile("mma.sync.aligned.m16n8k8.row.col.f32.tf32.tf32.f32 " \
        "{%0,%1,%2,%3}, {%4,%5,%6,%7}, {%8,%9}, {%0,%1,%2,%3};" \
        : "+f"((c)[0]), "+f"((c)[1]), "+f"((c)[2]), "+f"((c)[3]) \
        : "r"((a)[0]), "r"((a)[1]), "r"((a)[2]), "r"((a)[3]), "r"((b)[0]), "r"((b)[1]))

// swizzled smem float index for a [rows][32] panel
__device__ __forceinline__ int swz(int r, int c) {
    return r * 32 + ((((c >> 2) ^ (r & 7)) << 2) | (c & 3));
}

// ============ mma.sync tf32 GEMM, 3-stage pipeline =============================
// C = epi( A[M,K] @ B[N,K]^T );  B row-major [N][K].
// EPI: 0=+bias  1=relu(+bias)  2=+bias+res
// VT: tiles with n0 >= vtn0 write TRANSPOSED to vtp[(n-vtn0)*vtld + m] (skip C).
template<int BN, int EPI, int VT>
__global__ __launch_bounds__(256) void mma_gemm(
    const float* __restrict__ A, int lda,
    const float* __restrict__ B, int ldb,
    const float* __restrict__ bias, const float* __restrict__ res,
    float* __restrict__ C, int ldc, int K,
    float* __restrict__ vtp, int vtn0, int vtld)
{
    constexpr int WTM = (BN == 128) ? 64 : 32;
    constexpr int MW  = 128 / WTM;
    constexpr int MF  = WTM / 16;
    constexpr int NF  = 4;
    constexpr int SSZ = 128 * 32 + BN * 32;      // floats per stage

    const int m0 = blockIdx.y * 128;
    const int n0 = blockIdx.x * BN;

    extern __shared__ float smem[];
    const uint32_t uS = smem_u32(smem);

    const int tid  = threadIdx.x;
    const int lane = tid & 31;
    const int wid  = tid >> 5;
    const int wm   = wid & (MW - 1);
    const int wn   = wid / MW;
    const int laneR = lane >> 2, laneC = lane & 3;

    const int nch = K >> 5;

    auto load_chunk = [&](int c) {
        const int st = c % 3;
        const uint32_t ua = uS + st * SSZ * 4;
        const uint32_t ub = ua + 128 * 32 * 4;
        const int k0 = c << 5;
#pragma unroll
        for (int i = 0; i < 4; i++) {
            int idx = tid + i * 256; int r = idx >> 3, f = idx & 7;
            CP16(ua + r * 128 + ((f ^ (r & 7)) << 4),
                 A + (size_t)(m0 + r) * lda + k0 + f * 4);
        }
#pragma unroll
        for (int i = 0; i < BN / 32; i++) {
            int idx = tid + i * 256; int r = idx >> 3, f = idx & 7;
            CP16(ub + r * 128 + ((f ^ (r & 7)) << 4),
                 B + (size_t)(n0 + r) * ldb + k0 + f * 4);
        }
        CP_COMMIT();
    };

    float acc[MF][NF][4] = {};

    load_chunk(0);
    load_chunk(1);
    for (int c = 0; c < nch; c++) {
        if (c + 1 < nch) CP_WAIT1(); else CP_WAIT0();
        __syncthreads();
        if (c + 2 < nch) load_chunk(c + 2);
        const int st = c % 3;
        const float* sA = smem + st * SSZ;
        const float* sB = sA + 128 * 32;
#pragma unroll
        for (int ks = 0; ks < 4; ks++) {
            uint32_t af[MF][4];
#pragma unroll
            for (int mf = 0; mf < MF; mf++) {
                int r = wm * WTM + mf * 16 + laneR;
                int cc = ks * 8 + laneC;
                af[mf][0] = f2tf(sA[swz(r,     cc)]);
                af[mf][1] = f2tf(sA[swz(r + 8, cc)]);
                af[mf][2] = f2tf(sA[swz(r,     cc + 4)]);
                af[mf][3] = f2tf(sA[swz(r + 8, cc + 4)]);
            }
            uint32_t bf[NF][2];
#pragma unroll
            for (int nf = 0; nf < NF; nf++) {
                int n = wn * 32 + nf * 8 + laneR;
                int cc = ks * 8 + laneC;
                bf[nf][0] = f2tf(sB[swz(n, cc)]);
                bf[nf][1] = f2tf(sB[swz(n, cc + 4)]);
            }
#pragma unroll
            for (int mf = 0; mf < MF; mf++)
#pragma unroll
                for (int nf = 0; nf < NF; nf++)
                    MMA_TF32(acc[mf][nf], af[mf], bf[nf]);
        }
    }

    const bool isv = VT && (n0 >= vtn0);
#pragma unroll
    for (int mf = 0; mf < MF; mf++) {
#pragma unroll
        for (int nf = 0; nf < NF; nf++) {
            int r  = m0 + wm * WTM + mf * 16 + laneR;
            int cc = n0 + wn * 32 + nf * 8 + laneC * 2;
            float v0 = acc[mf][nf][0], v1 = acc[mf][nf][1];
            float v2 = acc[mf][nf][2], v3 = acc[mf][nf][3];
            float2 bb = *(const float2*)(bias + cc);
            v0 += bb.x; v1 += bb.y; v2 += bb.x; v3 += bb.y;
            if (EPI == 1) {
                v0 = fmaxf(v0, 0.f); v1 = fmaxf(v1, 0.f);
                v2 = fmaxf(v2, 0.f); v3 = fmaxf(v3, 0.f);
            }
            if (EPI == 2) {
                float2 r0 = *(const float2*)(res + (size_t)r * ldc + cc);
                float2 r1 = *(const float2*)(res + (size_t)(r + 8) * ldc + cc);
                v0 += r0.x; v1 += r0.y; v2 += r1.x; v3 += r1.y;
            }
            if (isv) {
                float* c0 = vtp + (size_t)(cc     - vtn0) * vtld;
                float* c1 = vtp + (size_t)(cc + 1 - vtn0) * vtld;
                c0[r] = v0; c1[r] = v1; c0[r + 8] = v2; c1[r + 8] = v3;
            } else {
                *(float2*)(C + (size_t)r * ldc + cc)       = make_float2(v0, v1);
                *(float2*)(C + (size_t)(r + 8) * ldc + cc) = make_float2(v2, v3);
            }
        }
    }
}

// ============ fused flash attention (single-buffer KV, 2 CTA/SM) ===============
template<int CAUSAL>
__global__ __launch_bounds__(256) void flash_attn(
    const float* __restrict__ Q, int ldq,
    const float* __restrict__ Kg, int ldk,
    const float* __restrict__ Vt, float* __restrict__ O, int Slen)
{
    extern __shared__ float sm[];
    float* sQ = sm;                 // 2 panels x 128x32 = 8192
    float* sK = sm + 8192;          // 2 panels x 64x32  = 4096
    float* sV = sm + 12288;         // 4096
    float* sP = sm + 16384;         // 8 warps x 16x64   = 8192

    const int mt = blockIdx.x, bh = blockIdx.y;
    const int b = bh >> 3, h = bh & 7;
    const int m0 = mt * 128;
    const int tid = threadIdx.x, lane = tid & 31, wid = tid >> 5;
    const int laneR = lane >> 2, laneC = lane & 3;

    const float* Qp = Q + ((size_t)b * TT + m0) * ldq + h * 64;
    const float* Kp = Kg + (size_t)b * Slen * ldk + h * 64;
    const float* Vp = Vt + (size_t)(h * 64) * (BB * Slen) + (size_t)b * Slen;
    float* Op = O + ((size_t)b * TT + m0) * DM + h * 64;

    const uint32_t uQ = smem_u32(sQ), uK = smem_u32(sK), uV = smem_u32(sV);

#pragma unroll
    for (int i = 0; i < 8; i++) {
        int idx = tid + i * 256;
        int r = idx >> 4, f = idx & 15;
        int panel = f >> 3, fo = f & 7;
        CP16(uQ + (panel * 4096 + r * 32 + ((fo ^ (r & 7)) << 2)) * 4,
             Qp + (size_t)r * ldq + f * 4);
    }

    auto load_kv = [&](int c) {
        const int s0 = c * 64;
#pragma unroll
        for (int i = 0; i < 4; i++) {
            int idx = tid + i * 256;
            int r = idx >> 4, f = idx & 15;
            int panel = f >> 3, fo = f & 7;
            CP16(uK + (panel * 2048 + r * 32 + ((fo ^ (r & 7)) << 2)) * 4,
                 Kp + (size_t)(s0 + r) * ldk + f * 4);
        }
#pragma unroll
        for (int i = 0; i < 4; i++) {
            int idx = tid + i * 256;
            int r = idx >> 4, f = idx & 15;
            int panel = f >> 3, fo = f & 7;
            CP16(uV + (panel * 2048 + r * 32 + ((fo ^ (r & 7)) << 2)) * 4,
                 Vp + (size_t)r * (BB * Slen) + s0 + f * 4);
        }
        CP_COMMIT();
    };

    const int nch = CAUSAL ? (m0 + 128) / 64 : Slen / 64;
    const int wr0 = wid * 16;
    float mr0 = -1e30f, mr1 = -1e30f, l0 = 0.f, l1 = 0.f;
    float oacc[8][4] = {};
    float* sPw = sP + wid * 1024;

    for (int c = 0; c < nch; c++) {
        load_kv(c);
        CP_WAIT0();
        __syncthreads();
        const int s0 = c * 64;
        const bool active = !CAUSAL || (s0 <= m0 + wr0 + 15);
        if (active) {
            // ---- S = Q @ K^T ----
            float sacc[8][4] = {};
#pragma unroll
            for (int ks = 0; ks < 8; ks++) {
                int kk = ks * 8 + laneC;
                int pa = kk >> 5, ca = kk & 31;
                uint32_t af[4];
                {
                    const float* qp = sQ + pa * 4096;
                    int r0 = wr0 + laneR;
                    af[0] = f2tf(qp[swz(r0,     ca)]);
                    af[1] = f2tf(qp[swz(r0 + 8, ca)]);
                    af[2] = f2tf(qp[swz(r0,     ca + 4)]);
                    af[3] = f2tf(qp[swz(r0 + 8, ca + 4)]);
                }
                const float* kp = sK + pa * 2048;
#pragma unroll
                for (int nf = 0; nf < 8; nf++) {
                    uint32_t bf[2];
                    int n = nf * 8 + laneR;
                    bf[0] = f2tf(kp[swz(n, ca)]);
                    bf[1] = f2tf(kp[swz(n, ca + 4)]);
                    MMA_TF32(sacc[nf], af, bf);
                }
            }

            // ---- scale + mask + online softmax ----
            const float SCL = 0.125f;
            const int t0g = m0 + wr0 + laneR;
            float rmax0 = -1e30f, rmax1 = -1e30f;
#pragma unroll
            for (int nf = 0; nf < 8; nf++) {
                int sg = s0 + nf * 8 + 2 * laneC;
                float v0 = sacc[nf][0] * SCL, v1 = sacc[nf][1] * SCL;
                float v2 = sacc[nf][2] * SCL, v3 = sacc[nf][3] * SCL;
                if (CAUSAL) {
                    if (sg     > t0g)     v0 = -1e30f;
                    if (sg + 1 > t0g)     v1 = -1e30f;
                    if (sg     > t0g + 8) v2 = -1e30f;
                    if (sg + 1 > t0g + 8) v3 = -1e30f;
                }
                sacc[nf][0] = v0; sacc[nf][1] = v1;
                sacc[nf][2] = v2; sacc[nf][3] = v3;
                rmax0 = fmaxf(rmax0, fmaxf(v0, v1));
                rmax1 = fmaxf(rmax1, fmaxf(v2, v3));
            }
            rmax0 = fmaxf(rmax0, __shfl_xor_sync(0xffffffffu, rmax0, 1));
            rmax0 = fmaxf(rmax0, __shfl_xor_sync(0xffffffffu, rmax0, 2));
            rmax1 = fmaxf(rmax1, __shfl_xor_sync(0xffffffffu, rmax1, 1));
            rmax1 = fmaxf(rmax1, __shfl_xor_sync(0xffffffffu, rmax1, 2));
            float mn0 = fmaxf(mr0, rmax0), mn1 = fmaxf(mr1, rmax1);
            float al0 = __expf(mr0 - mn0), al1 = __expf(mr1 - mn1);
            mr0 = mn0; mr1 = mn1;

            float rs0 = 0.f, rs1 = 0.f;
#pragma unroll
            for (int nf = 0; nf < 8; nf++) {
                float e0 = __expf(sacc[nf][0] - mn0);
                float e1 = __expf(sacc[nf][1] - mn0);
                float e2 = __expf(sacc[nf][2] - mn1);
                float e3 = __expf(sacc[nf][3] - mn1);
                rs0 += e0 + e1; rs1 += e2 + e3;
                int cc = nf * 8 + 2 * laneC;
                int pa = cc >> 5, ca = cc & 31;
                *(float2*)&sPw[pa * 512 + swz(laneR,     ca)] = make_float2(e0, e1);
                *(float2*)&sPw[pa * 512 + swz(laneR + 8, ca)] = make_float2(e2, e3);
            }
            rs0 += __shfl_xor_sync(0xffffffffu, rs0, 1);
            rs0 += __shfl_xor_sync(0xffffffffu, rs0, 2);
            rs1 += __shfl_xor_sync(0xffffffffu, rs1, 1);
            rs1 += __shfl_xor_sync(0xffffffffu, rs1, 2);
            l0 = l0 * al0 + rs0;
            l1 = l1 * al1 + rs1;
#pragma unroll
            for (int nf = 0; nf < 8; nf++) {
                oacc[nf][0] *= al0; oacc[nf][1] *= al0;
                oacc[nf][2] *= al1; oacc[nf][3] *= al1;
            }
            __syncwarp();

            // ---- O += P @ V ----
#pragma unroll
            for (int ks = 0; ks < 8; ks++) {
                int kk = ks * 8 + laneC;
                int pa = kk >> 5, ca = kk & 31;
                uint32_t af[4];
                const float* pp = sPw + pa * 512;
                af[0] = f2tf(pp[swz(laneR,     ca)]);
                af[1] = f2tf(pp[swz(laneR + 8, ca)]);
                af[2] = f2tf(pp[swz(laneR,     ca + 4)]);
                af[3] = f2tf(pp[swz(laneR + 8, ca + 4)]);
                const float* vp = sV + pa * 2048;
#pragma unroll
                for (int nf = 0; nf < 8; nf++) {
                    uint32_t bf[2];
                    int n = nf * 8 + laneR;
                    bf[0] = f2tf(vp[swz(n, ca)]);
                    bf[1] = f2tf(vp[swz(n, ca + 4)]);
                    MMA_TF32(oacc[nf], af, bf);
                }
            }
        }
        __syncthreads();
    }

    const float inv0 = 1.f / l0, inv1 = 1.f / l1;
#pragma unroll
    for (int nf = 0; nf < 8; nf++) {
        int cc = nf * 8 + 2 * laneC;
        int r = wr0 + laneR;
        *(float2*)(Op + (size_t)r * DM + cc) =
            make_float2(oacc[nf][0] * inv0, oacc[nf][1] * inv0);
        *(float2*)(Op + (size_t)(r + 8) * DM + cc) =
            make_float2(oacc[nf][2] * inv1, oacc[nf][3] * inv1);
    }
}

// ---------------- prep: all weight transposes + bias concats, one launch -------
struct PrepArgs {
    const float* s8[8]; float* d8[8];
    const float* w1; float* w1t;
    const float* w2; float* w2t;
    const float* bq; const float* bk; const float* bv;
    const float* cbk; const float* cbv;
    float* b1; float* b2;
};
__global__ __launch_bounds__(256) void prep_all(PrepArgs p)
{
    __shared__ float t[32][33];
    const int idx = blockIdx.x;
    const int tx = threadIdx.x, ty = threadIdx.y;

    const float* src; float* dst; int R, C, bx, by;
    if (idx < 2048) {
        int m = idx >> 8, tt = idx & 255;
        src = p.s8[m]; dst = p.d8[m]; R = 512; C = 512;
        bx = tt & 15; by = tt >> 4;
    } else if (idx < 3072) {
        int tt = idx - 2048;
        src = p.w1; dst = p.w1t; R = 512; C = 2048;
        bx = tt & 63; by = tt >> 6;
    } else if (idx < 4096) {
        int tt = idx - 3072;
        src = p.w2; dst = p.w2t; R = 2048; C = 512;
        bx = tt & 15; by = tt >> 4;
    } else {
        int i = ty * 32 + tx;
#pragma unroll
        for (int j = 0; j < 2; j++) {
            int c = i + j * 256;
            p.b1[c] = p.bq[c]; p.b1[512 + c] = p.bk[c]; p.b1[1024 + c] = p.bv[c];
            p.b2[c] = p.cbk[c]; p.b2[512 + c] = p.cbv[c];
        }
        return;
    }
    int x = bx * 32 + tx, y = by * 32;
#pragma unroll
    for (int i = 0; i < 4; i++)
        t[ty + i * 8][tx] = src[(size_t)(y + ty + i * 8) * C + x];
    __syncthreads();
    int x2 = by * 32 + tx, y2 = bx * 32;
#pragma unroll
    for (int i = 0; i < 4; i++)
        dst[(size_t)(y2 + ty + i * 8) * R + x2] = t[tx][ty + i * 8];
}

// ---------------- LayerNorm (float4) -------------------------------------------
__global__ __launch_bounds__(128) void ln_kernel(
    const float* __restrict__ x, const float* __restrict__ g,
    const float* __restrict__ b, float* __restrict__ out)
{
    const int row = blockIdx.x;
    const int tid = threadIdx.x;
    float4 v = *(const float4*)(x + (size_t)row * DM + tid * 4);

    float s  = v.x + v.y + v.z + v.w;
    float s2 = v.x * v.x + v.y * v.y + v.z * v.z + v.w * v.w;
#pragma unroll
    for (int o = 16; o; o >>= 1) {
        s  += __shfl_down_sync(0xffffffffu, s,  o);
        s2 += __shfl_down_sync(0xffffffffu, s2, o);
    }
    __shared__ float rs[4], rs2[4];
    int wid = tid >> 5, lane = tid & 31;
    if (lane == 0) { rs[wid] = s; rs2[wid] = s2; }
    __syncthreads();
    if (tid == 0) {
        float a = rs[0] + rs[1] + rs[2] + rs[3];
        float a2 = rs2[0] + rs2[1] + rs2[2] + rs2[3];
        rs[0] = a; rs2[0] = a2;
    }
    __syncthreads();
    float mean = rs[0] * (1.0f / DM);
    float var  = rs2[0] * (1.0f / DM) - mean * mean;
    float inv  = rsqrtf(var + 1e-5f);

    float4 gg = *(const float4*)(g + tid * 4);
    float4 bb = *(const float4*)(b + tid * 4);
    float4 o;
    o.x = (v.x - mean) * inv * gg.x + bb.x;
    o.y = (v.y - mean) * inv * gg.y + bb.y;
    o.z = (v.z - mean) * inv * gg.z + bb.z;
    o.w = (v.w - mean) * inv * gg.w + bb.w;
    *(float4*)(out + (size_t)row * DM + tid * 4) = o;
}

// ---------------- launch -------------------------------------------------------
extern "C" void kernel_launch(void* const* d_in, const int* in_sizes, int n_in,
                              void* d_out, int out_size)
{
    const float* tgt    = (const float*)d_in[0];
    const float* memory = (const float*)d_in[1];

    const size_t OW = (size_t)LAYER * DM * DM;
    const size_t OB = (size_t)LAYER * DM;
    const float* sa_wq = (const float*)d_in[4]  + OW;
    const float* sa_wk = (const float*)d_in[5]  + OW;
    const float* sa_wv = (const float*)d_in[6]  + OW;
    const float* sa_wo = (const float*)d_in[7]  + OW;
    const float* sa_bq = (const float*)d_in[8]  + OB;
    const float* sa_bk = (const float*)d_in[9]  + OB;
    const float* sa_bv = (const float*)d_in[10] + OB;
    const float* sa_bo = (const float*)d_in[11] + OB;
    const float* ca_wq = (const float*)d_in[12] + OW;
    const float* ca_wk = (const float*)d_in[13] + OW;
    const float* ca_wv = (const float*)d_in[14] + OW;
    const float* ca_wo = (const float*)d_in[15] + OW;
    const float* ca_bq = (const float*)d_in[16] + OB;
    const float* ca_bk = (const float*)d_in[17] + OB;
    const float* ca_bv = (const float*)d_in[18] + OB;
    const float* ca_bo = (const float*)d_in[19] + OB;
    const float* ff_w1 = (const float*)d_in[20] + (size_t)LAYER * DM * FFD;
    const float* ff_b1 = (const float*)d_in[21] + (size_t)LAYER * FFD;
    const float* ff_w2 = (const float*)d_in[22] + (size_t)LAYER * FFD * DM;
    const float* ff_b2 = (const float*)d_in[23] + OB;
    const float* ln_g  = (const float*)d_in[24];
    const float* ln_b  = (const float*)d_in[25];

    float *n_, *q_, *qkv_, *kv_, *vt_, *at_, *x_, *ff_, *wt_, *w1t_, *w2t_, *bc1_, *bc2_;
    cudaGetSymbolAddress((void**)&n_,   g_n);
    cudaGetSymbolAddress((void**)&q_,   g_q);
    cudaGetSymbolAddress((void**)&qkv_, g_qkv);
    cudaGetSymbolAddress((void**)&kv_,  g_kv);
    cudaGetSymbolAddress((void**)&vt_,  g_vt);
    cudaGetSymbolAddress((void**)&at_,  g_at);
    cudaGetSymbolAddress((void**)&x_,   g_x);
    cudaGetSymbolAddress((void**)&ff_,  g_ff);
    cudaGetSymbolAddress((void**)&wt_,  g_wt);
    cudaGetSymbolAddress((void**)&w1t_, g_w1t);
    cudaGetSymbolAddress((void**)&w2t_, g_w2t);
    cudaGetSymbolAddress((void**)&bc1_, g_bc1);
    cudaGetSymbolAddress((void**)&bc2_, g_bc2);

    const int S128 = 3 * (128 * 32 + 128 * 32) * 4;   // 98304
    const int S64  = 3 * (128 * 32 + 64  * 32) * 4;   // 73728
    const int SFL  = 24576 * 4;                       // 98304
    cudaFuncSetAttribute(mma_gemm<128,0,1>, cudaFuncAttributeMaxDynamicSharedMemorySize, S128);
    cudaFuncSetAttribute(mma_gemm<128,1,0>, cudaFuncAttributeMaxDynamicSharedMemorySize, S128);
    cudaFuncSetAttribute(mma_gemm<64,0,0>,  cudaFuncAttributeMaxDynamicSharedMemorySize, S64);
    cudaFuncSetAttribute(mma_gemm<64,2,0>,  cudaFuncAttributeMaxDynamicSharedMemorySize, S64);
    cudaFuncSetAttribute(flash_attn<1>,     cudaFuncAttributeMaxDynamicSharedMemorySize, SFL);
    cudaFuncSetAttribute(flash_attn<0>,     cudaFuncAttributeMaxDynamicSharedMemorySize, SFL);

    const int M = BB * TT;   // 4096

    float* wqkvT = wt_ + 0 * DM * DM;    // slots 0,1,2
    float* woT   = wt_ + 3 * DM * DM;
    float* cqT   = wt_ + 4 * DM * DM;
    float* ckvT  = wt_ + 5 * DM * DM;    // slots 5,6
    float* coT   = wt_ + 7 * DM * DM;

    PrepArgs pa;
    pa.s8[0]=sa_wq; pa.d8[0]=wt_ + 0*DM*DM;
    pa.s8[1]=sa_wk; pa.d8[1]=wt_ + 1*DM*DM;
    pa.s8[2]=sa_wv; pa.d8[2]=wt_ + 2*DM*DM;
    pa.s8[3]=sa_wo; pa.d8[3]=woT;
    pa.s8[4]=ca_wq; pa.d8[4]=cqT;
    pa.s8[5]=ca_wk; pa.d8[5]=wt_ + 5*DM*DM;
    pa.s8[6]=ca_wv; pa.d8[6]=wt_ + 6*DM*DM;
    pa.s8[7]=ca_wo; pa.d8[7]=coT;
    pa.w1 = ff_w1; pa.w1t = w1t_;
    pa.w2 = ff_w2; pa.w2t = w2t_;
    pa.bq = sa_bq; pa.bk = sa_bk; pa.bv = sa_bv;
    pa.cbk = ca_bk; pa.cbv = ca_bv;
    pa.b1 = bc1_; pa.b2 = bc2_;
    prep_all<<<4097, dim3(32,8)>>>(pa);

    // ---- self-attention: x = tgt + SA(LN(tgt)) ----
    ln_kernel<<<M, 128>>>(tgt, ln_g, ln_b, n_);
    mma_gemm<128,0,1><<<dim3(12,32),256,S128>>>(
        n_,DM, wqkvT,DM, bc1_,nullptr, qkv_,3*DM, DM, vt_,1024,M);
    flash_attn<1><<<dim3(4,64),256,SFL>>>(qkv_,3*DM, qkv_+DM,3*DM, vt_, at_, TT);
    mma_gemm<64,2,0><<<dim3(8,32),256,S64>>>(
        at_,DM, woT,DM, sa_bo,tgt, x_,DM, DM, nullptr,0,0);

    // ---- cross-attention: x += CA(LN(x), memory) ----
    ln_kernel<<<M, 128>>>(x_, ln_g, ln_b, n_);
    mma_gemm<64,0,0><<<dim3(8,32),256,S64>>>(
        n_,DM, cqT,DM, ca_bq,nullptr, q_,DM, DM, nullptr,0,0);
    mma_gemm<128,0,1><<<dim3(8,64),256,S128>>>(
        memory,DM, ckvT,DM, bc2_,nullptr, kv_,2*DM, DM, vt_,512,BB*SS);
    flash_attn<0><<<dim3(4,64),256,SFL>>>(q_,DM, kv_,2*DM, vt_, at_, SS);
    mma_gemm<64,2,0><<<dim3(8,32),256,S64>>>(
        at_,DM, coT,DM, ca_bo,x_, x_,DM, DM, nullptr,0,0);

    // ---- FFN: x += W2 relu(W1 LN(x)) ----
    ln_kernel<<<M, 128>>>(x_, ln_g, ln_b, n_);
    mma_gemm<128,1,0><<<dim3(16,32),256,S128>>>(
        n_,DM,  w1t_,DM,  ff_b1,nullptr, ff_,FFD, DM, nullptr,0,0);
    mma_gemm<64,2,0><<<dim3(8,32),256,S64>>>(
        ff_,FFD, w2t_,FFD, ff_b2,x_, x_,DM, FFD, nullptr,0,0);

    // ---- final LN -> out ----
    ln_kernel<<<M, 128>>>(x_, ln_g, ln_b, (float*)d_out);
}

// round 8
// speedup vs baseline: 1.5001x; 1.2283x over previous
#include <cuda_runtime.h>
#include <cstdint>

// Problem constants
#define NH   8
#define DM   512
#define FFD  2048
#define BB   8
#define TT   512
#define SS   1024
#define LAYER 5

// ---------------- scratch (device globals) ------------------------------------
__device__ float g_n   [BB*TT*DM];
__device__ float g_q   [BB*TT*DM];
__device__ float g_qkv [BB*TT*3*DM];          // fused SA QKV (V region redirected)
__device__ float g_kv  [BB*SS*2*DM];          // fused CA KV  (V region redirected)
__device__ float g_vt  [DM*BB*SS];            // transposed V  [512][B*S]
__device__ float g_at  [BB*TT*DM];
__device__ float g_x   [BB*TT*DM];
__device__ float g_ff  [BB*TT*FFD];
__device__ float g_wt  [8*DM*DM];
__device__ float g_w1t [FFD*DM];
__device__ float g_w2t [DM*FFD];
__device__ float g_bc1 [3*DM];
__device__ float g_bc2 [2*DM];

// ---------------- helpers ------------------------------------------------------
__device__ __forceinline__ uint32_t smem_u32(const void* p) {
    uint32_t a;
    asm("{ .reg .u64 t; cvta.to.shared.u64 t, %1; cvt.u32.u64 %0, t; }" : "=r"(a) : "l"(p));
    return a;
}
__device__ __forceinline__ uint32_t f2tf(float f) {
    uint32_t u;
    asm("cvt.rna.tf32.f32 %0, %1;" : "=r"(u) : "f"(f));
    return u;
}
#define CP16(dst, src) \
    asm volatile("cp.async.cg.shared.global [%0], [%1], 16;" :: "r"(dst), "l"(src))
#define CP_COMMIT() asm volatile("cp.async.commit_group;" ::: "memory")
#define CP_WAIT1()  asm volatile("cp.async.wait_group 1;" ::: "memory")
#define CP_WAIT0()  asm volatile("cp.async.wait_group 0;" ::: "memory")

#define MMA_TF32(c, a, b) \
    asm volatile("mma.sync.aligned.m16n8k8.row.col.f32.tf32.tf32.f32 " \
        "{%0,%1,%2,%3}, {%4,%5,%6,%7}, {%8,%9}, {%0,%1,%2,%3};" \
        : "+f"((c)[0]), "+f"((c)[1]), "+f"((c)[2]), "+f"((c)[3]) \
        : "r"((a)[0]), "r"((a)[1]), "r"((a)[2]), "r"((a)[3]), "r"((b)[0]), "r"((b)[1]))

// ldmatrix x4: 4 8x8(b16) matrices = 4 8x4(f32) tiles; thread t supplies
// the row address for matrix t>>3, row t&7; receives word (lane>>2, lane&3).
#define LDSM4(d0, d1, d2, d3, addr) \
    asm volatile("ldmatrix.sync.aligned.m8n8.x4.shared.b16 {%0,%1,%2,%3}, [%4];" \
        : "=r"(d0), "=r"(d1), "=r"(d2), "=r"(d3) : "r"(addr))

// swizzled smem float index for a [rows][32] panel
__device__ __forceinline__ int swz(int r, int c) {
    return r * 32 + ((((c >> 2) ^ (r & 7)) << 2) | (c & 3));
}

// ============ mma.sync tf32 GEMM, 3-stage pipeline, ldmatrix fragments =========
// C = epi( A[M,K] @ B[N,K]^T );  B row-major [N][K].
// EPI: 0=+bias  1=relu(+bias)  2=+bias+res
// VT: tiles with n0 >= vtn0 write TRANSPOSED to vtp[(n-vtn0)*vtld + m] (skip C).
template<int BN, int EPI, int VT>
__global__ __launch_bounds__(256) void mma_gemm(
    const float* __restrict__ A, int lda,
    const float* __restrict__ B, int ldb,
    const float* __restrict__ bias, const float* __restrict__ res,
    float* __restrict__ C, int ldc, int K,
    float* __restrict__ vtp, int vtn0, int vtld)
{
    constexpr int WTM = (BN == 128) ? 64 : 32;
    constexpr int MW  = 128 / WTM;
    constexpr int MF  = WTM / 16;
    constexpr int NF  = 4;
    constexpr int SSZ = 128 * 32 + BN * 32;      // floats per stage

    const int m0 = blockIdx.y * 128;
    const int n0 = blockIdx.x * BN;

    extern __shared__ float smem[];
    const uint32_t uS = smem_u32(smem);

    const int tid  = threadIdx.x;
    const int lane = tid & 31;
    const int wid  = tid >> 5;
    const int wm   = wid & (MW - 1);
    const int wn   = wid / MW;
    const int laneR = lane >> 2, laneC = lane & 3;

    // ldmatrix per-thread addressing roles
    const int mat = lane >> 3, mrr = lane & 7;
    const int ag_hi = mat >> 1;         // A group offset carried by this thread
    const int bg_lo = mat & 1;          // B group offset
    int aro[MF], arx[MF];
#pragma unroll
    for (int mf = 0; mf < MF; mf++) {
        int r = wm * WTM + mf * 16 + ((mat & 1) << 3) + mrr;
        aro[mf] = r * 128; arx[mf] = r & 7;
    }
    int bro[NF / 2], brx[NF / 2];
#pragma unroll
    for (int p = 0; p < NF / 2; p++) {
        int r = wn * 32 + (2 * p + (mat >> 1)) * 8 + mrr;
        bro[p] = r * 128; brx[p] = r & 7;
    }

    const int nch = K >> 5;

    auto load_chunk = [&](int c) {
        const int st = c % 3;
        const uint32_t ua = uS + st * SSZ * 4;
        const uint32_t ub = ua + 128 * 32 * 4;
        const int k0 = c << 5;
#pragma unroll
        for (int i = 0; i < 4; i++) {
            int idx = tid + i * 256; int r = idx >> 3, f = idx & 7;
            CP16(ua + r * 128 + ((f ^ (r & 7)) << 4),
                 A + (size_t)(m0 + r) * lda + k0 + f * 4);
        }
#pragma unroll
        for (int i = 0; i < BN / 32; i++) {
            int idx = tid + i * 256; int r = idx >> 3, f = idx & 7;
            CP16(ub + r * 128 + ((f ^ (r & 7)) << 4),
                 B + (size_t)(n0 + r) * ldb + k0 + f * 4);
        }
        CP_COMMIT();
    };

    float acc[MF][NF][4] = {};

    load_chunk(0);
    load_chunk(1);
    for (int c = 0; c < nch; c++) {
        if (c + 1 < nch) CP_WAIT1(); else CP_WAIT0();
        __syncthreads();
        if (c + 2 < nch) load_chunk(c + 2);
        const int st = c % 3;
        const uint32_t uA_s = uS + st * SSZ * 4;
        const uint32_t uB_s = uA_s + 128 * 32 * 4;
#pragma unroll
        for (int ks = 0; ks < 4; ks++) {
            const int gA = 2 * ks + ag_hi;
            const int gB = 2 * ks + bg_lo;
            uint32_t af[MF][4];
#pragma unroll
            for (int mf = 0; mf < MF; mf++) {
                uint32_t d0, d1, d2, d3;
                LDSM4(d0, d1, d2, d3, uA_s + aro[mf] + ((gA ^ arx[mf]) << 4));
                af[mf][0] = f2tf(__uint_as_float(d0));
                af[mf][1] = f2tf(__uint_as_float(d1));
                af[mf][2] = f2tf(__uint_as_float(d2));
                af[mf][3] = f2tf(__uint_as_float(d3));
            }
            uint32_t bf[NF][2];
#pragma unroll
            for (int p = 0; p < NF / 2; p++) {
                uint32_t d0, d1, d2, d3;
                LDSM4(d0, d1, d2, d3, uB_s + bro[p] + ((gB ^ brx[p]) << 4));
                bf[2*p  ][0] = f2tf(__uint_as_float(d0));
                bf[2*p  ][1] = f2tf(__uint_as_float(d1));
                bf[2*p+1][0] = f2tf(__uint_as_float(d2));
                bf[2*p+1][1] = f2tf(__uint_as_float(d3));
            }
#pragma unroll
            for (int mf = 0; mf < MF; mf++)
#pragma unroll
                for (int nf = 0; nf < NF; nf++)
                    MMA_TF32(acc[mf][nf], af[mf], bf[nf]);
        }
    }

    const bool isv = VT && (n0 >= vtn0);
#pragma unroll
    for (int mf = 0; mf < MF; mf++) {
#pragma unroll
        for (int nf = 0; nf < NF; nf++) {
            int r  = m0 + wm * WTM + mf * 16 + laneR;
            int cc = n0 + wn * 32 + nf * 8 + laneC * 2;
            float v0 = acc[mf][nf][0], v1 = acc[mf][nf][1];
            float v2 = acc[mf][nf][2], v3 = acc[mf][nf][3];
            float2 bb = *(const float2*)(bias + cc);
            v0 += bb.x; v1 += bb.y; v2 += bb.x; v3 += bb.y;
            if (EPI == 1) {
                v0 = fmaxf(v0, 0.f); v1 = fmaxf(v1, 0.f);
                v2 = fmaxf(v2, 0.f); v3 = fmaxf(v3, 0.f);
            }
            if (EPI == 2) {
                float2 r0 = *(const float2*)(res + (size_t)r * ldc + cc);
                float2 r1 = *(const float2*)(res + (size_t)(r + 8) * ldc + cc);
                v0 += r0.x; v1 += r0.y; v2 += r1.x; v3 += r1.y;
            }
            if (isv) {
                float* c0 = vtp + (size_t)(cc     - vtn0) * vtld;
                float* c1 = vtp + (size_t)(cc + 1 - vtn0) * vtld;
                c0[r] = v0; c1[r] = v1; c0[r + 8] = v2; c1[r + 8] = v3;
            } else {
                *(float2*)(C + (size_t)r * ldc + cc)       = make_float2(v0, v1);
                *(float2*)(C + (size_t)(r + 8) * ldc + cc) = make_float2(v2, v3);
            }
        }
    }
}

// ============ fused flash attention (double-buffered KV, ldmatrix) =============
template<int CAUSAL>
__global__ __launch_bounds__(256) void flash_attn(
    const float* __restrict__ Q, int ldq,
    const float* __restrict__ Kg, int ldk,
    const float* __restrict__ Vt, float* __restrict__ O, int Slen)
{
    extern __shared__ float sm[];
    float* sQ = sm;                 // 2 panels x 128x32 = 8192 floats
    float* sK = sm + 8192;          // 2 bufs x (2 panels x 64x32) = 8192
    float* sV = sm + 16384;         // 8192
    float* sP = sm + 24576;         // 8 warps x 16x64 = 8192

    const int mt = blockIdx.x, bh = blockIdx.y;
    const int b = bh >> 3, h = bh & 7;
    const int m0 = mt * 128;
    const int tid = threadIdx.x, lane = tid & 31, wid = tid >> 5;
    const int laneR = lane >> 2, laneC = lane & 3;

    const float* Qp = Q + ((size_t)b * TT + m0) * ldq + h * 64;
    const float* Kp = Kg + (size_t)b * Slen * ldk + h * 64;
    const float* Vp = Vt + (size_t)(h * 64) * (BB * Slen) + (size_t)b * Slen;
    float* Op = O + ((size_t)b * TT + m0) * DM + h * 64;

    const uint32_t uQ = smem_u32(sQ), uK = smem_u32(sK), uV = smem_u32(sV);
    const int wr0 = wid * 16;
    float* sPw = sP + wid * 1024;
    const uint32_t uPw = smem_u32(sPw);

    // ldmatrix roles
    const int mat = lane >> 3, mrr = lane & 7;
    const int ag_hi = mat >> 1;
    const int bg_lo = mat & 1;
    const int qrow = wr0 + ((mat & 1) << 3) + mrr;     // Q A-frag row
    const int qro = qrow * 128, qrx = qrow & 7;
    const int prow = ((mat & 1) << 3) + mrr;           // P A-frag row
    const int pro = prow * 128, prx = prow & 7;
    int bro[4], brx[4];
#pragma unroll
    for (int p = 0; p < 4; p++) {
        int r = (2 * p + (mat >> 1)) * 8 + mrr;
        bro[p] = r * 128; brx[p] = r & 7;
    }

    // Q tile: 128 rows x 64 floats (joins first commit group)
#pragma unroll
    for (int i = 0; i < 8; i++) {
        int idx = tid + i * 256;
        int r = idx >> 4, f = idx & 15;
        int panel = f >> 3, fo = f & 7;
        CP16(uQ + (panel * 4096 + r * 32 + ((fo ^ (r & 7)) << 2)) * 4,
             Qp + (size_t)r * ldq + f * 4);
    }

    auto load_kv = [&](int c) {
        const int buf = c & 1;
        const int s0 = c * 64;
#pragma unroll
        for (int i = 0; i < 4; i++) {
            int idx = tid + i * 256;
            int r = idx >> 4, f = idx & 15;
            int panel = f >> 3, fo = f & 7;
            CP16(uK + (buf * 4096 + panel * 2048 + r * 32 + ((fo ^ (r & 7)) << 2)) * 4,
                 Kp + (size_t)(s0 + r) * ldk + f * 4);
        }
#pragma unroll
        for (int i = 0; i < 4; i++) {
            int idx = tid + i * 256;
            int r = idx >> 4, f = idx & 15;
            int panel = f >> 3, fo = f & 7;
            CP16(uV + (buf * 4096 + panel * 2048 + r * 32 + ((fo ^ (r & 7)) << 2)) * 4,
                 Vp + (size_t)r * (BB * Slen) + s0 + f * 4);
        }
        CP_COMMIT();
    };

    const int nch = CAUSAL ? (m0 + 128) / 64 : Slen / 64;
    float mr0 = -1e30f, mr1 = -1e30f, l0 = 0.f, l1 = 0.f;
    float oacc[8][4] = {};

    load_kv(0);
    for (int c = 0; c < nch; c++) {
        if (c + 1 < nch) { load_kv(c + 1); CP_WAIT1(); }
        else             { CP_WAIT0(); }
        __syncthreads();
        const int s0 = c * 64;
        const bool active = !CAUSAL || (s0 <= m0 + wr0 + 15);
        if (active) {
            const uint32_t uKb = uK + (c & 1) * 16384;
            const uint32_t uVb = uV + (c & 1) * 16384;

            // ---- S = Q @ K^T ----
            float sacc[8][4] = {};
#pragma unroll
            for (int ks = 0; ks < 8; ks++) {
                const int pa = ks >> 2;
                const int gA = ((ks & 3) << 1) + ag_hi;
                const int gB = ((ks & 3) << 1) + bg_lo;
                uint32_t af[4];
                {
                    uint32_t d0, d1, d2, d3;
                    LDSM4(d0, d1, d2, d3, uQ + (pa << 14) + qro + ((gA ^ qrx) << 4));
                    af[0] = f2tf(__uint_as_float(d0));
                    af[1] = f2tf(__uint_as_float(d1));
                    af[2] = f2tf(__uint_as_float(d2));
                    af[3] = f2tf(__uint_as_float(d3));
                }
                uint32_t bf[8][2];
#pragma unroll
                for (int p = 0; p < 4; p++) {
                    uint32_t d0, d1, d2, d3;
                    LDSM4(d0, d1, d2, d3, uKb + (pa << 13) + bro[p] + ((gB ^ brx[p]) << 4));
                    bf[2*p  ][0] = f2tf(__uint_as_float(d0));
                    bf[2*p  ][1] = f2tf(__uint_as_float(d1));
                    bf[2*p+1][0] = f2tf(__uint_as_float(d2));
                    bf[2*p+1][1] = f2tf(__uint_as_float(d3));
                }
#pragma unroll
                for (int nf = 0; nf < 8; nf++)
                    MMA_TF32(sacc[nf], af, bf[nf]);
            }

            // ---- scale + mask + online softmax ----
            const float SCL = 0.125f;
            const int t0g = m0 + wr0 + laneR;
            float rmax0 = -1e30f, rmax1 = -1e30f;
#pragma unroll
            for (int nf = 0; nf < 8; nf++) {
                int sg = s0 + nf * 8 + 2 * laneC;
                float v0 = sacc[nf][0] * SCL, v1 = sacc[nf][1] * SCL;
                float v2 = sacc[nf][2] * SCL, v3 = sacc[nf][3] * SCL;
                if (CAUSAL) {
                    if (sg     > t0g)     v0 = -1e30f;
                    if (sg + 1 > t0g)     v1 = -1e30f;
                    if (sg     > t0g + 8) v2 = -1e30f;
                    if (sg + 1 > t0g + 8) v3 = -1e30f;
                }
                sacc[nf][0] = v0; sacc[nf][1] = v1;
                sacc[nf][2] = v2; sacc[nf][3] = v3;
                rmax0 = fmaxf(rmax0, fmaxf(v0, v1));
                rmax1 = fmaxf(rmax1, fmaxf(v2, v3));
            }
            rmax0 = fmaxf(rmax0, __shfl_xor_sync(0xffffffffu, rmax0, 1));
            rmax0 = fmaxf(rmax0, __shfl_xor_sync(0xffffffffu, rmax0, 2));
            rmax1 = fmaxf(rmax1, __shfl_xor_sync(0xffffffffu, rmax1, 1));
            rmax1 = fmaxf(rmax1, __shfl_xor_sync(0xffffffffu, rmax1, 2));
            float mn0 = fmaxf(mr0, rmax0), mn1 = fmaxf(mr1, rmax1);
            float al0 = __expf(mr0 - mn0), al1 = __expf(mr1 - mn1);
            mr0 = mn0; mr1 = mn1;

            float rs0 = 0.f, rs1 = 0.f;
#pragma unroll
            for (int nf = 0; nf < 8; nf++) {
                float e0 = __expf(sacc[nf][0] - mn0);
                float e1 = __expf(sacc[nf][1] - mn0);
                float e2 = __expf(sacc[nf][2] - mn1);
                float e3 = __expf(sacc[nf][3] - mn1);
                rs0 += e0 + e1; rs1 += e2 + e3;
                int cc = nf * 8 + 2 * laneC;
                int pa = cc >> 5, ca = cc & 31;
                *(float2*)&sPw[pa * 512 + swz(laneR,     ca)] = make_float2(e0, e1);
                *(float2*)&sPw[pa * 512 + swz(laneR + 8, ca)] = make_float2(e2, e3);
            }
            rs0 += __shfl_xor_sync(0xffffffffu, rs0, 1);
            rs0 += __shfl_xor_sync(0xffffffffu, rs0, 2);
            rs1 += __shfl_xor_sync(0xffffffffu, rs1, 1);
            rs1 += __shfl_xor_sync(0xffffffffu, rs1, 2);
            l0 = l0 * al0 + rs0;
            l1 = l1 * al1 + rs1;
#pragma unroll
            for (int nf = 0; nf < 8; nf++) {
                oacc[nf][0] *= al0; oacc[nf][1] *= al0;
                oacc[nf][2] *= al1; oacc[nf][3] *= al1;
            }
            __syncwarp();

            // ---- O += P @ V ----
#pragma unroll
            for (int ks = 0; ks < 8; ks++) {
                const int pa = ks >> 2;
                const int gA = ((ks & 3) << 1) + ag_hi;
                const int gB = ((ks & 3) << 1) + bg_lo;
                uint32_t af[4];
                {
                    uint32_t d0, d1, d2, d3;
                    LDSM4(d0, d1, d2, d3, uPw + (pa << 11) + pro + ((gA ^ prx) << 4));
                    af[0] = f2tf(__uint_as_float(d0));
                    af[1] = f2tf(__uint_as_float(d1));
                    af[2] = f2tf(__uint_as_float(d2));
                    af[3] = f2tf(__uint_as_float(d3));
                }
#pragma unroll
                for (int p = 0; p < 4; p++) {
                    uint32_t d0, d1, d2, d3;
                    LDSM4(d0, d1, d2, d3, uVb + (pa << 13) + bro[p] + ((gB ^ brx[p]) << 4));
                    uint32_t bf0[2] = { f2tf(__uint_as_float(d0)), f2tf(__uint_as_float(d1)) };
                    uint32_t bf1[2] = { f2tf(__uint_as_float(d2)), f2tf(__uint_as_float(d3)) };
                    MMA_TF32(oacc[2*p],     af, bf0);
                    MMA_TF32(oacc[2*p + 1], af, bf1);
                }
            }
        }
        __syncthreads();
    }

    const float inv0 = 1.f / l0, inv1 = 1.f / l1;
#pragma unroll
    for (int nf = 0; nf < 8; nf++) {
        int cc = nf * 8 + 2 * laneC;
        int r = wr0 + laneR;
        *(float2*)(Op + (size_t)r * DM + cc) =
            make_float2(oacc[nf][0] * inv0, oacc[nf][1] * inv0);
        *(float2*)(Op + (size_t)(r + 8) * DM + cc) =
            make_float2(oacc[nf][2] * inv1, oacc[nf][3] * inv1);
    }
}

// ---------------- prep: all weight transposes + bias concats, one launch -------
struct PrepArgs {
    const float* s8[8]; float* d8[8];
    const float* w1; float* w1t;
    const float* w2; float* w2t;
    const float* bq; const float* bk; const float* bv;
    const float* cbk; const float* cbv;
    float* b1; float* b2;
};
__global__ __launch_bounds__(256) void prep_all(PrepArgs p)
{
    __shared__ float t[32][33];
    const int idx = blockIdx.x;
    const int tx = threadIdx.x, ty = threadIdx.y;

    const float* src; float* dst; int R, C, bx, by;
    if (idx < 2048) {
        int m = idx >> 8, tt = idx & 255;
        src = p.s8[m]; dst = p.d8[m]; R = 512; C = 512;
        bx = tt & 15; by = tt >> 4;
    } else if (idx < 3072) {
        int tt = idx - 2048;
        src = p.w1; dst = p.w1t; R = 512; C = 2048;
        bx = tt & 63; by = tt >> 6;
    } else if (idx < 4096) {
        int tt = idx - 3072;
        src = p.w2; dst = p.w2t; R = 2048; C = 512;
        bx = tt & 15; by = tt >> 4;
    } else {
        int i = ty * 32 + tx;
#pragma unroll
        for (int j = 0; j < 2; j++) {
            int c = i + j * 256;
            p.b1[c] = p.bq[c]; p.b1[512 + c] = p.bk[c]; p.b1[1024 + c] = p.bv[c];
            p.b2[c] = p.cbk[c]; p.b2[512 + c] = p.cbv[c];
        }
        return;
    }
    int x = bx * 32 + tx, y = by * 32;
#pragma unroll
    for (int i = 0; i < 4; i++)
        t[ty + i * 8][tx] = src[(size_t)(y + ty + i * 8) * C + x];
    __syncthreads();
    int x2 = by * 32 + tx, y2 = bx * 32;
#pragma unroll
    for (int i = 0; i < 4; i++)
        dst[(size_t)(y2 + ty + i * 8) * R + x2] = t[tx][ty + i * 8];
}

// ---------------- LayerNorm (float4) -------------------------------------------
__global__ __launch_bounds__(128) void ln_kernel(
    const float* __restrict__ x, const float* __restrict__ g,
    const float* __restrict__ b, float* __restrict__ out)
{
    const int row = blockIdx.x;
    const int tid = threadIdx.x;
    float4 v = *(const float4*)(x + (size_t)row * DM + tid * 4);

    float s  = v.x + v.y + v.z + v.w;
    float s2 = v.x * v.x + v.y * v.y + v.z * v.z + v.w * v.w;
#pragma unroll
    for (int o = 16; o; o >>= 1) {
        s  += __shfl_down_sync(0xffffffffu, s,  o);
        s2 += __shfl_down_sync(0xffffffffu, s2, o);
    }
    __shared__ float rs[4], rs2[4];
    int wid = tid >> 5, lane = tid & 31;
    if (lane == 0) { rs[wid] = s; rs2[wid] = s2; }
    __syncthreads();
    if (tid == 0) {
        float a = rs[0] + rs[1] + rs[2] + rs[3];
        float a2 = rs2[0] + rs2[1] + rs2[2] + rs2[3];
        rs[0] = a; rs2[0] = a2;
    }
    __syncthreads();
    float mean = rs[0] * (1.0f / DM);
    float var  = rs2[0] * (1.0f / DM) - mean * mean;
    float inv  = rsqrtf(var + 1e-5f);

    float4 gg = *(const float4*)(g + tid * 4);
    float4 bb = *(const float4*)(b + tid * 4);
    float4 o;
    o.x = (v.x - mean) * inv * gg.x + bb.x;
    o.y = (v.y - mean) * inv * gg.y + bb.y;
    o.z = (v.z - mean) * inv * gg.z + bb.z;
    o.w = (v.w - mean) * inv * gg.w + bb.w;
    *(float4*)(out + (size_t)row * DM + tid * 4) = o;
}

// ---------------- launch -------------------------------------------------------
extern "C" void kernel_launch(void* const* d_in, const int* in_sizes, int n_in,
                              void* d_out, int out_size)
{
    const float* tgt    = (const float*)d_in[0];
    const float* memory = (const float*)d_in[1];

    const size_t OW = (size_t)LAYER * DM * DM;
    const size_t OB = (size_t)LAYER * DM;
    const float* sa_wq = (const float*)d_in[4]  + OW;
    const float* sa_wk = (const float*)d_in[5]  + OW;
    const float* sa_wv = (const float*)d_in[6]  + OW;
    const float* sa_wo = (const float*)d_in[7]  + OW;
    const float* sa_bq = (const float*)d_in[8]  + OB;
    const float* sa_bk = (const float*)d_in[9]  + OB;
    const float* sa_bv = (const float*)d_in[10] + OB;
    const float* sa_bo = (const float*)d_in[11] + OB;
    const float* ca_wq = (const float*)d_in[12] + OW;
    const float* ca_wk = (const float*)d_in[13] + OW;
    const float* ca_wv = (const float*)d_in[14] + OW;
    const float* ca_wo = (const float*)d_in[15] + OW;
    const float* ca_bq = (const float*)d_in[16] + OB;
    const float* ca_bk = (const float*)d_in[17] + OB;
    const float* ca_bv = (const float*)d_in[18] + OB;
    const float* ca_bo = (const float*)d_in[19] + OB;
    const float* ff_w1 = (const float*)d_in[20] + (size_t)LAYER * DM * FFD;
    const float* ff_b1 = (const float*)d_in[21] + (size_t)LAYER * FFD;
    const float* ff_w2 = (const float*)d_in[22] + (size_t)LAYER * FFD * DM;
    const float* ff_b2 = (const float*)d_in[23] + OB;
    const float* ln_g  = (const float*)d_in[24];
    const float* ln_b  = (const float*)d_in[25];

    float *n_, *q_, *qkv_, *kv_, *vt_, *at_, *x_, *ff_, *wt_, *w1t_, *w2t_, *bc1_, *bc2_;
    cudaGetSymbolAddress((void**)&n_,   g_n);
    cudaGetSymbolAddress((void**)&q_,   g_q);
    cudaGetSymbolAddress((void**)&qkv_, g_qkv);
    cudaGetSymbolAddress((void**)&kv_,  g_kv);
    cudaGetSymbolAddress((void**)&vt_,  g_vt);
    cudaGetSymbolAddress((void**)&at_,  g_at);
    cudaGetSymbolAddress((void**)&x_,   g_x);
    cudaGetSymbolAddress((void**)&ff_,  g_ff);
    cudaGetSymbolAddress((void**)&wt_,  g_wt);
    cudaGetSymbolAddress((void**)&w1t_, g_w1t);
    cudaGetSymbolAddress((void**)&w2t_, g_w2t);
    cudaGetSymbolAddress((void**)&bc1_, g_bc1);
    cudaGetSymbolAddress((void**)&bc2_, g_bc2);

    const int S128 = 3 * (128 * 32 + 128 * 32) * 4;   // 98304
    const int S64  = 3 * (128 * 32 + 64  * 32) * 4;   // 73728
    const int SFL  = 32768 * 4;                       // 131072
    cudaFuncSetAttribute(mma_gemm<128,0,1>, cudaFuncAttributeMaxDynamicSharedMemorySize, S128);
    cudaFuncSetAttribute(mma_gemm<128,1,0>, cudaFuncAttributeMaxDynamicSharedMemorySize, S128);
    cudaFuncSetAttribute(mma_gemm<64,0,0>,  cudaFuncAttributeMaxDynamicSharedMemorySize, S64);
    cudaFuncSetAttribute(mma_gemm<64,2,0>,  cudaFuncAttributeMaxDynamicSharedMemorySize, S64);
    cudaFuncSetAttribute(flash_attn<1>,     cudaFuncAttributeMaxDynamicSharedMemorySize, SFL);
    cudaFuncSetAttribute(flash_attn<0>,     cudaFuncAttributeMaxDynamicSharedMemorySize, SFL);

    const int M = BB * TT;   // 4096

    float* wqkvT = wt_ + 0 * DM * DM;    // slots 0,1,2
    float* woT   = wt_ + 3 * DM * DM;
    float* cqT   = wt_ + 4 * DM * DM;
    float* ckvT  = wt_ + 5 * DM * DM;    // slots 5,6
    float* coT   = wt_ + 7 * DM * DM;

    PrepArgs pa;
    pa.s8[0]=sa_wq; pa.d8[0]=wt_ + 0*DM*DM;
    pa.s8[1]=sa_wk; pa.d8[1]=wt_ + 1*DM*DM;
    pa.s8[2]=sa_wv; pa.d8[2]=wt_ + 2*DM*DM;
    pa.s8[3]=sa_wo; pa.d8[3]=woT;
    pa.s8[4]=ca_wq; pa.d8[4]=cqT;
    pa.s8[5]=ca_wk; pa.d8[5]=wt_ + 5*DM*DM;
    pa.s8[6]=ca_wv; pa.d8[6]=wt_ + 6*DM*DM;
    pa.s8[7]=ca_wo; pa.d8[7]=coT;
    pa.w1 = ff_w1; pa.w1t = w1t_;
    pa.w2 = ff_w2; pa.w2t = w2t_;
    pa.bq = sa_bq; pa.bk = sa_bk; pa.bv = sa_bv;
    pa.cbk = ca_bk; pa.cbv = ca_bv;
    pa.b1 = bc1_; pa.b2 = bc2_;
    prep_all<<<4097, dim3(32,8)>>>(pa);

    // ---- self-attention: x = tgt + SA(LN(tgt)) ----
    ln_kernel<<<M, 128>>>(tgt, ln_g, ln_b, n_);
    mma_gemm<128,0,1><<<dim3(12,32),256,S128>>>(
        n_,DM, wqkvT,DM, bc1_,nullptr, qkv_,3*DM, DM, vt_,1024,M);
    flash_attn<1><<<dim3(4,64),256,SFL>>>(qkv_,3*DM, qkv_+DM,3*DM, vt_, at_, TT);
    mma_gemm<64,2,0><<<dim3(8,32),256,S64>>>(
        at_,DM, woT,DM, sa_bo,tgt, x_,DM, DM, nullptr,0,0);

    // ---- cross-attention: x += CA(LN(x), memory) ----
    ln_kernel<<<M, 128>>>(x_, ln_g, ln_b, n_);
    mma_gemm<64,0,0><<<dim3(8,32),256,S64>>>(
        n_,DM, cqT,DM, ca_bq,nullptr, q_,DM, DM, nullptr,0,0);
    mma_gemm<128,0,1><<<dim3(8,64),256,S128>>>(
        memory,DM, ckvT,DM, bc2_,nullptr, kv_,2*DM, DM, vt_,512,BB*SS);
    flash_attn<0><<<dim3(4,64),256,SFL>>>(q_,DM, kv_,2*DM, vt_, at_, SS);
    mma_gemm<64,2,0><<<dim3(8,32),256,S64>>>(
        at_,DM, coT,DM, ca_bo,x_, x_,DM, DM, nullptr,0,0);

    // ---- FFN: x += W2 relu(W1 LN(x)) ----
    ln_kernel<<<M, 128>>>(x_, ln_g, ln_b, n_);
    mma_gemm<128,1,0><<<dim3(16,32),256,S128>>>(
        n_,DM,  w1t_,DM,  ff_b1,nullptr, ff_,FFD, DM, nullptr,0,0);
    mma_gemm<64,2,0><<<dim3(8,32),256,S64>>>(
        ff_,FFD, w2t_,FFD, ff_b2,x_, x_,DM, FFD, nullptr,0,0);

    // ---- final LN -> out ----
    ln_kernel<<<M, 128>>>(x_, ln_g, ln_b, (float*)d_out);
}

// round 9
// speedup vs baseline: 1.5134x; 1.0089x over previous
#include <cuda_runtime.h>
#include <cstdint>

// Problem constants
#define NH   8
#define DM   512
#define FFD  2048
#define BB   8
#define TT   512
#define SS   1024
#define LAYER 5

// ---------------- scratch (device globals) ------------------------------------
__device__ float g_n   [BB*TT*DM];
__device__ float g_q   [BB*TT*DM];
__device__ float g_qkv [BB*TT*3*DM];          // fused SA QKV (V region redirected)
__device__ float g_kv  [BB*SS*2*DM];          // fused CA KV  (V region redirected)
__device__ float g_vt  [DM*BB*SS];            // transposed V  [512][B*S]
__device__ float g_at  [BB*TT*DM];
__device__ float g_x   [BB*TT*DM];
__device__ float g_ff  [BB*TT*FFD];
__device__ float g_wt  [8*DM*DM];
__device__ float g_w1t [FFD*DM];
__device__ float g_w2t [DM*FFD];
__device__ float g_bc1 [3*DM];
__device__ float g_bc2 [2*DM];

// ---------------- helpers ------------------------------------------------------
__device__ __forceinline__ uint32_t smem_u32(const void* p) {
    uint32_t a;
    asm("{ .reg .u64 t; cvta.to.shared.u64 t, %1; cvt.u32.u64 %0, t; }" : "=r"(a) : "l"(p));
    return a;
}
__device__ __forceinline__ uint32_t f2tf(float f) {
    uint32_t u;
    asm("cvt.rna.tf32.f32 %0, %1;" : "=r"(u) : "f"(f));
    return u;
}
__device__ __forceinline__ float rnd_tf(float f) { return __uint_as_float(f2tf(f)); }

#define CP16(dst, src) \
    asm volatile("cp.async.cg.shared.global [%0], [%1], 16;" :: "r"(dst), "l"(src))
#define CP_COMMIT() asm volatile("cp.async.commit_group;" ::: "memory")
#define CP_WAIT1()  asm volatile("cp.async.wait_group 1;" ::: "memory")
#define CP_WAIT0()  asm volatile("cp.async.wait_group 0;" ::: "memory")

#define MMA_TF32(c, a, b) \
    asm volatile("mma.sync.aligned.m16n8k8.row.col.f32.tf32.tf32.f32 " \
        "{%0,%1,%2,%3}, {%4,%5,%6,%7}, {%8,%9}, {%0,%1,%2,%3};" \
        : "+f"((c)[0]), "+f"((c)[1]), "+f"((c)[2]), "+f"((c)[3]) \
        : "r"((a)[0]), "r"((a)[1]), "r"((a)[2]), "r"((a)[3]), "r"((b)[0]), "r"((b)[1]))

// ldmatrix x4: 4 8x8(b16) matrices = 4 8x4(f32) tiles; thread t supplies
// the row address for matrix t>>3, row t&7; receives word (lane>>2, lane&3).
#define LDSM4(d0, d1, d2, d3, addr) \
    asm volatile("ldmatrix.sync.aligned.m8n8.x4.shared.b16 {%0,%1,%2,%3}, [%4];" \
        : "=r"(d0), "=r"(d1), "=r"(d2), "=r"(d3) : "r"(addr))

// swizzled smem float index for a [rows][32] panel
__device__ __forceinline__ int swz(int r, int c) {
    return r * 32 + ((((c >> 2) ^ (r & 7)) << 2) | (c & 3));
}

// ============ mma.sync tf32 GEMM, 3-stage pipeline, ldmatrix fragments =========
// C = epi( A[M,K] @ B[N,K]^T );  B row-major [N][K].
// EPI: 0=+bias  1=relu(+bias)  2=+bias+res
// VT: tiles with n0 >= vtn0 write TRANSPOSED to vtp[(n-vtn0)*vtld + m] (skip C).
// RND: round stored outputs to tf32 (outputs that feed flash_attn MMAs).
template<int BN, int EPI, int VT, int RND>
__global__ __launch_bounds__(256) void mma_gemm(
    const float* __restrict__ A, int lda,
    const float* __restrict__ B, int ldb,
    const float* __restrict__ bias, const float* __restrict__ res,
    float* __restrict__ C, int ldc, int K,
    float* __restrict__ vtp, int vtn0, int vtld)
{
    constexpr int WTM = (BN == 128) ? 64 : 32;
    constexpr int MW  = 128 / WTM;
    constexpr int MF  = WTM / 16;
    constexpr int NF  = 4;
    constexpr int SSZ = 128 * 32 + BN * 32;      // floats per stage

    const int m0 = blockIdx.y * 128;
    const int n0 = blockIdx.x * BN;

    extern __shared__ float smem[];
    const uint32_t uS = smem_u32(smem);

    const int tid  = threadIdx.x;
    const int lane = tid & 31;
    const int wid  = tid >> 5;
    const int wm   = wid & (MW - 1);
    const int wn   = wid / MW;
    const int laneR = lane >> 2, laneC = lane & 3;

    // ldmatrix per-thread addressing roles
    const int mat = lane >> 3, mrr = lane & 7;
    const int ag_hi = mat >> 1;
    const int bg_lo = mat & 1;
    int aro[MF], arx[MF];
#pragma unroll
    for (int mf = 0; mf < MF; mf++) {
        int r = wm * WTM + mf * 16 + ((mat & 1) << 3) + mrr;
        aro[mf] = r * 128; arx[mf] = r & 7;
    }
    int bro[NF / 2], brx[NF / 2];
#pragma unroll
    for (int p = 0; p < NF / 2; p++) {
        int r = wn * 32 + (2 * p + (mat >> 1)) * 8 + mrr;
        bro[p] = r * 128; brx[p] = r & 7;
    }

    const int nch = K >> 5;

    auto load_chunk = [&](int c) {
        const int st = c % 3;
        const uint32_t ua = uS + st * SSZ * 4;
        const uint32_t ub = ua + 128 * 32 * 4;
        const int k0 = c << 5;
#pragma unroll
        for (int i = 0; i < 4; i++) {
            int idx = tid + i * 256; int r = idx >> 3, f = idx & 7;
            CP16(ua + r * 128 + ((f ^ (r & 7)) << 4),
                 A + (size_t)(m0 + r) * lda + k0 + f * 4);
        }
#pragma unroll
        for (int i = 0; i < BN / 32; i++) {
            int idx = tid + i * 256; int r = idx >> 3, f = idx & 7;
            CP16(ub + r * 128 + ((f ^ (r & 7)) << 4),
                 B + (size_t)(n0 + r) * ldb + k0 + f * 4);
        }
        CP_COMMIT();
    };

    float acc[MF][NF][4] = {};

    load_chunk(0);
    load_chunk(1);
    for (int c = 0; c < nch; c++) {
        if (c + 1 < nch) CP_WAIT1(); else CP_WAIT0();
        __syncthreads();
        if (c + 2 < nch) load_chunk(c + 2);
        const int st = c % 3;
        const uint32_t uA_s = uS + st * SSZ * 4;
        const uint32_t uB_s = uA_s + 128 * 32 * 4;
#pragma unroll
        for (int ks = 0; ks < 4; ks++) {
            const int gA = 2 * ks + ag_hi;
            const int gB = 2 * ks + bg_lo;
            uint32_t af[MF][4];
#pragma unroll
            for (int mf = 0; mf < MF; mf++) {
                uint32_t d0, d1, d2, d3;
                LDSM4(d0, d1, d2, d3, uA_s + aro[mf] + ((gA ^ arx[mf]) << 4));
                af[mf][0] = f2tf(__uint_as_float(d0));
                af[mf][1] = f2tf(__uint_as_float(d1));
                af[mf][2] = f2tf(__uint_as_float(d2));
                af[mf][3] = f2tf(__uint_as_float(d3));
            }
            uint32_t bf[NF][2];
#pragma unroll
            for (int p = 0; p < NF / 2; p++) {
                uint32_t d0, d1, d2, d3;
                LDSM4(d0, d1, d2, d3, uB_s + bro[p] + ((gB ^ brx[p]) << 4));
                bf[2*p  ][0] = f2tf(__uint_as_float(d0));
                bf[2*p  ][1] = f2tf(__uint_as_float(d1));
                bf[2*p+1][0] = f2tf(__uint_as_float(d2));
                bf[2*p+1][1] = f2tf(__uint_as_float(d3));
            }
#pragma unroll
            for (int mf = 0; mf < MF; mf++)
#pragma unroll
                for (int nf = 0; nf < NF; nf++)
                    MMA_TF32(acc[mf][nf], af[mf], bf[nf]);
        }
    }

    const bool isv = VT && (n0 >= vtn0);
#pragma unroll
    for (int mf = 0; mf < MF; mf++) {
#pragma unroll
        for (int nf = 0; nf < NF; nf++) {
            int r  = m0 + wm * WTM + mf * 16 + laneR;
            int cc = n0 + wn * 32 + nf * 8 + laneC * 2;
            float v0 = acc[mf][nf][0], v1 = acc[mf][nf][1];
            float v2 = acc[mf][nf][2], v3 = acc[mf][nf][3];
            float2 bb = *(const float2*)(bias + cc);
            v0 += bb.x; v1 += bb.y; v2 += bb.x; v3 += bb.y;
            if (EPI == 1) {
                v0 = fmaxf(v0, 0.f); v1 = fmaxf(v1, 0.f);
                v2 = fmaxf(v2, 0.f); v3 = fmaxf(v3, 0.f);
            }
            if (EPI == 2) {
                float2 r0 = *(const float2*)(res + (size_t)r * ldc + cc);
                float2 r1 = *(const float2*)(res + (size_t)(r + 8) * ldc + cc);
                v0 += r0.x; v1 += r0.y; v2 += r1.x; v3 += r1.y;
            }
            if (RND) {
                v0 = rnd_tf(v0); v1 = rnd_tf(v1);
                v2 = rnd_tf(v2); v3 = rnd_tf(v3);
            }
            if (isv) {
                float* c0 = vtp + (size_t)(cc     - vtn0) * vtld;
                float* c1 = vtp + (size_t)(cc + 1 - vtn0) * vtld;
                c0[r] = v0; c1[r] = v1; c0[r + 8] = v2; c1[r + 8] = v3;
            } else {
                *(float2*)(C + (size_t)r * ldc + cc)       = make_float2(v0, v1);
                *(float2*)(C + (size_t)(r + 8) * ldc + cc) = make_float2(v2, v3);
            }
        }
    }
}

// ============ fused flash attention (double-buffered KV, ldmatrix, no cvt) =====
// Q/K/Vt inputs are PRE-ROUNDED tf32 bits; fragments go straight to mma.
template<int CAUSAL>
__global__ __launch_bounds__(256) void flash_attn(
    const float* __restrict__ Q, int ldq,
    const float* __restrict__ Kg, int ldk,
    const float* __restrict__ Vt, float* __restrict__ O, int Slen)
{
    extern __shared__ float sm[];
    float* sQ = sm;                 // 2 panels x 128x32 = 8192 floats
    float* sK = sm + 8192;          // 2 bufs x (2 panels x 64x32) = 8192
    float* sV = sm + 16384;         // 8192
    float* sP = sm + 24576;         // 8 warps x 16x64 = 8192

    const int mt = blockIdx.x, bh = blockIdx.y;
    const int b = bh >> 3, h = bh & 7;
    const int m0 = mt * 128;
    const int tid = threadIdx.x, lane = tid & 31, wid = tid >> 5;
    const int laneR = lane >> 2, laneC = lane & 3;

    const float* Qp = Q + ((size_t)b * TT + m0) * ldq + h * 64;
    const float* Kp = Kg + (size_t)b * Slen * ldk + h * 64;
    const float* Vp = Vt + (size_t)(h * 64) * (BB * Slen) + (size_t)b * Slen;
    float* Op = O + ((size_t)b * TT + m0) * DM + h * 64;

    const uint32_t uQ = smem_u32(sQ), uK = smem_u32(sK), uV = smem_u32(sV);
    const int wr0 = wid * 16;
    float* sPw = sP + wid * 1024;
    const uint32_t uPw = smem_u32(sPw);

    // ldmatrix roles
    const int mat = lane >> 3, mrr = lane & 7;
    const int ag_hi = mat >> 1;
    const int bg_lo = mat & 1;
    const int qrow = wr0 + ((mat & 1) << 3) + mrr;
    const int qro = qrow * 128, qrx = qrow & 7;
    const int prow = ((mat & 1) << 3) + mrr;
    const int pro = prow * 128, prx = prow & 7;
    int bro[4], brx[4];
#pragma unroll
    for (int p = 0; p < 4; p++) {
        int r = (2 * p + (mat >> 1)) * 8 + mrr;
        bro[p] = r * 128; brx[p] = r & 7;
    }

    // Q tile: 128 rows x 64 floats (joins first commit group)
#pragma unroll
    for (int i = 0; i < 8; i++) {
        int idx = tid + i * 256;
        int r = idx >> 4, f = idx & 15;
        int panel = f >> 3, fo = f & 7;
        CP16(uQ + (panel * 4096 + r * 32 + ((fo ^ (r & 7)) << 2)) * 4,
             Qp + (size_t)r * ldq + f * 4);
    }

    auto load_kv = [&](int c) {
        const int buf = c & 1;
        const int s0 = c * 64;
#pragma unroll
        for (int i = 0; i < 4; i++) {
            int idx = tid + i * 256;
            int r = idx >> 4, f = idx & 15;
            int panel = f >> 3, fo = f & 7;
            CP16(uK + (buf * 4096 + panel * 2048 + r * 32 + ((fo ^ (r & 7)) << 2)) * 4,
                 Kp + (size_t)(s0 + r) * ldk + f * 4);
        }
#pragma unroll
        for (int i = 0; i < 4; i++) {
            int idx = tid + i * 256;
            int r = idx >> 4, f = idx & 15;
            int panel = f >> 3, fo = f & 7;
            CP16(uV + (buf * 4096 + panel * 2048 + r * 32 + ((fo ^ (r & 7)) << 2)) * 4,
                 Vp + (size_t)r * (BB * Slen) + s0 + f * 4);
        }
        CP_COMMIT();
    };

    const int nch = CAUSAL ? (m0 + 128) / 64 : Slen / 64;
    float mr0 = -1e30f, mr1 = -1e30f, l0 = 0.f, l1 = 0.f;
    float oacc[8][4] = {};

    load_kv(0);
    for (int c = 0; c < nch; c++) {
        if (c + 1 < nch) { load_kv(c + 1); CP_WAIT1(); }
        else             { CP_WAIT0(); }
        __syncthreads();
        const int s0 = c * 64;
        const bool active = !CAUSAL || (s0 <= m0 + wr0 + 15);
        if (active) {
            const uint32_t uKb = uK + (c & 1) * 16384;
            const uint32_t uVb = uV + (c & 1) * 16384;

            // ---- S = Q @ K^T (fragments pre-rounded; no cvt) ----
            float sacc[8][4] = {};
#pragma unroll
            for (int ks = 0; ks < 8; ks++) {
                const int pa = ks >> 2;
                const int gA = ((ks & 3) << 1) + ag_hi;
                const int gB = ((ks & 3) << 1) + bg_lo;
                uint32_t af[4];
                LDSM4(af[0], af[1], af[2], af[3], uQ + (pa << 14) + qro + ((gA ^ qrx) << 4));
                uint32_t bf[8][2];
#pragma unroll
                for (int p = 0; p < 4; p++) {
                    LDSM4(bf[2*p][0], bf[2*p][1], bf[2*p+1][0], bf[2*p+1][1],
                          uKb + (pa << 13) + bro[p] + ((gB ^ brx[p]) << 4));
                }
#pragma unroll
                for (int nf = 0; nf < 8; nf++)
                    MMA_TF32(sacc[nf], af, bf[nf]);
            }

            // ---- scale + mask + online softmax ----
            const float SCL = 0.125f;
            const int t0g = m0 + wr0 + laneR;
            float rmax0 = -1e30f, rmax1 = -1e30f;
#pragma unroll
            for (int nf = 0; nf < 8; nf++) {
                int sg = s0 + nf * 8 + 2 * laneC;
                float v0 = sacc[nf][0] * SCL, v1 = sacc[nf][1] * SCL;
                float v2 = sacc[nf][2] * SCL, v3 = sacc[nf][3] * SCL;
                if (CAUSAL) {
                    if (sg     > t0g)     v0 = -1e30f;
                    if (sg + 1 > t0g)     v1 = -1e30f;
                    if (sg     > t0g + 8) v2 = -1e30f;
                    if (sg + 1 > t0g + 8) v3 = -1e30f;
                }
                sacc[nf][0] = v0; sacc[nf][1] = v1;
                sacc[nf][2] = v2; sacc[nf][3] = v3;
                rmax0 = fmaxf(rmax0, fmaxf(v0, v1));
                rmax1 = fmaxf(rmax1, fmaxf(v2, v3));
            }
            rmax0 = fmaxf(rmax0, __shfl_xor_sync(0xffffffffu, rmax0, 1));
            rmax0 = fmaxf(rmax0, __shfl_xor_sync(0xffffffffu, rmax0, 2));
            rmax1 = fmaxf(rmax1, __shfl_xor_sync(0xffffffffu, rmax1, 1));
            rmax1 = fmaxf(rmax1, __shfl_xor_sync(0xffffffffu, rmax1, 2));
            float mn0 = fmaxf(mr0, rmax0), mn1 = fmaxf(mr1, rmax1);
            float al0 = __expf(mr0 - mn0), al1 = __expf(mr1 - mn1);
            mr0 = mn0; mr1 = mn1;

            float rs0 = 0.f, rs1 = 0.f;
            uint32_t* sPu = (uint32_t*)sPw;
#pragma unroll
            for (int nf = 0; nf < 8; nf++) {
                float e0 = __expf(sacc[nf][0] - mn0);
                float e1 = __expf(sacc[nf][1] - mn0);
                float e2 = __expf(sacc[nf][2] - mn1);
                float e3 = __expf(sacc[nf][3] - mn1);
                rs0 += e0 + e1; rs1 += e2 + e3;
                int cc = nf * 8 + 2 * laneC;
                int pa = cc >> 5, ca = cc & 31;
                *(uint2*)&sPu[pa * 512 + swz(laneR,     ca)] = make_uint2(f2tf(e0), f2tf(e1));
                *(uint2*)&sPu[pa * 512 + swz(laneR + 8, ca)] = make_uint2(f2tf(e2), f2tf(e3));
            }
            rs0 += __shfl_xor_sync(0xffffffffu, rs0, 1);
            rs0 += __shfl_xor_sync(0xffffffffu, rs0, 2);
            rs1 += __shfl_xor_sync(0xffffffffu, rs1, 1);
            rs1 += __shfl_xor_sync(0xffffffffu, rs1, 2);
            l0 = l0 * al0 + rs0;
            l1 = l1 * al1 + rs1;
#pragma unroll
            for (int nf = 0; nf < 8; nf++) {
                oacc[nf][0] *= al0; oacc[nf][1] *= al0;
                oacc[nf][2] *= al1; oacc[nf][3] *= al1;
            }
            __syncwarp();

            // ---- O += P @ V (no cvt) ----
#pragma unroll
            for (int ks = 0; ks < 8; ks++) {
                const int pa = ks >> 2;
                const int gA = ((ks & 3) << 1) + ag_hi;
                const int gB = ((ks & 3) << 1) + bg_lo;
                uint32_t af[4];
                LDSM4(af[0], af[1], af[2], af[3], uPw + (pa << 11) + pro + ((gA ^ prx) << 4));
#pragma unroll
                for (int p = 0; p < 4; p++) {
                    uint32_t bf0[2], bf1[2];
                    LDSM4(bf0[0], bf0[1], bf1[0], bf1[1],
                          uVb + (pa << 13) + bro[p] + ((gB ^ brx[p]) << 4));
                    MMA_TF32(oacc[2*p],     af, bf0);
                    MMA_TF32(oacc[2*p + 1], af, bf1);
                }
            }
        }
        __syncthreads();
    }

    const float inv0 = 1.f / l0, inv1 = 1.f / l1;
#pragma unroll
    for (int nf = 0; nf < 8; nf++) {
        int cc = nf * 8 + 2 * laneC;
        int r = wr0 + laneR;
        *(float2*)(Op + (size_t)r * DM + cc) =
            make_float2(oacc[nf][0] * inv0, oacc[nf][1] * inv0);
        *(float2*)(Op + (size_t)(r + 8) * DM + cc) =
            make_float2(oacc[nf][2] * inv1, oacc[nf][3] * inv1);
    }
}

// ---------------- prep: all weight transposes + bias concats, one launch -------
struct PrepArgs {
    const float* s8[8]; float* d8[8];
    const float* w1; float* w1t;
    const float* w2; float* w2t;
    const float* bq; const float* bk; const float* bv;
    const float* cbk; const float* cbv;
    float* b1; float* b2;
};
__global__ __launch_bounds__(256) void prep_all(PrepArgs p)
{
    __shared__ float t[32][33];
    const int idx = blockIdx.x;
    const int tx = threadIdx.x, ty = threadIdx.y;

    const float* src; float* dst; int R, C, bx, by;
    if (idx < 2048) {
        int m = idx >> 8, tt = idx & 255;
        src = p.s8[m]; dst = p.d8[m]; R = 512; C = 512;
        bx = tt & 15; by = tt >> 4;
    } else if (idx < 3072) {
        int tt = idx - 2048;
        src = p.w1; dst = p.w1t; R = 512; C = 2048;
        bx = tt & 63; by = tt >> 6;
    } else if (idx < 4096) {
        int tt = idx - 3072;
        src = p.w2; dst = p.w2t; R = 2048; C = 512;
        bx = tt & 15; by = tt >> 4;
    } else {
        int i = ty * 32 + tx;
#pragma unroll
        for (int j = 0; j < 2; j++) {
            int c = i + j * 256;
            p.b1[c] = p.bq[c]; p.b1[512 + c] = p.bk[c]; p.b1[1024 + c] = p.bv[c];
            p.b2[c] = p.cbk[c]; p.b2[512 + c] = p.cbv[c];
        }
        return;
    }
    int x = bx * 32 + tx, y = by * 32;
#pragma unroll
    for (int i = 0; i < 4; i++)
        t[ty + i * 8][tx] = src[(size_t)(y + ty + i * 8) * C + x];
    __syncthreads();
    int x2 = by * 32 + tx, y2 = bx * 32;
#pragma unroll
    for (int i = 0; i < 4; i++)
        dst[(size_t)(y2 + ty + i * 8) * R + x2] = t[tx][ty + i * 8];
}

// ---------------- LayerNorm (float4) -------------------------------------------
__global__ __launch_bounds__(128) void ln_kernel(
    const float* __restrict__ x, const float* __restrict__ g,
    const float* __restrict__ b, float* __restrict__ out)
{
    const int row = blockIdx.x;
    const int tid = threadIdx.x;
    float4 v = *(const float4*)(x + (size_t)row * DM + tid * 4);

    float s  = v.x + v.y + v.z + v.w;
    float s2 = v.x * v.x + v.y * v.y + v.z * v.z + v.w * v.w;
#pragma unroll
    for (int o = 16; o; o >>= 1) {
        s  += __shfl_down_sync(0xffffffffu, s,  o);
        s2 += __shfl_down_sync(0xffffffffu, s2, o);
    }
    __shared__ float rs[4], rs2[4];
    int wid = tid >> 5, lane = tid & 31;
    if (lane == 0) { rs[wid] = s; rs2[wid] = s2; }
    __syncthreads();
    if (tid == 0) {
        float a = rs[0] + rs[1] + rs[2] + rs[3];
        float a2 = rs2[0] + rs2[1] + rs2[2] + rs2[3];
        rs[0] = a; rs2[0] = a2;
    }
    __syncthreads();
    float mean = rs[0] * (1.0f / DM);
    float var  = rs2[0] * (1.0f / DM) - mean * mean;
    float inv  = rsqrtf(var + 1e-5f);

    float4 gg = *(const float4*)(g + tid * 4);
    float4 bb = *(const float4*)(b + tid * 4);
    float4 o;
    o.x = (v.x - mean) * inv * gg.x + bb.x;
    o.y = (v.y - mean) * inv * gg.y + bb.y;
    o.z = (v.z - mean) * inv * gg.z + bb.z;
    o.w = (v.w - mean) * inv * gg.w + bb.w;
    *(float4*)(out + (size_t)row * DM + tid * 4) = o;
}

// ---------------- launch -------------------------------------------------------
extern "C" void kernel_launch(void* const* d_in, const int* in_sizes, int n_in,
                              void* d_out, int out_size)
{
    const float* tgt    = (const float*)d_in[0];
    const float* memory = (const float*)d_in[1];

    const size_t OW = (size_t)LAYER * DM * DM;
    const size_t OB = (size_t)LAYER * DM;
    const float* sa_wq = (const float*)d_in[4]  + OW;
    const float* sa_wk = (const float*)d_in[5]  + OW;
    const float* sa_wv = (const float*)d_in[6]  + OW;
    const float* sa_wo = (const float*)d_in[7]  + OW;
    const float* sa_bq = (const float*)d_in[8]  + OB;
    const float* sa_bk = (const float*)d_in[9]  + OB;
    const float* sa_bv = (const float*)d_in[10] + OB;
    const float* sa_bo = (const float*)d_in[11] + OB;
    const float* ca_wq = (const float*)d_in[12] + OW;
    const float* ca_wk = (const float*)d_in[13] + OW;
    const float* ca_wv = (const float*)d_in[14] + OW;
    const float* ca_wo = (const float*)d_in[15] + OW;
    const float* ca_bq = (const float*)d_in[16] + OB;
    const float* ca_bk = (const float*)d_in[17] + OB;
    const float* ca_bv = (const float*)d_in[18] + OB;
    const float* ca_bo = (const float*)d_in[19] + OB;
    const float* ff_w1 = (const float*)d_in[20] + (size_t)LAYER * DM * FFD;
    const float* ff_b1 = (const float*)d_in[21] + (size_t)LAYER * FFD;
    const float* ff_w2 = (const float*)d_in[22] + (size_t)LAYER * FFD * DM;
    const float* ff_b2 = (const float*)d_in[23] + OB;
    const float* ln_g  = (const float*)d_in[24];
    const float* ln_b  = (const float*)d_in[25];

    float *n_, *q_, *qkv_, *kv_, *vt_, *at_, *x_, *ff_, *wt_, *w1t_, *w2t_, *bc1_, *bc2_;
    cudaGetSymbolAddress((void**)&n_,   g_n);
    cudaGetSymbolAddress((void**)&q_,   g_q);
    cudaGetSymbolAddress((void**)&qkv_, g_qkv);
    cudaGetSymbolAddress((void**)&kv_,  g_kv);
    cudaGetSymbolAddress((void**)&vt_,  g_vt);
    cudaGetSymbolAddress((void**)&at_,  g_at);
    cudaGetSymbolAddress((void**)&x_,   g_x);
    cudaGetSymbolAddress((void**)&ff_,  g_ff);
    cudaGetSymbolAddress((void**)&wt_,  g_wt);
    cudaGetSymbolAddress((void**)&w1t_, g_w1t);
    cudaGetSymbolAddress((void**)&w2t_, g_w2t);
    cudaGetSymbolAddress((void**)&bc1_, g_bc1);
    cudaGetSymbolAddress((void**)&bc2_, g_bc2);

    const int S128 = 3 * (128 * 32 + 128 * 32) * 4;   // 98304
    const int S64  = 3 * (128 * 32 + 64  * 32) * 4;   // 73728
    const int SFL  = 32768 * 4;                       // 131072
    cudaFuncSetAttribute(mma_gemm<128,0,1,1>, cudaFuncAttributeMaxDynamicSharedMemorySize, S128);
    cudaFuncSetAttribute(mma_gemm<128,1,0,0>, cudaFuncAttributeMaxDynamicSharedMemorySize, S128);
    cudaFuncSetAttribute(mma_gemm<64,0,0,1>,  cudaFuncAttributeMaxDynamicSharedMemorySize, S64);
    cudaFuncSetAttribute(mma_gemm<64,2,0,0>,  cudaFuncAttributeMaxDynamicSharedMemorySize, S64);
    cudaFuncSetAttribute(flash_attn<1>,       cudaFuncAttributeMaxDynamicSharedMemorySize, SFL);
    cudaFuncSetAttribute(flash_attn<0>,       cudaFuncAttributeMaxDynamicSharedMemorySize, SFL);

    const int M = BB * TT;   // 4096

    float* wqkvT = wt_ + 0 * DM * DM;    // slots 0,1,2
    float* woT   = wt_ + 3 * DM * DM;
    float* cqT   = wt_ + 4 * DM * DM;
    float* ckvT  = wt_ + 5 * DM * DM;    // slots 5,6
    float* coT   = wt_ + 7 * DM * DM;

    PrepArgs pa;
    pa.s8[0]=sa_wq; pa.d8[0]=wt_ + 0*DM*DM;
    pa.s8[1]=sa_wk; pa.d8[1]=wt_ + 1*DM*DM;
    pa.s8[2]=sa_wv; pa.d8[2]=wt_ + 2*DM*DM;
    pa.s8[3]=sa_wo; pa.d8[3]=woT;
    pa.s8[4]=ca_wq; pa.d8[4]=cqT;
    pa.s8[5]=ca_wk; pa.d8[5]=wt_ + 5*DM*DM;
    pa.s8[6]=ca_wv; pa.d8[6]=wt_ + 6*DM*DM;
    pa.s8[7]=ca_wo; pa.d8[7]=coT;
    pa.w1 = ff_w1; pa.w1t = w1t_;
    pa.w2 = ff_w2; pa.w2t = w2t_;
    pa.bq = sa_bq; pa.bk = sa_bk; pa.bv = sa_bv;
    pa.cbk = ca_bk; pa.cbv = ca_bv;
    pa.b1 = bc1_; pa.b2 = bc2_;
    prep_all<<<4097, dim3(32,8)>>>(pa);

    // ---- self-attention: x = tgt + SA(LN(tgt)) ----
    ln_kernel<<<M, 128>>>(tgt, ln_g, ln_b, n_);
    mma_gemm<128,0,1,1><<<dim3(12,32),256,S128>>>(
        n_,DM, wqkvT,DM, bc1_,nullptr, qkv_,3*DM, DM, vt_,1024,M);
    flash_attn<1><<<dim3(4,64),256,SFL>>>(qkv_,3*DM, qkv_+DM,3*DM, vt_, at_, TT);
    mma_gemm<64,2,0,0><<<dim3(8,32),256,S64>>>(
        at_,DM, woT,DM, sa_bo,tgt, x_,DM, DM, nullptr,0,0);

    // ---- cross-attention: x += CA(LN(x), memory) ----
    ln_kernel<<<M, 128>>>(x_, ln_g, ln_b, n_);
    mma_gemm<64,0,0,1><<<dim3(8,32),256,S64>>>(
        n_,DM, cqT,DM, ca_bq,nullptr, q_,DM, DM, nullptr,0,0);
    mma_gemm<128,0,1,1><<<dim3(8,64),256,S128>>>(
        memory,DM, ckvT,DM, bc2_,nullptr, kv_,2*DM, DM, vt_,512,BB*SS);
    flash_attn<0><<<dim3(4,64),256,SFL>>>(q_,DM, kv_,2*DM, vt_, at_, SS);
    mma_gemm<64,2,0,0><<<dim3(8,32),256,S64>>>(
        at_,DM, coT,DM, ca_bo,x_, x_,DM, DM, nullptr,0,0);

    // ---- FFN: x += W2 relu(W1 LN(x)) ----
    ln_kernel<<<M, 128>>>(x_, ln_g, ln_b, n_);
    mma_gemm<128,1,0,0><<<dim3(16,32),256,S128>>>(
        n_,DM,  w1t_,DM,  ff_b1,nullptr, ff_,FFD, DM, nullptr,0,0);
    mma_gemm<64,2,0,0><<<dim3(8,32),256,S64>>>(
        ff_,FFD, w2t_,FFD, ff_b2,x_, x_,DM, FFD, nullptr,0,0);

    // ---- final LN -> out ----
    ln_kernel<<<M, 128>>>(x_, ln_g, ln_b, (float*)d_out);
}

// round 10
// speedup vs baseline: 2.8881x; 1.9084x over previous
#include <cuda_runtime.h>
#include <cuda_fp16.h>
#include <cstdint>

// Problem constants
#define NH   8
#define DM   512
#define FFD  2048
#define BB   8
#define TT   512
#define SS   1024
#define LAYER 5

// ---------------- scratch (device globals) ------------------------------------
__device__ __half g_nh  [BB*TT*DM];            // LN output (half)
__device__ __half g_qh  [BB*TT*DM];            // CA Q
__device__ __half g_qkvh[BB*TT*3*DM];          // fused SA QKV (V region redirected)
__device__ __half g_kvh [BB*SS*2*DM];          // fused CA KV  (V region redirected)
__device__ __half g_vth [DM*BB*SS];            // transposed V [512][B*S]
__device__ __half g_ath [BB*TT*DM];            // attention out
__device__ __half g_ffh [BB*TT*FFD];           // FFN hidden
__device__ __half g_memh[BB*SS*DM];            // memory converted to half
__device__ __half g_wth [8*DM*DM];             // 8 transposed weights (half)
__device__ __half g_w1th[FFD*DM];
__device__ __half g_w2th[DM*FFD];
__device__ float  g_x   [BB*TT*DM];            // residual stream (fp32)
__device__ float  g_bc1 [3*DM];
__device__ float  g_bc2 [2*DM];

// ---------------- helpers ------------------------------------------------------
__device__ __forceinline__ uint32_t smem_u32(const void* p) {
    uint32_t a;
    asm("{ .reg .u64 t; cvta.to.shared.u64 t, %1; cvt.u32.u64 %0, t; }" : "=r"(a) : "l"(p));
    return a;
}
#define CP16(dst, src) \
    asm volatile("cp.async.cg.shared.global [%0], [%1], 16;" :: "r"(dst), "l"(src))
#define CP_COMMIT() asm volatile("cp.async.commit_group;" ::: "memory")
#define CP_WAIT1()  asm volatile("cp.async.wait_group 1;" ::: "memory")
#define CP_WAIT0()  asm volatile("cp.async.wait_group 0;" ::: "memory")

// fp16 mma: D(f32) += A(f16) * B(f16);  A 4 regs, B 2 regs, C 4 f32
#define MMA_F16(c, a, b) \
    asm volatile("mma.sync.aligned.m16n8k16.row.col.f32.f16.f16.f32 " \
        "{%0,%1,%2,%3}, {%4,%5,%6,%7}, {%8,%9}, {%0,%1,%2,%3};" \
        : "+f"((c)[0]), "+f"((c)[1]), "+f"((c)[2]), "+f"((c)[3]) \
        : "r"((a)[0]), "r"((a)[1]), "r"((a)[2]), "r"((a)[3]), "r"((b)[0]), "r"((b)[1]))

#define LDSM4(d0, d1, d2, d3, addr) \
    asm volatile("ldmatrix.sync.aligned.m8n8.x4.shared.b16 {%0,%1,%2,%3}, [%4];" \
        : "=r"(d0), "=r"(d1), "=r"(d2), "=r"(d3) : "r"(addr))

// ============ mma.sync fp16 GEMM, 3-stage pipeline, ldmatrix fragments =========
// C = epi( A[M,K] @ B[N,K]^T );  A,B half row-major; K-chunk = 64 halves (128B rows)
// EPI: 0=+bias  1=relu(+bias)  2=+bias+res(fp32)
// HOUT: 1 -> C is half; 0 -> C is float
// VT: tiles with n0 >= vtn0 write TRANSPOSED half to vtp[(n-vtn0)*vtld + m]
template<int BN, int EPI, int HOUT, int VT>
__global__ __launch_bounds__(256) void mma_gemm(
    const __half* __restrict__ A, int lda,
    const __half* __restrict__ B, int ldb,
    const float* __restrict__ bias, const float* __restrict__ res,
    void* __restrict__ Cv, int ldc, int K,
    __half* __restrict__ vtp, int vtn0, int vtld)
{
    constexpr int WTM = (BN == 128) ? 64 : 32;
    constexpr int MW  = 128 / WTM;
    constexpr int MF  = WTM / 16;
    constexpr int NF  = 4;
    constexpr int SSZB = (128 + BN) * 128;       // bytes per stage

    const int m0 = blockIdx.y * 128;
    const int n0 = blockIdx.x * BN;

    extern __shared__ char smem[];
    const uint32_t uS = smem_u32(smem);

    const int tid  = threadIdx.x;
    const int lane = tid & 31;
    const int wid  = tid >> 5;
    const int wm   = wid & (MW - 1);
    const int wn   = wid / MW;
    const int laneR = lane >> 2, laneC = lane & 3;

    // ldmatrix per-thread addressing roles (16B group = 8 halves)
    const int mat = lane >> 3, mrr = lane & 7;
    const int ag_hi = mat >> 1;
    const int bg_lo = mat & 1;
    int aro[MF], arx[MF];
#pragma unroll
    for (int mf = 0; mf < MF; mf++) {
        int r = wm * WTM + mf * 16 + ((mat & 1) << 3) + mrr;
        aro[mf] = r * 128; arx[mf] = r & 7;
    }
    int bro[NF / 2], brx[NF / 2];
#pragma unroll
    for (int p = 0; p < NF / 2; p++) {
        int r = wn * 32 + (2 * p + (mat >> 1)) * 8 + mrr;
        bro[p] = r * 128; brx[p] = r & 7;
    }

    const int nch = K >> 6;    // 64 halves per chunk

    auto load_chunk = [&](int c) {
        const int st = c % 3;
        const uint32_t ua = uS + st * SSZB;
        const uint32_t ub = ua + 128 * 128;
        const int k0 = c << 6;
#pragma unroll
        for (int i = 0; i < 4; i++) {
            int idx = tid + i * 256; int r = idx >> 3, f = idx & 7;
            CP16(ua + r * 128 + ((f ^ (r & 7)) << 4),
                 A + (size_t)(m0 + r) * lda + k0 + f * 8);
        }
#pragma unroll
        for (int i = 0; i < BN / 32; i++) {
            int idx = tid + i * 256; int r = idx >> 3, f = idx & 7;
            CP16(ub + r * 128 + ((f ^ (r & 7)) << 4),
                 B + (size_t)(n0 + r) * ldb + k0 + f * 8);
        }
        CP_COMMIT();
    };

    float acc[MF][NF][4] = {};

    load_chunk(0);
    load_chunk(1);
    for (int c = 0; c < nch; c++) {
        if (c + 1 < nch) CP_WAIT1(); else CP_WAIT0();
        __syncthreads();
        if (c + 2 < nch) load_chunk(c + 2);
        const int st = c % 3;
        const uint32_t uA_s = uS + st * SSZB;
        const uint32_t uB_s = uA_s + 128 * 128;
#pragma unroll
        for (int ks = 0; ks < 4; ks++) {
            const int gA = 2 * ks + ag_hi;
            const int gB = 2 * ks + bg_lo;
            uint32_t af[MF][4];
#pragma unroll
            for (int mf = 0; mf < MF; mf++)
                LDSM4(af[mf][0], af[mf][1], af[mf][2], af[mf][3],
                      uA_s + aro[mf] + ((gA ^ arx[mf]) << 4));
            uint32_t bf[NF][2];
#pragma unroll
            for (int p = 0; p < NF / 2; p++)
                LDSM4(bf[2*p][0], bf[2*p][1], bf[2*p+1][0], bf[2*p+1][1],
                      uB_s + bro[p] + ((gB ^ brx[p]) << 4));
#pragma unroll
            for (int mf = 0; mf < MF; mf++)
#pragma unroll
                for (int nf = 0; nf < NF; nf++)
                    MMA_F16(acc[mf][nf], af[mf], bf[nf]);
        }
    }

    const bool isv = VT && (n0 >= vtn0);
#pragma unroll
    for (int mf = 0; mf < MF; mf++) {
#pragma unroll
        for (int nf = 0; nf < NF; nf++) {
            int r  = m0 + wm * WTM + mf * 16 + laneR;
            int cc = n0 + wn * 32 + nf * 8 + laneC * 2;
            float v0 = acc[mf][nf][0], v1 = acc[mf][nf][1];
            float v2 = acc[mf][nf][2], v3 = acc[mf][nf][3];
            float2 bb = *(const float2*)(bias + cc);
            v0 += bb.x; v1 += bb.y; v2 += bb.x; v3 += bb.y;
            if (EPI == 1) {
                v0 = fmaxf(v0, 0.f); v1 = fmaxf(v1, 0.f);
                v2 = fmaxf(v2, 0.f); v3 = fmaxf(v3, 0.f);
            }
            if (EPI == 2) {
                float2 r0 = *(const float2*)(res + (size_t)r * ldc + cc);
                float2 r1 = *(const float2*)(res + (size_t)(r + 8) * ldc + cc);
                v0 += r0.x; v1 += r0.y; v2 += r1.x; v3 += r1.y;
            }
            if (isv) {
                __half* c0 = vtp + (size_t)(cc     - vtn0) * vtld;
                __half* c1 = vtp + (size_t)(cc + 1 - vtn0) * vtld;
                c0[r] = __float2half(v0); c1[r] = __float2half(v1);
                c0[r + 8] = __float2half(v2); c1[r + 8] = __float2half(v3);
            } else if (HOUT) {
                __half* Ch = (__half*)Cv;
                *(__half2*)(Ch + (size_t)r * ldc + cc)       = __floats2half2_rn(v0, v1);
                *(__half2*)(Ch + (size_t)(r + 8) * ldc + cc) = __floats2half2_rn(v2, v3);
            } else {
                float* Cf = (float*)Cv;
                *(float2*)(Cf + (size_t)r * ldc + cc)       = make_float2(v0, v1);
                *(float2*)(Cf + (size_t)(r + 8) * ldc + cc) = make_float2(v2, v3);
            }
        }
    }
}

// ============ fused flash attention (fp16 operands, 2 CTA/SM) ===================
// Q [.,ldq] half (head h at col h*64); K [.,ldk] half; Vt [512][B*Slen] half.
// smem: Q 16K | K 2x8K | V 2x8K | P 8x2K  = 64 KB
template<int CAUSAL>
__global__ __launch_bounds__(256, 2) void flash_attn(
    const __half* __restrict__ Q, int ldq,
    const __half* __restrict__ Kg, int ldk,
    const __half* __restrict__ Vt, __half* __restrict__ O, int Slen)
{
    extern __shared__ char sm[];
    const uint32_t uQ = smem_u32(sm);
    const uint32_t uK = uQ + 16384;
    const uint32_t uV = uK + 16384;
    const uint32_t uP = uV + 16384;

    const int mt = blockIdx.x, bh = blockIdx.y;
    const int b = bh >> 3, h = bh & 7;
    const int m0 = mt * 128;
    const int tid = threadIdx.x, lane = tid & 31, wid = tid >> 5;
    const int laneR = lane >> 2, laneC = lane & 3;

    const __half* Qp = Q + ((size_t)b * TT + m0) * ldq + h * 64;
    const __half* Kp = Kg + (size_t)b * Slen * ldk + h * 64;
    const __half* Vp = Vt + (size_t)(h * 64) * (BB * Slen) + (size_t)b * Slen;
    __half* Op = O + ((size_t)b * TT + m0) * DM + h * 64;

    const int wr0 = wid * 16;
    const uint32_t uPw = uP + wid * 2048;
    char* sPw = sm + 49152 + wid * 2048;

    // ldmatrix roles
    const int mat = lane >> 3, mrr = lane & 7;
    const int ag_hi = mat >> 1;
    const int bg_lo = mat & 1;
    const int qrow = wr0 + ((mat & 1) << 3) + mrr;
    const int qro = qrow * 128, qrx = qrow & 7;
    const int prow = ((mat & 1) << 3) + mrr;
    const int pro = prow * 128, prx = prow & 7;
    int bro[4], brx[4];
#pragma unroll
    for (int p = 0; p < 4; p++) {
        int r = p * 16 + ((mat >> 1) << 3) + mrr;
        bro[p] = r * 128; brx[p] = r & 7;
    }

    // Q tile: 128 rows x 64 halves = 128B/row (joins first commit group)
#pragma unroll
    for (int i = 0; i < 4; i++) {
        int idx = tid + i * 256;
        int r = idx >> 3, f = idx & 7;
        CP16(uQ + r * 128 + ((f ^ (r & 7)) << 4), Qp + (size_t)r * ldq + f * 8);
    }

    auto load_kv = [&](int c) {
        const int buf = c & 1;
        const int s0 = c * 64;
#pragma unroll
        for (int i = 0; i < 2; i++) {
            int idx = tid + i * 256;
            int r = idx >> 3, f = idx & 7;
            CP16(uK + buf * 8192 + r * 128 + ((f ^ (r & 7)) << 4),
                 Kp + (size_t)(s0 + r) * ldk + f * 8);
        }
#pragma unroll
        for (int i = 0; i < 2; i++) {
            int idx = tid + i * 256;
            int r = idx >> 3, f = idx & 7;
            CP16(uV + buf * 8192 + r * 128 + ((f ^ (r & 7)) << 4),
                 Vp + (size_t)r * (BB * Slen) + s0 + f * 8);
        }
        CP_COMMIT();
    };

    const int nch = CAUSAL ? (m0 + 128) / 64 : Slen / 64;
    float mr0 = -1e30f, mr1 = -1e30f, l0 = 0.f, l1 = 0.f;
    float oacc[8][4] = {};

    load_kv(0);
    for (int c = 0; c < nch; c++) {
        if (c + 1 < nch) { load_kv(c + 1); CP_WAIT1(); }
        else             { CP_WAIT0(); }
        __syncthreads();
        const int s0 = c * 64;
        const bool active = !CAUSAL || (s0 <= m0 + wr0 + 15);
        if (active) {
            const uint32_t uKb = uK + (c & 1) * 8192;
            const uint32_t uVb = uV + (c & 1) * 8192;

            // ---- S = Q @ K^T ----
            float sacc[8][4] = {};
#pragma unroll
            for (int ks = 0; ks < 4; ks++) {
                const int gA = 2 * ks + ag_hi;
                const int gB = 2 * ks + bg_lo;
                uint32_t af[4];
                LDSM4(af[0], af[1], af[2], af[3], uQ + qro + ((gA ^ qrx) << 4));
                uint32_t bf[8][2];
#pragma unroll
                for (int p = 0; p < 4; p++)
                    LDSM4(bf[2*p][0], bf[2*p][1], bf[2*p+1][0], bf[2*p+1][1],
                          uKb + bro[p] + ((gB ^ brx[p]) << 4));
#pragma unroll
                for (int nf = 0; nf < 8; nf++)
                    MMA_F16(sacc[nf], af, bf[nf]);
            }

            // ---- scale + mask + online softmax ----
            const float SCL = 0.125f;
            const int t0g = m0 + wr0 + laneR;
            float rmax0 = -1e30f, rmax1 = -1e30f;
#pragma unroll
            for (int nf = 0; nf < 8; nf++) {
                int sg = s0 + nf * 8 + 2 * laneC;
                float v0 = sacc[nf][0] * SCL, v1 = sacc[nf][1] * SCL;
                float v2 = sacc[nf][2] * SCL, v3 = sacc[nf][3] * SCL;
                if (CAUSAL) {
                    if (sg     > t0g)     v0 = -1e30f;
                    if (sg + 1 > t0g)     v1 = -1e30f;
                    if (sg     > t0g + 8) v2 = -1e30f;
                    if (sg + 1 > t0g + 8) v3 = -1e30f;
                }
                sacc[nf][0] = v0; sacc[nf][1] = v1;
                sacc[nf][2] = v2; sacc[nf][3] = v3;
                rmax0 = fmaxf(rmax0, fmaxf(v0, v1));
                rmax1 = fmaxf(rmax1, fmaxf(v2, v3));
            }
            rmax0 = fmaxf(rmax0, __shfl_xor_sync(0xffffffffu, rmax0, 1));
            rmax0 = fmaxf(rmax0, __shfl_xor_sync(0xffffffffu, rmax0, 2));
            rmax1 = fmaxf(rmax1, __shfl_xor_sync(0xffffffffu, rmax1, 1));
            rmax1 = fmaxf(rmax1, __shfl_xor_sync(0xffffffffu, rmax1, 2));
            float mn0 = fmaxf(mr0, rmax0), mn1 = fmaxf(mr1, rmax1);
            float al0 = __expf(mr0 - mn0), al1 = __expf(mr1 - mn1);
            mr0 = mn0; mr1 = mn1;

            float rs0 = 0.f, rs1 = 0.f;
#pragma unroll
            for (int nf = 0; nf < 8; nf++) {
                float e0 = __expf(sacc[nf][0] - mn0);
                float e1 = __expf(sacc[nf][1] - mn0);
                float e2 = __expf(sacc[nf][2] - mn1);
                float e3 = __expf(sacc[nf][3] - mn1);
                rs0 += e0 + e1; rs1 += e2 + e3;
                // store P as half2: row laneR / laneR+8, col group nf, offset laneC*4
                int off = ((nf ^ (laneR & 7)) << 4) + laneC * 4;
                *(__half2*)(sPw + laneR * 128 + off)       = __floats2half2_rn(e0, e1);
                *(__half2*)(sPw + (laneR + 8) * 128 + off) = __floats2half2_rn(e2, e3);
            }
            rs0 += __shfl_xor_sync(0xffffffffu, rs0, 1);
            rs0 += __shfl_xor_sync(0xffffffffu, rs0, 2);
            rs1 += __shfl_xor_sync(0xffffffffu, rs1, 1);
            rs1 += __shfl_xor_sync(0xffffffffu, rs1, 2);
            l0 = l0 * al0 + rs0;
            l1 = l1 * al1 + rs1;
#pragma unroll
            for (int nf = 0; nf < 8; nf++) {
                oacc[nf][0] *= al0; oacc[nf][1] *= al0;
                oacc[nf][2] *= al1; oacc[nf][3] *= al1;
            }
            __syncwarp();

            // ---- O += P @ V ----
#pragma unroll
            for (int ks = 0; ks < 4; ks++) {
                const int gA = 2 * ks + ag_hi;
                const int gB = 2 * ks + bg_lo;
                uint32_t af[4];
                LDSM4(af[0], af[1], af[2], af[3], uPw + pro + ((gA ^ prx) << 4));
#pragma unroll
                for (int p = 0; p < 4; p++) {
                    uint32_t bf0[2], bf1[2];
                    LDSM4(bf0[0], bf0[1], bf1[0], bf1[1],
                          uVb + bro[p] + ((gB ^ brx[p]) << 4));
                    MMA_F16(oacc[2*p],     af, bf0);
                    MMA_F16(oacc[2*p + 1], af, bf1);
                }
            }
        }
        __syncthreads();
    }

    const float inv0 = 1.f / l0, inv1 = 1.f / l1;
#pragma unroll
    for (int nf = 0; nf < 8; nf++) {
        int cc = nf * 8 + 2 * laneC;
        int r = wr0 + laneR;
        *(__half2*)(Op + (size_t)r * DM + cc) =
            __floats2half2_rn(oacc[nf][0] * inv0, oacc[nf][1] * inv0);
        *(__half2*)(Op + (size_t)(r + 8) * DM + cc) =
            __floats2half2_rn(oacc[nf][2] * inv1, oacc[nf][3] * inv1);
    }
}

// ---------------- prep: transposes->half + bias concats + memory->half ---------
struct PrepArgs {
    const float* s8[8]; __half* d8[8];
    const float* w1; __half* w1t;
    const float* w2; __half* w2t;
    const float* bq; const float* bk; const float* bv;
    const float* cbk; const float* cbv;
    float* b1; float* b2;
    const float* mem; __half* memh;
};
__global__ __launch_bounds__(256) void prep_all(PrepArgs p)
{
    __shared__ float t[32][33];
    const int idx = blockIdx.x;
    const int tx = threadIdx.x, ty = threadIdx.y;

    if (idx >= 4097) {   // memory fp32 -> half, 2048 floats per block
        int j = idx - 4097;
        int base = j * 2048 + (ty * 32 + tx) * 8;
        float4 a = *(const float4*)(p.mem + base);
        float4 b = *(const float4*)(p.mem + base + 4);
        __half2 h0 = __floats2half2_rn(a.x, a.y);
        __half2 h1 = __floats2half2_rn(a.z, a.w);
        __half2 h2 = __floats2half2_rn(b.x, b.y);
        __half2 h3 = __floats2half2_rn(b.z, b.w);
        uint4 o;
        o.x = *(uint32_t*)&h0; o.y = *(uint32_t*)&h1;
        o.z = *(uint32_t*)&h2; o.w = *(uint32_t*)&h3;
        *(uint4*)(p.memh + base) = o;
        return;
    }

    const float* src; __half* dst; int R, C, bx, by;
    if (idx < 2048) {
        int m = idx >> 8, tt = idx & 255;
        src = p.s8[m]; dst = p.d8[m]; R = 512; C = 512;
        bx = tt & 15; by = tt >> 4;
    } else if (idx < 3072) {
        int tt = idx - 2048;
        src = p.w1; dst = p.w1t; R = 512; C = 2048;
        bx = tt & 63; by = tt >> 6;
    } else if (idx < 4096) {
        int tt = idx - 3072;
        src = p.w2; dst = p.w2t; R = 2048; C = 512;
        bx = tt & 15; by = tt >> 4;
    } else {
        int i = ty * 32 + tx;
#pragma unroll
        for (int j = 0; j < 2; j++) {
            int c = i + j * 256;
            p.b1[c] = p.bq[c]; p.b1[512 + c] = p.bk[c]; p.b1[1024 + c] = p.bv[c];
            p.b2[c] = p.cbk[c]; p.b2[512 + c] = p.cbv[c];
        }
        return;
    }
    int x = bx * 32 + tx, y = by * 32;
#pragma unroll
    for (int i = 0; i < 4; i++)
        t[ty + i * 8][tx] = src[(size_t)(y + ty + i * 8) * C + x];
    __syncthreads();
    int x2 = by * 32 + tx, y2 = bx * 32;
#pragma unroll
    for (int i = 0; i < 4; i++)
        dst[(size_t)(y2 + ty + i * 8) * R + x2] = __float2half(t[tx][ty + i * 8]);
}

// ---------------- LayerNorm (float4 in; half or float out) ---------------------
template<int HOUT>
__global__ __launch_bounds__(128) void ln_kernel(
    const float* __restrict__ x, const float* __restrict__ g,
    const float* __restrict__ b, void* __restrict__ outv)
{
    const int row = blockIdx.x;
    const int tid = threadIdx.x;
    float4 v = *(const float4*)(x + (size_t)row * DM + tid * 4);

    float s  = v.x + v.y + v.z + v.w;
    float s2 = v.x * v.x + v.y * v.y + v.z * v.z + v.w * v.w;
#pragma unroll
    for (int o = 16; o; o >>= 1) {
        s  += __shfl_down_sync(0xffffffffu, s,  o);
        s2 += __shfl_down_sync(0xffffffffu, s2, o);
    }
    __shared__ float rs[4], rs2[4];
    int wid = tid >> 5, lane = tid & 31;
    if (lane == 0) { rs[wid] = s; rs2[wid] = s2; }
    __syncthreads();
    if (tid == 0) {
        float a = rs[0] + rs[1] + rs[2] + rs[3];
        float a2 = rs2[0] + rs2[1] + rs2[2] + rs2[3];
        rs[0] = a; rs2[0] = a2;
    }
    __syncthreads();
    float mean = rs[0] * (1.0f / DM);
    float var  = rs2[0] * (1.0f / DM) - mean * mean;
    float inv  = rsqrtf(var + 1e-5f);

    float4 gg = *(const float4*)(g + tid * 4);
    float4 bb = *(const float4*)(b + tid * 4);
    float o0 = (v.x - mean) * inv * gg.x + bb.x;
    float o1 = (v.y - mean) * inv * gg.y + bb.y;
    float o2 = (v.z - mean) * inv * gg.z + bb.z;
    float o3 = (v.w - mean) * inv * gg.w + bb.w;
    if (HOUT) {
        __half* oh = (__half*)outv;
        __half2 h01 = __floats2half2_rn(o0, o1);
        __half2 h23 = __floats2half2_rn(o2, o3);
        uint2 u; u.x = *(uint32_t*)&h01; u.y = *(uint32_t*)&h23;
        *(uint2*)(oh + (size_t)row * DM + tid * 4) = u;
    } else {
        float* of = (float*)outv;
        *(float4*)(of + (size_t)row * DM + tid * 4) = make_float4(o0, o1, o2, o3);
    }
}

// ---------------- launch -------------------------------------------------------
extern "C" void kernel_launch(void* const* d_in, const int* in_sizes, int n_in,
                              void* d_out, int out_size)
{
    const float* tgt    = (const float*)d_in[0];
    const float* memory = (const float*)d_in[1];

    const size_t OW = (size_t)LAYER * DM * DM;
    const size_t OB = (size_t)LAYER * DM;
    const float* sa_wq = (const float*)d_in[4]  + OW;
    const float* sa_wk = (const float*)d_in[5]  + OW;
    const float* sa_wv = (const float*)d_in[6]  + OW;
    const float* sa_wo = (const float*)d_in[7]  + OW;
    const float* sa_bq = (const float*)d_in[8]  + OB;
    const float* sa_bk = (const float*)d_in[9]  + OB;
    const float* sa_bv = (const float*)d_in[10] + OB;
    const float* sa_bo = (const float*)d_in[11] + OB;
    const float* ca_wq = (const float*)d_in[12] + OW;
    const float* ca_wk = (const float*)d_in[13] + OW;
    const float* ca_wv = (const float*)d_in[14] + OW;
    const float* ca_wo = (const float*)d_in[15] + OW;
    const float* ca_bq = (const float*)d_in[16] + OB;
    const float* ca_bk = (const float*)d_in[17] + OB;
    const float* ca_bv = (const float*)d_in[18] + OB;
    const float* ca_bo = (const float*)d_in[19] + OB;
    const float* ff_w1 = (const float*)d_in[20] + (size_t)LAYER * DM * FFD;
    const float* ff_b1 = (const float*)d_in[21] + (size_t)LAYER * FFD;
    const float* ff_w2 = (const float*)d_in[22] + (size_t)LAYER * FFD * DM;
    const float* ff_b2 = (const float*)d_in[23] + OB;
    const float* ln_g  = (const float*)d_in[24];
    const float* ln_b  = (const float*)d_in[25];

    __half *nh_, *qh_, *qkvh_, *kvh_, *vth_, *ath_, *ffh_, *memh_, *wth_, *w1th_, *w2th_;
    float *x_, *bc1_, *bc2_;
    cudaGetSymbolAddress((void**)&nh_,   g_nh);
    cudaGetSymbolAddress((void**)&qh_,   g_qh);
    cudaGetSymbolAddress((void**)&qkvh_, g_qkvh);
    cudaGetSymbolAddress((void**)&kvh_,  g_kvh);
    cudaGetSymbolAddress((void**)&vth_,  g_vth);
    cudaGetSymbolAddress((void**)&ath_,  g_ath);
    cudaGetSymbolAddress((void**)&ffh_,  g_ffh);
    cudaGetSymbolAddress((void**)&memh_, g_memh);
    cudaGetSymbolAddress((void**)&wth_,  g_wth);
    cudaGetSymbolAddress((void**)&w1th_, g_w1th);
    cudaGetSymbolAddress((void**)&w2th_, g_w2th);
    cudaGetSymbolAddress((void**)&x_,    g_x);
    cudaGetSymbolAddress((void**)&bc1_,  g_bc1);
    cudaGetSymbolAddress((void**)&bc2_,  g_bc2);

    const int S128 = 3 * (128 + 128) * 128;   // 98304
    const int S64  = 3 * (128 + 64)  * 128;   // 73728
    const int SFL  = 65536;
    cudaFuncSetAttribute(mma_gemm<128,0,1,1>, cudaFuncAttributeMaxDynamicSharedMemorySize, S128);
    cudaFuncSetAttribute(mma_gemm<128,1,1,0>, cudaFuncAttributeMaxDynamicSharedMemorySize, S128);
    cudaFuncSetAttribute(mma_gemm<64,0,1,0>,  cudaFuncAttributeMaxDynamicSharedMemorySize, S64);
    cudaFuncSetAttribute(mma_gemm<64,2,0,0>,  cudaFuncAttributeMaxDynamicSharedMemorySize, S64);
    cudaFuncSetAttribute(flash_attn<1>,       cudaFuncAttributeMaxDynamicSharedMemorySize, SFL);
    cudaFuncSetAttribute(flash_attn<0>,       cudaFuncAttributeMaxDynamicSharedMemorySize, SFL);

    const int M = BB * TT;   // 4096

    __half* wqkvT = wth_ + 0 * DM * DM;    // slots 0,1,2
    __half* woT   = wth_ + 3 * DM * DM;
    __half* cqT   = wth_ + 4 * DM * DM;
    __half* ckvT  = wth_ + 5 * DM * DM;    // slots 5,6
    __half* coT   = wth_ + 7 * DM * DM;

    PrepArgs pa;
    pa.s8[0]=sa_wq; pa.d8[0]=wth_ + 0*DM*DM;
    pa.s8[1]=sa_wk; pa.d8[1]=wth_ + 1*DM*DM;
    pa.s8[2]=sa_wv; pa.d8[2]=wth_ + 2*DM*DM;
    pa.s8[3]=sa_wo; pa.d8[3]=woT;
    pa.s8[4]=ca_wq; pa.d8[4]=cqT;
    pa.s8[5]=ca_wk; pa.d8[5]=wth_ + 5*DM*DM;
    pa.s8[6]=ca_wv; pa.d8[6]=wth_ + 6*DM*DM;
    pa.s8[7]=ca_wo; pa.d8[7]=coT;
    pa.w1 = ff_w1; pa.w1t = w1th_;
    pa.w2 = ff_w2; pa.w2t = w2th_;
    pa.bq = sa_bq; pa.bk = sa_bk; pa.bv = sa_bv;
    pa.cbk = ca_bk; pa.cbv = ca_bv;
    pa.b1 = bc1_; pa.b2 = bc2_;
    pa.mem = memory; pa.memh = memh_;
    prep_all<<<4097 + (BB*SS*DM)/2048, dim3(32,8)>>>(pa);

    // ---- self-attention: x = tgt + SA(LN(tgt)) ----
    ln_kernel<1><<<M, 128>>>(tgt, ln_g, ln_b, nh_);
    mma_gemm<128,0,1,1><<<dim3(12,32),256,S128>>>(
        nh_,DM, wqkvT,DM, bc1_,nullptr, qkvh_,3*DM, DM, vth_,1024,M);
    flash_attn<1><<<dim3(4,64),256,SFL>>>(qkvh_,3*DM, qkvh_+DM,3*DM, vth_, ath_, TT);
    mma_gemm<64,2,0,0><<<dim3(8,32),256,S64>>>(
        ath_,DM, woT,DM, sa_bo,tgt, x_,DM, DM, nullptr,0,0);

    // ---- cross-attention: x += CA(LN(x), memory) ----
    ln_kernel<1><<<M, 128>>>(x_, ln_g, ln_b, nh_);
    mma_gemm<64,0,1,0><<<dim3(8,32),256,S64>>>(
        nh_,DM, cqT,DM, ca_bq,nullptr, qh_,DM, DM, nullptr,0,0);
    mma_gemm<128,0,1,1><<<dim3(8,64),256,S128>>>(
        memh_,DM, ckvT,DM, bc2_,nullptr, kvh_,2*DM, DM, vth_,512,BB*SS);
    flash_attn<0><<<dim3(4,64),256,SFL>>>(qh_,DM, kvh_,2*DM, vth_, ath_, SS);
    mma_gemm<64,2,0,0><<<dim3(8,32),256,S64>>>(
        ath_,DM, coT,DM, ca_bo,x_, x_,DM, DM, nullptr,0,0);

    // ---- FFN: x += W2 relu(W1 LN(x)) ----
    ln_kernel<1><<<M, 128>>>(x_, ln_g, ln_b, nh_);
    mma_gemm<128,1,1,0><<<dim3(16,32),256,S128>>>(
        nh_,DM,  w1th_,DM,  ff_b1,nullptr, ffh_,FFD, DM, nullptr,0,0);
    mma_gemm<64,2,0,0><<<dim3(8,32),256,S64>>>(
        ffh_,FFD, w2th_,FFD, ff_b2,x_, x_,DM, FFD, nullptr,0,0);

    // ---- final LN -> out ----
    ln_kernel<0><<<M, 128>>>(x_, ln_g, ln_b, (float*)d_out);
}

// round 11
// speedup vs baseline: 3.0027x; 1.0397x over previous
#include <cuda_runtime.h>
#include <cuda_fp16.h>
#include <cstdint>

// Problem constants
#define NH   8
#define DM   512
#define FFD  2048
#define BB   8
#define TT   512
#define SS   1024
#define LAYER 5

// ---------------- scratch (device globals) ------------------------------------
__device__ __half g_nh  [BB*TT*DM];            // LN output (half)
__device__ __half g_qh  [BB*TT*DM];            // CA Q
__device__ __half g_qkvh[BB*TT*3*DM];          // fused SA QKV (V region redirected)
__device__ __half g_kvh [BB*SS*2*DM];          // fused CA KV  (V region redirected)
__device__ __half g_vth [DM*BB*TT];            // SA transposed V [512][B*T]
__device__ __half g_vth2[DM*BB*SS];            // CA transposed V [512][B*S]
__device__ __half g_ath [BB*TT*DM];            // attention out
__device__ __half g_ffh [BB*TT*FFD];           // FFN hidden
__device__ __half g_memh[BB*SS*DM];            // memory converted to half
__device__ __half g_wth [8*DM*DM];             // 8 transposed weights (half)
__device__ __half g_w1th[FFD*DM];
__device__ __half g_w2th[DM*FFD];
__device__ float  g_x   [BB*TT*DM];            // residual stream (fp32)
__device__ float  g_bc1 [3*DM];
__device__ float  g_bc2 [2*DM];

// ---------------- helpers ------------------------------------------------------
__device__ __forceinline__ uint32_t smem_u32(const void* p) {
    uint32_t a;
    asm("{ .reg .u64 t; cvta.to.shared.u64 t, %1; cvt.u32.u64 %0, t; }" : "=r"(a) : "l"(p));
    return a;
}
#define CP16(dst, src) \
    asm volatile("cp.async.cg.shared.global [%0], [%1], 16;" :: "r"(dst), "l"(src))
#define CP_COMMIT() asm volatile("cp.async.commit_group;" ::: "memory")
#define CP_WAIT1()  asm volatile("cp.async.wait_group 1;" ::: "memory")
#define CP_WAIT0()  asm volatile("cp.async.wait_group 0;" ::: "memory")

#define MMA_F16(c, a, b) \
    asm volatile("mma.sync.aligned.m16n8k16.row.col.f32.f16.f16.f32 " \
        "{%0,%1,%2,%3}, {%4,%5,%6,%7}, {%8,%9}, {%0,%1,%2,%3};" \
        : "+f"((c)[0]), "+f"((c)[1]), "+f"((c)[2]), "+f"((c)[3]) \
        : "r"((a)[0]), "r"((a)[1]), "r"((a)[2]), "r"((a)[3]), "r"((b)[0]), "r"((b)[1]))

#define LDSM4(d0, d1, d2, d3, addr) \
    asm volatile("ldmatrix.sync.aligned.m8n8.x4.shared.b16 {%0,%1,%2,%3}, [%4];" \
        : "=r"(d0), "=r"(d1), "=r"(d2), "=r"(d3) : "r"(addr))

// ============ mma.sync fp16 GEMM, 3-stage pipeline, ldmatrix fragments =========
template<int BN, int EPI, int HOUT, int VT>
__global__ __launch_bounds__(256) void mma_gemm(
    const __half* __restrict__ A, int lda,
    const __half* __restrict__ B, int ldb,
    const float* __restrict__ bias, const float* __restrict__ res,
    void* __restrict__ Cv, int ldc, int K,
    __half* __restrict__ vtp, int vtn0, int vtld)
{
    constexpr int WTM = (BN == 128) ? 64 : 32;
    constexpr int MW  = 128 / WTM;
    constexpr int MF  = WTM / 16;
    constexpr int NF  = 4;
    constexpr int SSZB = (128 + BN) * 128;       // bytes per stage

    const int m0 = blockIdx.y * 128;
    const int n0 = blockIdx.x * BN;

    extern __shared__ char smem[];
    const uint32_t uS = smem_u32(smem);

    const int tid  = threadIdx.x;
    const int lane = tid & 31;
    const int wid  = tid >> 5;
    const int wm   = wid & (MW - 1);
    const int wn   = wid / MW;
    const int laneR = lane >> 2, laneC = lane & 3;

    const int mat = lane >> 3, mrr = lane & 7;
    const int ag_hi = mat >> 1;
    const int bg_lo = mat & 1;
    int aro[MF], arx[MF];
#pragma unroll
    for (int mf = 0; mf < MF; mf++) {
        int r = wm * WTM + mf * 16 + ((mat & 1) << 3) + mrr;
        aro[mf] = r * 128; arx[mf] = r & 7;
    }
    int bro[NF / 2], brx[NF / 2];
#pragma unroll
    for (int p = 0; p < NF / 2; p++) {
        int r = wn * 32 + (2 * p + (mat >> 1)) * 8 + mrr;
        bro[p] = r * 128; brx[p] = r & 7;
    }

    const int nch = K >> 6;

    auto load_chunk = [&](int c) {
        const int st = c % 3;
        const uint32_t ua = uS + st * SSZB;
        const uint32_t ub = ua + 128 * 128;
        const int k0 = c << 6;
#pragma unroll
        for (int i = 0; i < 4; i++) {
            int idx = tid + i * 256; int r = idx >> 3, f = idx & 7;
            CP16(ua + r * 128 + ((f ^ (r & 7)) << 4),
                 A + (size_t)(m0 + r) * lda + k0 + f * 8);
        }
#pragma unroll
        for (int i = 0; i < BN / 32; i++) {
            int idx = tid + i * 256; int r = idx >> 3, f = idx & 7;
            CP16(ub + r * 128 + ((f ^ (r & 7)) << 4),
                 B + (size_t)(n0 + r) * ldb + k0 + f * 8);
        }
        CP_COMMIT();
    };

    float acc[MF][NF][4] = {};

    load_chunk(0);
    load_chunk(1);
    for (int c = 0; c < nch; c++) {
        if (c + 1 < nch) CP_WAIT1(); else CP_WAIT0();
        __syncthreads();
        if (c + 2 < nch) load_chunk(c + 2);
        const int st = c % 3;
        const uint32_t uA_s = uS + st * SSZB;
        const uint32_t uB_s = uA_s + 128 * 128;
#pragma unroll
        for (int ks = 0; ks < 4; ks++) {
            const int gA = 2 * ks + ag_hi;
            const int gB = 2 * ks + bg_lo;
            uint32_t af[MF][4];
#pragma unroll
            for (int mf = 0; mf < MF; mf++)
                LDSM4(af[mf][0], af[mf][1], af[mf][2], af[mf][3],
                      uA_s + aro[mf] + ((gA ^ arx[mf]) << 4));
            uint32_t bf[NF][2];
#pragma unroll
            for (int p = 0; p < NF / 2; p++)
                LDSM4(bf[2*p][0], bf[2*p][1], bf[2*p+1][0], bf[2*p+1][1],
                      uB_s + bro[p] + ((gB ^ brx[p]) << 4));
#pragma unroll
            for (int mf = 0; mf < MF; mf++)
#pragma unroll
                for (int nf = 0; nf < NF; nf++)
                    MMA_F16(acc[mf][nf], af[mf], bf[nf]);
        }
    }

    const bool isv = VT && (n0 >= vtn0);
#pragma unroll
    for (int mf = 0; mf < MF; mf++) {
#pragma unroll
        for (int nf = 0; nf < NF; nf++) {
            int r  = m0 + wm * WTM + mf * 16 + laneR;
            int cc = n0 + wn * 32 + nf * 8 + laneC * 2;
            float v0 = acc[mf][nf][0], v1 = acc[mf][nf][1];
            float v2 = acc[mf][nf][2], v3 = acc[mf][nf][3];
            float2 bb = *(const float2*)(bias + cc);
            v0 += bb.x; v1 += bb.y; v2 += bb.x; v3 += bb.y;
            if (EPI == 1) {
                v0 = fmaxf(v0, 0.f); v1 = fmaxf(v1, 0.f);
                v2 = fmaxf(v2, 0.f); v3 = fmaxf(v3, 0.f);
            }
            if (EPI == 2) {
                float2 r0 = *(const float2*)(res + (size_t)r * ldc + cc);
                float2 r1 = *(const float2*)(res + (size_t)(r + 8) * ldc + cc);
                v0 += r0.x; v1 += r0.y; v2 += r1.x; v3 += r1.y;
            }
            if (isv) {
                __half* c0 = vtp + (size_t)(cc     - vtn0) * vtld;
                __half* c1 = vtp + (size_t)(cc + 1 - vtn0) * vtld;
                c0[r] = __float2half(v0); c1[r] = __float2half(v1);
                c0[r + 8] = __float2half(v2); c1[r + 8] = __float2half(v3);
            } else if (HOUT) {
                __half* Ch = (__half*)Cv;
                *(__half2*)(Ch + (size_t)r * ldc + cc)       = __floats2half2_rn(v0, v1);
                *(__half2*)(Ch + (size_t)(r + 8) * ldc + cc) = __floats2half2_rn(v2, v3);
            } else {
                float* Cf = (float*)Cv;
                *(float2*)(Cf + (size_t)r * ldc + cc)       = make_float2(v0, v1);
                *(float2*)(Cf + (size_t)(r + 8) * ldc + cc) = make_float2(v2, v3);
            }
        }
    }
}

// ============ fused flash attention (fp16, 3-stage KV ring, 2 CTA/SM) ==========
// smem: Q 16K | K 3x8K | V 3x8K | P 8x2K  = 80 KB
template<int CAUSAL>
__global__ __launch_bounds__(256, 2) void flash_attn(
    const __half* __restrict__ Q, int ldq,
    const __half* __restrict__ Kg, int ldk,
    const __half* __restrict__ Vt, __half* __restrict__ O, int Slen)
{
    extern __shared__ char sm[];
    const uint32_t uQ = smem_u32(sm);
    const uint32_t uK = uQ + 16384;
    const uint32_t uV = uK + 24576;
    const uint32_t uP = uV + 24576;

    const int mt = blockIdx.x, bh = blockIdx.y;
    const int b = bh >> 3, h = bh & 7;
    const int m0 = mt * 128;
    const int tid = threadIdx.x, lane = tid & 31, wid = tid >> 5;
    const int laneR = lane >> 2, laneC = lane & 3;

    const __half* Qp = Q + ((size_t)b * TT + m0) * ldq + h * 64;
    const __half* Kp = Kg + (size_t)b * Slen * ldk + h * 64;
    const __half* Vp = Vt + (size_t)(h * 64) * (BB * Slen) + (size_t)b * Slen;
    __half* Op = O + ((size_t)b * TT + m0) * DM + h * 64;

    const int wr0 = wid * 16;
    const uint32_t uPw = uP + wid * 2048;
    char* sPw = sm + 65536 + wid * 2048;

    const int mat = lane >> 3, mrr = lane & 7;
    const int ag_hi = mat >> 1;
    const int bg_lo = mat & 1;
    const int qrow = wr0 + ((mat & 1) << 3) + mrr;
    const int qro = qrow * 128, qrx = qrow & 7;
    const int prow = ((mat & 1) << 3) + mrr;
    const int pro = prow * 128, prx = prow & 7;
    int bro[4], brx[4];
#pragma unroll
    for (int p = 0; p < 4; p++) {
        int r = p * 16 + ((mat >> 1) << 3) + mrr;
        bro[p] = r * 128; brx[p] = r & 7;
    }

    // Q tile (joins first commit group)
#pragma unroll
    for (int i = 0; i < 4; i++) {
        int idx = tid + i * 256;
        int r = idx >> 3, f = idx & 7;
        CP16(uQ + r * 128 + ((f ^ (r & 7)) << 4), Qp + (size_t)r * ldq + f * 8);
    }

    auto load_kv = [&](int c) {
        const int st = c % 3;
        const int s0 = c * 64;
#pragma unroll
        for (int i = 0; i < 2; i++) {
            int idx = tid + i * 256;
            int r = idx >> 3, f = idx & 7;
            CP16(uK + st * 8192 + r * 128 + ((f ^ (r & 7)) << 4),
                 Kp + (size_t)(s0 + r) * ldk + f * 8);
        }
#pragma unroll
        for (int i = 0; i < 2; i++) {
            int idx = tid + i * 256;
            int r = idx >> 3, f = idx & 7;
            CP16(uV + st * 8192 + r * 128 + ((f ^ (r & 7)) << 4),
                 Vp + (size_t)r * (BB * Slen) + s0 + f * 8);
        }
        CP_COMMIT();
    };

    const int nch = CAUSAL ? (m0 + 128) / 64 : Slen / 64;
    float mr0 = -1e30f, mr1 = -1e30f, l0 = 0.f, l1 = 0.f;
    float oacc[8][4] = {};

    load_kv(0);
    load_kv(1);
    for (int c = 0; c < nch; c++) {
        if (c + 1 < nch) CP_WAIT1(); else CP_WAIT0();
        __syncthreads();
        if (c + 2 < nch) load_kv(c + 2);
        const int s0 = c * 64;
        const bool active = !CAUSAL || (s0 <= m0 + wr0 + 15);
        if (active) {
            const uint32_t uKb = uK + (c % 3) * 8192;
            const uint32_t uVb = uV + (c % 3) * 8192;

            // ---- S = Q @ K^T ----
            float sacc[8][4] = {};
#pragma unroll
            for (int ks = 0; ks < 4; ks++) {
                const int gA = 2 * ks + ag_hi;
                const int gB = 2 * ks + bg_lo;
                uint32_t af[4];
                LDSM4(af[0], af[1], af[2], af[3], uQ + qro + ((gA ^ qrx) << 4));
                uint32_t bf[8][2];
#pragma unroll
                for (int p = 0; p < 4; p++)
                    LDSM4(bf[2*p][0], bf[2*p][1], bf[2*p+1][0], bf[2*p+1][1],
                          uKb + bro[p] + ((gB ^ brx[p]) << 4));
#pragma unroll
                for (int nf = 0; nf < 8; nf++)
                    MMA_F16(sacc[nf], af, bf[nf]);
            }

            // ---- scale + mask + online softmax ----
            const float SCL = 0.125f;
            const int t0g = m0 + wr0 + laneR;
            float rmax0 = -1e30f, rmax1 = -1e30f;
#pragma unroll
            for (int nf = 0; nf < 8; nf++) {
                int sg = s0 + nf * 8 + 2 * laneC;
                float v0 = sacc[nf][0] * SCL, v1 = sacc[nf][1] * SCL;
                float v2 = sacc[nf][2] * SCL, v3 = sacc[nf][3] * SCL;
                if (CAUSAL) {
                    if (sg     > t0g)     v0 = -1e30f;
                    if (sg + 1 > t0g)     v1 = -1e30f;
                    if (sg     > t0g + 8) v2 = -1e30f;
                    if (sg + 1 > t0g + 8) v3 = -1e30f;
                }
                sacc[nf][0] = v0; sacc[nf][1] = v1;
                sacc[nf][2] = v2; sacc[nf][3] = v3;
                rmax0 = fmaxf(rmax0, fmaxf(v0, v1));
                rmax1 = fmaxf(rmax1, fmaxf(v2, v3));
            }
            rmax0 = fmaxf(rmax0, __shfl_xor_sync(0xffffffffu, rmax0, 1));
            rmax0 = fmaxf(rmax0, __shfl_xor_sync(0xffffffffu, rmax0, 2));
            rmax1 = fmaxf(rmax1, __shfl_xor_sync(0xffffffffu, rmax1, 1));
            rmax1 = fmaxf(rmax1, __shfl_xor_sync(0xffffffffu, rmax1, 2));
            float mn0 = fmaxf(mr0, rmax0), mn1 = fmaxf(mr1, rmax1);
            float al0 = __expf(mr0 - mn0), al1 = __expf(mr1 - mn1);
            mr0 = mn0; mr1 = mn1;

            float rs0 = 0.f, rs1 = 0.f;
#pragma unroll
            for (int nf = 0; nf < 8; nf++) {
                float e0 = __expf(sacc[nf][0] - mn0);
                float e1 = __expf(sacc[nf][1] - mn0);
                float e2 = __expf(sacc[nf][2] - mn1);
                float e3 = __expf(sacc[nf][3] - mn1);
                rs0 += e0 + e1; rs1 += e2 + e3;
                int off = ((nf ^ (laneR & 7)) << 4) + laneC * 4;
                *(__half2*)(sPw + laneR * 128 + off)       = __floats2half2_rn(e0, e1);
                *(__half2*)(sPw + (laneR + 8) * 128 + off) = __floats2half2_rn(e2, e3);
            }
            rs0 += __shfl_xor_sync(0xffffffffu, rs0, 1);
            rs0 += __shfl_xor_sync(0xffffffffu, rs0, 2);
            rs1 += __shfl_xor_sync(0xffffffffu, rs1, 1);
            rs1 += __shfl_xor_sync(0xffffffffu, rs1, 2);
            l0 = l0 * al0 + rs0;
            l1 = l1 * al1 + rs1;
#pragma unroll
            for (int nf = 0; nf < 8; nf++) {
                oacc[nf][0] *= al0; oacc[nf][1] *= al0;
                oacc[nf][2] *= al1; oacc[nf][3] *= al1;
            }
            __syncwarp();

            // ---- O += P @ V ----
#pragma unroll
            for (int ks = 0; ks < 4; ks++) {
                const int gA = 2 * ks + ag_hi;
                const int gB = 2 * ks + bg_lo;
                uint32_t af[4];
                LDSM4(af[0], af[1], af[2], af[3], uPw + pro + ((gA ^ prx) << 4));
#pragma unroll
                for (int p = 0; p < 4; p++) {
                    uint32_t bf0[2], bf1[2];
                    LDSM4(bf0[0], bf0[1], bf1[0], bf1[1],
                          uVb + bro[p] + ((gB ^ brx[p]) << 4));
                    MMA_F16(oacc[2*p],     af, bf0);
                    MMA_F16(oacc[2*p + 1], af, bf1);
                }
            }
        }
    }

    const float inv0 = 1.f / l0, inv1 = 1.f / l1;
#pragma unroll
    for (int nf = 0; nf < 8; nf++) {
        int cc = nf * 8 + 2 * laneC;
        int r = wr0 + laneR;
        *(__half2*)(Op + (size_t)r * DM + cc) =
            __floats2half2_rn(oacc[nf][0] * inv0, oacc[nf][1] * inv0);
        *(__half2*)(Op + (size_t)(r + 8) * DM + cc) =
            __floats2half2_rn(oacc[nf][2] * inv1, oacc[nf][3] * inv1);
    }
}

// ---------------- prep: transposes->half + bias concats + memory->half ---------
struct PrepArgs {
    const float* s8[8]; __half* d8[8];
    const float* w1; __half* w1t;
    const float* w2; __half* w2t;
    const float* bq; const float* bk; const float* bv;
    const float* cbk; const float* cbv;
    float* b1; float* b2;
    const float* mem; __half* memh;
};
__global__ __launch_bounds__(256) void prep_all(PrepArgs p)
{
    __shared__ float t[32][33];
    const int idx = blockIdx.x;
    const int tx = threadIdx.x, ty = threadIdx.y;

    if (idx >= 4097) {   // memory fp32 -> half
        int j = idx - 4097;
        int base = j * 2048 + (ty * 32 + tx) * 8;
        float4 a = *(const float4*)(p.mem + base);
        float4 b = *(const float4*)(p.mem + base + 4);
        __half2 h0 = __floats2half2_rn(a.x, a.y);
        __half2 h1 = __floats2half2_rn(a.z, a.w);
        __half2 h2 = __floats2half2_rn(b.x, b.y);
        __half2 h3 = __floats2half2_rn(b.z, b.w);
        uint4 o;
        o.x = *(uint32_t*)&h0; o.y = *(uint32_t*)&h1;
        o.z = *(uint32_t*)&h2; o.w = *(uint32_t*)&h3;
        *(uint4*)(p.memh + base) = o;
        return;
    }

    const float* src; __half* dst; int R, C, bx, by;
    if (idx < 2048) {
        int m = idx >> 8, tt = idx & 255;
        src = p.s8[m]; dst = p.d8[m]; R = 512; C = 512;
        bx = tt & 15; by = tt >> 4;
    } else if (idx < 3072) {
        int tt = idx - 2048;
        src = p.w1; dst = p.w1t; R = 512; C = 2048;
        bx = tt & 63; by = tt >> 6;
    } else if (idx < 4096) {
        int tt = idx - 3072;
        src = p.w2; dst = p.w2t; R = 2048; C = 512;
        bx = tt & 15; by = tt >> 4;
    } else {
        int i = ty * 32 + tx;
#pragma unroll
        for (int j = 0; j < 2; j++) {
            int c = i + j * 256;
            p.b1[c] = p.bq[c]; p.b1[512 + c] = p.bk[c]; p.b1[1024 + c] = p.bv[c];
            p.b2[c] = p.cbk[c]; p.b2[512 + c] = p.cbv[c];
        }
        return;
    }
    int x = bx * 32 + tx, y = by * 32;
#pragma unroll
    for (int i = 0; i < 4; i++)
        t[ty + i * 8][tx] = src[(size_t)(y + ty + i * 8) * C + x];
    __syncthreads();
    int x2 = by * 32 + tx, y2 = bx * 32;
#pragma unroll
    for (int i = 0; i < 4; i++)
        dst[(size_t)(y2 + ty + i * 8) * R + x2] = __float2half(t[tx][ty + i * 8]);
}

// ---------------- LayerNorm (float4 in; half or float out) ---------------------
template<int HOUT>
__global__ __launch_bounds__(128) void ln_kernel(
    const float* __restrict__ x, const float* __restrict__ g,
    const float* __restrict__ b, void* __restrict__ outv)
{
    const int row = blockIdx.x;
    const int tid = threadIdx.x;
    float4 v = *(const float4*)(x + (size_t)row * DM + tid * 4);

    float s  = v.x + v.y + v.z + v.w;
    float s2 = v.x * v.x + v.y * v.y + v.z * v.z + v.w * v.w;
#pragma unroll
    for (int o = 16; o; o >>= 1) {
        s  += __shfl_down_sync(0xffffffffu, s,  o);
        s2 += __shfl_down_sync(0xffffffffu, s2, o);
    }
    __shared__ float rs[4], rs2[4];
    int wid = tid >> 5, lane = tid & 31;
    if (lane == 0) { rs[wid] = s; rs2[wid] = s2; }
    __syncthreads();
    if (tid == 0) {
        float a = rs[0] + rs[1] + rs[2] + rs[3];
        float a2 = rs2[0] + rs2[1] + rs2[2] + rs2[3];
        rs[0] = a; rs2[0] = a2;
    }
    __syncthreads();
    float mean = rs[0] * (1.0f / DM);
    float var  = rs2[0] * (1.0f / DM) - mean * mean;
    float inv  = rsqrtf(var + 1e-5f);

    float4 gg = *(const float4*)(g + tid * 4);
    float4 bb = *(const float4*)(b + tid * 4);
    float o0 = (v.x - mean) * inv * gg.x + bb.x;
    float o1 = (v.y - mean) * inv * gg.y + bb.y;
    float o2 = (v.z - mean) * inv * gg.z + bb.z;
    float o3 = (v.w - mean) * inv * gg.w + bb.w;
    if (HOUT) {
        __half* oh = (__half*)outv;
        __half2 h01 = __floats2half2_rn(o0, o1);
        __half2 h23 = __floats2half2_rn(o2, o3);
        uint2 u; u.x = *(uint32_t*)&h01; u.y = *(uint32_t*)&h23;
        *(uint2*)(oh + (size_t)row * DM + tid * 4) = u;
    } else {
        float* of = (float*)outv;
        *(float4*)(of + (size_t)row * DM + tid * 4) = make_float4(o0, o1, o2, o3);
    }
}

// ---------------- launch -------------------------------------------------------
extern "C" void kernel_launch(void* const* d_in, const int* in_sizes, int n_in,
                              void* d_out, int out_size)
{
    const float* tgt    = (const float*)d_in[0];
    const float* memory = (const float*)d_in[1];

    const size_t OW = (size_t)LAYER * DM * DM;
    const size_t OB = (size_t)LAYER * DM;
    const float* sa_wq = (const float*)d_in[4]  + OW;
    const float* sa_wk = (const float*)d_in[5]  + OW;
    const float* sa_wv = (const float*)d_in[6]  + OW;
    const float* sa_wo = (const float*)d_in[7]  + OW;
    const float* sa_bq = (const float*)d_in[8]  + OB;
    const float* sa_bk = (const float*)d_in[9]  + OB;
    const float* sa_bv = (const float*)d_in[10] + OB;
    const float* sa_bo = (const float*)d_in[11] + OB;
    const float* ca_wq = (const float*)d_in[12] + OW;
    const float* ca_wk = (const float*)d_in[13] + OW;
    const float* ca_wv = (const float*)d_in[14] + OW;
    const float* ca_wo = (const float*)d_in[15] + OW;
    const float* ca_bq = (const float*)d_in[16] + OB;
    const float* ca_bk = (const float*)d_in[17] + OB;
    const float* ca_bv = (const float*)d_in[18] + OB;
    const float* ca_bo = (const float*)d_in[19] + OB;
    const float* ff_w1 = (const float*)d_in[20] + (size_t)LAYER * DM * FFD;
    const float* ff_b1 = (const float*)d_in[21] + (size_t)LAYER * FFD;
    const float* ff_w2 = (const float*)d_in[22] + (size_t)LAYER * FFD * DM;
    const float* ff_b2 = (const float*)d_in[23] + OB;
    const float* ln_g  = (const float*)d_in[24];
    const float* ln_b  = (const float*)d_in[25];

    __half *nh_, *qh_, *qkvh_, *kvh_, *vth_, *vth2_, *ath_, *ffh_, *memh_, *wth_, *w1th_, *w2th_;
    float *x_, *bc1_, *bc2_;
    cudaGetSymbolAddress((void**)&nh_,   g_nh);
    cudaGetSymbolAddress((void**)&qh_,   g_qh);
    cudaGetSymbolAddress((void**)&qkvh_, g_qkvh);
    cudaGetSymbolAddress((void**)&kvh_,  g_kvh);
    cudaGetSymbolAddress((void**)&vth_,  g_vth);
    cudaGetSymbolAddress((void**)&vth2_, g_vth2);
    cudaGetSymbolAddress((void**)&ath_,  g_ath);
    cudaGetSymbolAddress((void**)&ffh_,  g_ffh);
    cudaGetSymbolAddress((void**)&memh_, g_memh);
    cudaGetSymbolAddress((void**)&wth_,  g_wth);
    cudaGetSymbolAddress((void**)&w1th_, g_w1th);
    cudaGetSymbolAddress((void**)&w2th_, g_w2th);
    cudaGetSymbolAddress((void**)&x_,    g_x);
    cudaGetSymbolAddress((void**)&bc1_,  g_bc1);
    cudaGetSymbolAddress((void**)&bc2_,  g_bc2);

    // persistent aux stream + events for graph fork/join (created once)
    static cudaStream_t s_aux = nullptr;
    static cudaEvent_t evF = nullptr, evP = nullptr, evKV = nullptr;
    if (!s_aux) {
        cudaStreamCreateWithFlags(&s_aux, cudaStreamNonBlocking);
        cudaEventCreateWithFlags(&evF,  cudaEventDisableTiming);
        cudaEventCreateWithFlags(&evP,  cudaEventDisableTiming);
        cudaEventCreateWithFlags(&evKV, cudaEventDisableTiming);
    }

    const int S128 = 3 * (128 + 128) * 128;   // 98304
    const int S64  = 3 * (128 + 64)  * 128;   // 73728
    const int SFL  = 81920;
    cudaFuncSetAttribute(mma_gemm<128,0,1,1>, cudaFuncAttributeMaxDynamicSharedMemorySize, S128);
    cudaFuncSetAttribute(mma_gemm<128,1,1,0>, cudaFuncAttributeMaxDynamicSharedMemorySize, S128);
    cudaFuncSetAttribute(mma_gemm<64,0,1,0>,  cudaFuncAttributeMaxDynamicSharedMemorySize, S64);
    cudaFuncSetAttribute(mma_gemm<64,2,0,0>,  cudaFuncAttributeMaxDynamicSharedMemorySize, S64);
    cudaFuncSetAttribute(flash_attn<1>,       cudaFuncAttributeMaxDynamicSharedMemorySize, SFL);
    cudaFuncSetAttribute(flash_attn<0>,       cudaFuncAttributeMaxDynamicSharedMemorySize, SFL);

    const int M = BB * TT;   // 4096

    __half* wqkvT = wth_ + 0 * DM * DM;    // slots 0,1,2
    __half* woT   = wth_ + 3 * DM * DM;
    __half* cqT   = wth_ + 4 * DM * DM;
    __half* ckvT  = wth_ + 5 * DM * DM;    // slots 5,6
    __half* coT   = wth_ + 7 * DM * DM;

    PrepArgs pa;
    pa.s8[0]=sa_wq; pa.d8[0]=wth_ + 0*DM*DM;
    pa.s8[1]=sa_wk; pa.d8[1]=wth_ + 1*DM*DM;
    pa.s8[2]=sa_wv; pa.d8[2]=wth_ + 2*DM*DM;
    pa.s8[3]=sa_wo; pa.d8[3]=woT;
    pa.s8[4]=ca_wq; pa.d8[4]=cqT;
    pa.s8[5]=ca_wk; pa.d8[5]=wth_ + 5*DM*DM;
    pa.s8[6]=ca_wv; pa.d8[6]=wth_ + 6*DM*DM;
    pa.s8[7]=ca_wo; pa.d8[7]=coT;
    pa.w1 = ff_w1; pa.w1t = w1th_;
    pa.w2 = ff_w2; pa.w2t = w2th_;
    pa.bq = sa_bq; pa.bk = sa_bk; pa.bv = sa_bv;
    pa.cbk = ca_bk; pa.cbv = ca_bv;
    pa.b1 = bc1_; pa.b2 = bc2_;
    pa.mem = memory; pa.memh = memh_;

    // ---- fork: prep + CA-KV projection on aux stream ----
    cudaEventRecord(evF, 0);
    cudaStreamWaitEvent(s_aux, evF, 0);
    prep_all<<<4097 + (BB*SS*DM)/2048, dim3(32,8), 0, s_aux>>>(pa);
    cudaEventRecord(evP, s_aux);      // weights/biases ready
    mma_gemm<128,0,1,1><<<dim3(8,64),256,S128,s_aux>>>(
        memh_,DM, ckvT,DM, bc2_,nullptr, kvh_,2*DM, DM, vth2_,512,BB*SS);
    cudaEventRecord(evKV, s_aux);     // CA K/V ready

    // ---- main: self-attention: x = tgt + SA(LN(tgt)) ----
    ln_kernel<1><<<M, 128>>>(tgt, ln_g, ln_b, nh_);
    cudaStreamWaitEvent(0, evP, 0);   // need weights for QKV
    mma_gemm<128,0,1,1><<<dim3(12,32),256,S128>>>(
        nh_,DM, wqkvT,DM, bc1_,nullptr, qkvh_,3*DM, DM, vth_,1024,M);
    flash_attn<1><<<dim3(4,64),256,SFL>>>(qkvh_,3*DM, qkvh_+DM,3*DM, vth_, ath_, TT);
    mma_gemm<64,2,0,0><<<dim3(8,32),256,S64>>>(
        ath_,DM, woT,DM, sa_bo,tgt, x_,DM, DM, nullptr,0,0);

    // ---- cross-attention: x += CA(LN(x), memory) ----
    ln_kernel<1><<<M, 128>>>(x_, ln_g, ln_b, nh_);
    mma_gemm<64,0,1,0><<<dim3(8,32),256,S64>>>(
        nh_,DM, cqT,DM, ca_bq,nullptr, qh_,DM, DM, nullptr,0,0);
    cudaStreamWaitEvent(0, evKV, 0);  // join CA K/V branch
    flash_attn<0><<<dim3(4,64),256,SFL>>>(qh_,DM, kvh_,2*DM, vth2_, ath_, SS);
    mma_gemm<64,2,0,0><<<dim3(8,32),256,S64>>>(
        ath_,DM, coT,DM, ca_bo,x_, x_,DM, DM, nullptr,0,0);

    // ---- FFN: x += W2 relu(W1 LN(x)) ----
    ln_kernel<1><<<M, 128>>>(x_, ln_g, ln_b, nh_);
    mma_gemm<128,1,1,0><<<dim3(16,32),256,S128>>>(
        nh_,DM,  w1th_,DM,  ff_b1,nullptr, ffh_,FFD, DM, nullptr,0,0);
    mma_gemm<64,2,0,0><<<dim3(8,32),256,S64>>>(
        ffh_,FFD, w2th_,FFD, ff_b2,x_, x_,DM, FFD, nullptr,0,0);

    // ---- final LN -> out ----
    ln_kernel<0><<<M, 128>>>(x_, ln_g, ln_b, (float*)d_out);
}

// round 12
// speedup vs baseline: 3.1099x; 1.0357x over previous
#include <cuda_runtime.h>
#include <cuda_fp16.h>
#include <cstdint>

// Problem constants
#define NH   8
#define DM   512
#define FFD  2048
#define BB   8
#define TT   512
#define SS   1024
#define LAYER 5

// ---------------- scratch (device globals) ------------------------------------
__device__ __half g_nh  [BB*TT*DM];            // LN output (half)
__device__ __half g_qh  [BB*TT*DM];            // CA Q
__device__ __half g_qkvh[BB*TT*3*DM];          // fused SA QKV (V region redirected)
__device__ __half g_kvh [BB*SS*2*DM];          // fused CA KV  (V region redirected)
__device__ __half g_vth [DM*BB*TT];            // SA transposed V [512][B*T]
__device__ __half g_vth2[DM*BB*SS];            // CA transposed V [512][B*S]
__device__ __half g_ath [BB*TT*DM];            // attention out
__device__ __half g_ffh [BB*TT*FFD];           // FFN hidden
__device__ __half g_memh[BB*SS*DM];            // memory converted to half
__device__ __half g_wth [8*DM*DM];             // 8 transposed weights (half)
__device__ __half g_w1th[FFD*DM];
__device__ __half g_w2th[DM*FFD];
__device__ float  g_x   [BB*TT*DM];            // residual stream (fp32)
__device__ float  g_bc1 [3*DM];
__device__ float  g_bc2 [2*DM];

// ---------------- helpers ------------------------------------------------------
__device__ __forceinline__ uint32_t smem_u32(const void* p) {
    uint32_t a;
    asm("{ .reg .u64 t; cvta.to.shared.u64 t, %1; cvt.u32.u64 %0, t; }" : "=r"(a) : "l"(p));
    return a;
}
__device__ __forceinline__ uint32_t h2u(__half2 h) { return *(uint32_t*)&h; }

#define CP16(dst, src) \
    asm volatile("cp.async.cg.shared.global [%0], [%1], 16;" :: "r"(dst), "l"(src))
#define CP_COMMIT() asm volatile("cp.async.commit_group;" ::: "memory")
#define CP_WAIT1()  asm volatile("cp.async.wait_group 1;" ::: "memory")
#define CP_WAIT0()  asm volatile("cp.async.wait_group 0;" ::: "memory")

#define MMA_F16(c, a, b) \
    asm volatile("mma.sync.aligned.m16n8k16.row.col.f32.f16.f16.f32 " \
        "{%0,%1,%2,%3}, {%4,%5,%6,%7}, {%8,%9}, {%0,%1,%2,%3};" \
        : "+f"((c)[0]), "+f"((c)[1]), "+f"((c)[2]), "+f"((c)[3]) \
        : "r"((a)[0]), "r"((a)[1]), "r"((a)[2]), "r"((a)[3]), "r"((b)[0]), "r"((b)[1]))

#define LDSM4(d0, d1, d2, d3, addr) \
    asm volatile("ldmatrix.sync.aligned.m8n8.x4.shared.b16 {%0,%1,%2,%3}, [%4];" \
        : "=r"(d0), "=r"(d1), "=r"(d2), "=r"(d3) : "r"(addr))

// ============ mma.sync fp16 GEMM, 3-stage pipeline, ldmatrix fragments =========
template<int BN, int EPI, int HOUT, int VT>
__global__ __launch_bounds__(256) void mma_gemm(
    const __half* __restrict__ A, int lda,
    const __half* __restrict__ B, int ldb,
    const float* __restrict__ bias, const float* __restrict__ res,
    void* __restrict__ Cv, int ldc, int K,
    __half* __restrict__ vtp, int vtn0, int vtld)
{
    constexpr int WTM = (BN == 128) ? 64 : 32;
    constexpr int MW  = 128 / WTM;
    constexpr int MF  = WTM / 16;
    constexpr int NF  = 4;
    constexpr int SSZB = (128 + BN) * 128;       // bytes per stage

    const int m0 = blockIdx.y * 128;
    const int n0 = blockIdx.x * BN;

    extern __shared__ char smem[];
    const uint32_t uS = smem_u32(smem);

    const int tid  = threadIdx.x;
    const int lane = tid & 31;
    const int wid  = tid >> 5;
    const int wm   = wid & (MW - 1);
    const int wn   = wid / MW;
    const int laneR = lane >> 2, laneC = lane & 3;

    const int mat = lane >> 3, mrr = lane & 7;
    const int ag_hi = mat >> 1;
    const int bg_lo = mat & 1;
    int aro[MF], arx[MF];
#pragma unroll
    for (int mf = 0; mf < MF; mf++) {
        int r = wm * WTM + mf * 16 + ((mat & 1) << 3) + mrr;
        aro[mf] = r * 128; arx[mf] = r & 7;
    }
    int bro[NF / 2], brx[NF / 2];
#pragma unroll
    for (int p = 0; p < NF / 2; p++) {
        int r = wn * 32 + (2 * p + (mat >> 1)) * 8 + mrr;
        bro[p] = r * 128; brx[p] = r & 7;
    }

    const int nch = K >> 6;

    auto load_chunk = [&](int c) {
        const int st = c % 3;
        const uint32_t ua = uS + st * SSZB;
        const uint32_t ub = ua + 128 * 128;
        const int k0 = c << 6;
#pragma unroll
        for (int i = 0; i < 4; i++) {
            int idx = tid + i * 256; int r = idx >> 3, f = idx & 7;
            CP16(ua + r * 128 + ((f ^ (r & 7)) << 4),
                 A + (size_t)(m0 + r) * lda + k0 + f * 8);
        }
#pragma unroll
        for (int i = 0; i < BN / 32; i++) {
            int idx = tid + i * 256; int r = idx >> 3, f = idx & 7;
            CP16(ub + r * 128 + ((f ^ (r & 7)) << 4),
                 B + (size_t)(n0 + r) * ldb + k0 + f * 8);
        }
        CP_COMMIT();
    };

    float acc[MF][NF][4] = {};

    load_chunk(0);
    load_chunk(1);
    for (int c = 0; c < nch; c++) {
        if (c + 1 < nch) CP_WAIT1(); else CP_WAIT0();
        __syncthreads();
        if (c + 2 < nch) load_chunk(c + 2);
        const int st = c % 3;
        const uint32_t uA_s = uS + st * SSZB;
        const uint32_t uB_s = uA_s + 128 * 128;
#pragma unroll
        for (int ks = 0; ks < 4; ks++) {
            const int gA = 2 * ks + ag_hi;
            const int gB = 2 * ks + bg_lo;
            uint32_t af[MF][4];
#pragma unroll
            for (int mf = 0; mf < MF; mf++)
                LDSM4(af[mf][0], af[mf][1], af[mf][2], af[mf][3],
                      uA_s + aro[mf] + ((gA ^ arx[mf]) << 4));
            uint32_t bf[NF][2];
#pragma unroll
            for (int p = 0; p < NF / 2; p++)
                LDSM4(bf[2*p][0], bf[2*p][1], bf[2*p+1][0], bf[2*p+1][1],
                      uB_s + bro[p] + ((gB ^ brx[p]) << 4));
#pragma unroll
            for (int mf = 0; mf < MF; mf++)
#pragma unroll
                for (int nf = 0; nf < NF; nf++)
                    MMA_F16(acc[mf][nf], af[mf], bf[nf]);
        }
    }

    const bool isv = VT && (n0 >= vtn0);
#pragma unroll
    for (int mf = 0; mf < MF; mf++) {
#pragma unroll
        for (int nf = 0; nf < NF; nf++) {
            int r  = m0 + wm * WTM + mf * 16 + laneR;
            int cc = n0 + wn * 32 + nf * 8 + laneC * 2;
            float v0 = acc[mf][nf][0], v1 = acc[mf][nf][1];
            float v2 = acc[mf][nf][2], v3 = acc[mf][nf][3];
            float2 bb = *(const float2*)(bias + cc);
            v0 += bb.x; v1 += bb.y; v2 += bb.x; v3 += bb.y;
            if (EPI == 1) {
                v0 = fmaxf(v0, 0.f); v1 = fmaxf(v1, 0.f);
                v2 = fmaxf(v2, 0.f); v3 = fmaxf(v3, 0.f);
            }
            if (EPI == 2) {
                float2 r0 = *(const float2*)(res + (size_t)r * ldc + cc);
                float2 r1 = *(const float2*)(res + (size_t)(r + 8) * ldc + cc);
                v0 += r0.x; v1 += r0.y; v2 += r1.x; v3 += r1.y;
            }
            if (isv) {
                __half* c0 = vtp + (size_t)(cc     - vtn0) * vtld;
                __half* c1 = vtp + (size_t)(cc + 1 - vtn0) * vtld;
                c0[r] = __float2half(v0); c1[r] = __float2half(v1);
                c0[r + 8] = __float2half(v2); c1[r + 8] = __float2half(v3);
            } else if (HOUT) {
                __half* Ch = (__half*)Cv;
                *(__half2*)(Ch + (size_t)r * ldc + cc)       = __floats2half2_rn(v0, v1);
                *(__half2*)(Ch + (size_t)(r + 8) * ldc + cc) = __floats2half2_rn(v2, v3);
            } else {
                float* Cf = (float*)Cv;
                *(float2*)(Cf + (size_t)r * ldc + cc)       = make_float2(v0, v1);
                *(float2*)(Cf + (size_t)(r + 8) * ldc + cc) = make_float2(v2, v3);
            }
        }
    }
}

// ============ fused flash attention (fp16, 3-stage KV ring, P in registers) ====
// smem: Q 16K | K 3x8K | V 3x8K  = 64 KB. 2 CTA/SM.
// Key identity: m16n8k16 C-fragment layout == A-fragment layout (per k-group),
// so exp'd S accumulators packed to half2 are directly the P operand for P@V.
template<int CAUSAL>
__global__ __launch_bounds__(256, 2) void flash_attn(
    const __half* __restrict__ Q, int ldq,
    const __half* __restrict__ Kg, int ldk,
    const __half* __restrict__ Vt, __half* __restrict__ O, int Slen)
{
    extern __shared__ char sm[];
    const uint32_t uQ = smem_u32(sm);
    const uint32_t uK = uQ + 16384;
    const uint32_t uV = uK + 24576;

    const int mt = blockIdx.x, bh = blockIdx.y;
    const int b = bh >> 3, h = bh & 7;
    const int m0 = mt * 128;
    const int tid = threadIdx.x, lane = tid & 31, wid = tid >> 5;
    const int laneR = lane >> 2, laneC = lane & 3;

    const __half* Qp = Q + ((size_t)b * TT + m0) * ldq + h * 64;
    const __half* Kp = Kg + (size_t)b * Slen * ldk + h * 64;
    const __half* Vp = Vt + (size_t)(h * 64) * (BB * Slen) + (size_t)b * Slen;
    __half* Op = O + ((size_t)b * TT + m0) * DM + h * 64;

    const int wr0 = wid * 16;

    const int mat = lane >> 3, mrr = lane & 7;
    const int ag_hi = mat >> 1;
    const int bg_lo = mat & 1;
    const int qrow = wr0 + ((mat & 1) << 3) + mrr;
    const int qro = qrow * 128, qrx = qrow & 7;
    int bro[4], brx[4];
#pragma unroll
    for (int p = 0; p < 4; p++) {
        int r = p * 16 + ((mat >> 1) << 3) + mrr;
        bro[p] = r * 128; brx[p] = r & 7;
    }

    // Q tile (joins first commit group)
#pragma unroll
    for (int i = 0; i < 4; i++) {
        int idx = tid + i * 256;
        int r = idx >> 3, f = idx & 7;
        CP16(uQ + r * 128 + ((f ^ (r & 7)) << 4), Qp + (size_t)r * ldq + f * 8);
    }

    auto load_kv = [&](int c) {
        const int st = c % 3;
        const int s0 = c * 64;
#pragma unroll
        for (int i = 0; i < 2; i++) {
            int idx = tid + i * 256;
            int r = idx >> 3, f = idx & 7;
            CP16(uK + st * 8192 + r * 128 + ((f ^ (r & 7)) << 4),
                 Kp + (size_t)(s0 + r) * ldk + f * 8);
        }
#pragma unroll
        for (int i = 0; i < 2; i++) {
            int idx = tid + i * 256;
            int r = idx >> 3, f = idx & 7;
            CP16(uV + st * 8192 + r * 128 + ((f ^ (r & 7)) << 4),
                 Vp + (size_t)r * (BB * Slen) + s0 + f * 8);
        }
        CP_COMMIT();
    };

    const int nch = CAUSAL ? (m0 + 128) / 64 : Slen / 64;
    float mr0 = -1e30f, mr1 = -1e30f, l0 = 0.f, l1 = 0.f;
    float oacc[8][4] = {};

    load_kv(0);
    load_kv(1);
    for (int c = 0; c < nch; c++) {
        if (c + 1 < nch) CP_WAIT1(); else CP_WAIT0();
        __syncthreads();
        if (c + 2 < nch) load_kv(c + 2);
        const int s0 = c * 64;
        const bool active = !CAUSAL || (s0 <= m0 + wr0 + 15);
        if (active) {
            const uint32_t uKb = uK + (c % 3) * 8192;
            const uint32_t uVb = uV + (c % 3) * 8192;

            // ---- S = Q @ K^T ----
            float sacc[8][4] = {};
#pragma unroll
            for (int ks = 0; ks < 4; ks++) {
                const int gA = 2 * ks + ag_hi;
                const int gB = 2 * ks + bg_lo;
                uint32_t af[4];
                LDSM4(af[0], af[1], af[2], af[3], uQ + qro + ((gA ^ qrx) << 4));
                uint32_t bf[8][2];
#pragma unroll
                for (int p = 0; p < 4; p++)
                    LDSM4(bf[2*p][0], bf[2*p][1], bf[2*p+1][0], bf[2*p+1][1],
                          uKb + bro[p] + ((gB ^ brx[p]) << 4));
#pragma unroll
                for (int nf = 0; nf < 8; nf++)
                    MMA_F16(sacc[nf], af, bf[nf]);
            }

            // ---- scale + mask + online softmax ----
            const float SCL = 0.125f;
            const int t0g = m0 + wr0 + laneR;
            float rmax0 = -1e30f, rmax1 = -1e30f;
#pragma unroll
            for (int nf = 0; nf < 8; nf++) {
                int sg = s0 + nf * 8 + 2 * laneC;
                float v0 = sacc[nf][0] * SCL, v1 = sacc[nf][1] * SCL;
                float v2 = sacc[nf][2] * SCL, v3 = sacc[nf][3] * SCL;
                if (CAUSAL) {
                    if (sg     > t0g)     v0 = -1e30f;
                    if (sg + 1 > t0g)     v1 = -1e30f;
                    if (sg     > t0g + 8) v2 = -1e30f;
                    if (sg + 1 > t0g + 8) v3 = -1e30f;
                }
                sacc[nf][0] = v0; sacc[nf][1] = v1;
                sacc[nf][2] = v2; sacc[nf][3] = v3;
                rmax0 = fmaxf(rmax0, fmaxf(v0, v1));
                rmax1 = fmaxf(rmax1, fmaxf(v2, v3));
            }
            rmax0 = fmaxf(rmax0, __shfl_xor_sync(0xffffffffu, rmax0, 1));
            rmax0 = fmaxf(rmax0, __shfl_xor_sync(0xffffffffu, rmax0, 2));
            rmax1 = fmaxf(rmax1, __shfl_xor_sync(0xffffffffu, rmax1, 1));
            rmax1 = fmaxf(rmax1, __shfl_xor_sync(0xffffffffu, rmax1, 2));
            float mn0 = fmaxf(mr0, rmax0), mn1 = fmaxf(mr1, rmax1);
            float al0 = __expf(mr0 - mn0), al1 = __expf(mr1 - mn1);
            mr0 = mn0; mr1 = mn1;

            // exp -> P fragments directly in registers (half2 pairs)
            uint32_t ph[8][2];
            float rs0 = 0.f, rs1 = 0.f;
#pragma unroll
            for (int nf = 0; nf < 8; nf++) {
                float e0 = __expf(sacc[nf][0] - mn0);
                float e1 = __expf(sacc[nf][1] - mn0);
                float e2 = __expf(sacc[nf][2] - mn1);
                float e3 = __expf(sacc[nf][3] - mn1);
                rs0 += e0 + e1; rs1 += e2 + e3;
                ph[nf][0] = h2u(__floats2half2_rn(e0, e1));
                ph[nf][1] = h2u(__floats2half2_rn(e2, e3));
            }
            rs0 += __shfl_xor_sync(0xffffffffu, rs0, 1);
            rs0 += __shfl_xor_sync(0xffffffffu, rs0, 2);
            rs1 += __shfl_xor_sync(0xffffffffu, rs1, 1);
            rs1 += __shfl_xor_sync(0xffffffffu, rs1, 2);
            l0 = l0 * al0 + rs0;
            l1 = l1 * al1 + rs1;
#pragma unroll
            for (int nf = 0; nf < 8; nf++) {
                oacc[nf][0] *= al0; oacc[nf][1] *= al0;
                oacc[nf][2] *= al1; oacc[nf][3] *= al1;
            }

            // ---- O += P @ V (P from registers; no smem round-trip) ----
#pragma unroll
            for (int j = 0; j < 4; j++) {
                const int gB = 2 * j + bg_lo;
                uint32_t af[4] = { ph[2*j][0], ph[2*j][1], ph[2*j+1][0], ph[2*j+1][1] };
#pragma unroll
                for (int p = 0; p < 4; p++) {
                    uint32_t bf0[2], bf1[2];
                    LDSM4(bf0[0], bf0[1], bf1[0], bf1[1],
                          uVb + bro[p] + ((gB ^ brx[p]) << 4));
                    MMA_F16(oacc[2*p],     af, bf0);
                    MMA_F16(oacc[2*p + 1], af, bf1);
                }
            }
        }
    }

    const float inv0 = 1.f / l0, inv1 = 1.f / l1;
#pragma unroll
    for (int nf = 0; nf < 8; nf++) {
        int cc = nf * 8 + 2 * laneC;
        int r = wr0 + laneR;
        *(__half2*)(Op + (size_t)r * DM + cc) =
            __floats2half2_rn(oacc[nf][0] * inv0, oacc[nf][1] * inv0);
        *(__half2*)(Op + (size_t)(r + 8) * DM + cc) =
            __floats2half2_rn(oacc[nf][2] * inv1, oacc[nf][3] * inv1);
    }
}

// ---------------- prep: transposes->half + bias concats + memory->half ---------
struct PrepArgs {
    const float* s8[8]; __half* d8[8];
    const float* w1; __half* w1t;
    const float* w2; __half* w2t;
    const float* bq; const float* bk; const float* bv;
    const float* cbk; const float* cbv;
    float* b1; float* b2;
    const float* mem; __half* memh;
};
__global__ __launch_bounds__(256) void prep_all(PrepArgs p)
{
    __shared__ float t[32][33];
    const int idx = blockIdx.x;
    const int tx = threadIdx.x, ty = threadIdx.y;

    if (idx >= 4097) {   // memory fp32 -> half
        int j = idx - 4097;
        int base = j * 2048 + (ty * 32 + tx) * 8;
        float4 a = *(const float4*)(p.mem + base);
        float4 b = *(const float4*)(p.mem + base + 4);
        __half2 h0 = __floats2half2_rn(a.x, a.y);
        __half2 h1 = __floats2half2_rn(a.z, a.w);
        __half2 h2 = __floats2half2_rn(b.x, b.y);
        __half2 h3 = __floats2half2_rn(b.z, b.w);
        uint4 o;
        o.x = *(uint32_t*)&h0; o.y = *(uint32_t*)&h1;
        o.z = *(uint32_t*)&h2; o.w = *(uint32_t*)&h3;
        *(uint4*)(p.memh + base) = o;
        return;
    }

    const float* src; __half* dst; int R, C, bx, by;
    if (idx < 2048) {
        int m = idx >> 8, tt = idx & 255;
        src = p.s8[m]; dst = p.d8[m]; R = 512; C = 512;
        bx = tt & 15; by = tt >> 4;
    } else if (idx < 3072) {
        int tt = idx - 2048;
        src = p.w1; dst = p.w1t; R = 512; C = 2048;
        bx = tt & 63; by = tt >> 6;
    } else if (idx < 4096) {
        int tt = idx - 3072;
        src = p.w2; dst = p.w2t; R = 2048; C = 512;
        bx = tt & 15; by = tt >> 4;
    } else {
        int i = ty * 32 + tx;
#pragma unroll
        for (int j = 0; j < 2; j++) {
            int c = i + j * 256;
            p.b1[c] = p.bq[c]; p.b1[512 + c] = p.bk[c]; p.b1[1024 + c] = p.bv[c];
            p.b2[c] = p.cbk[c]; p.b2[512 + c] = p.cbv[c];
        }
        return;
    }
    int x = bx * 32 + tx, y = by * 32;
#pragma unroll
    for (int i = 0; i < 4; i++)
        t[ty + i * 8][tx] = src[(size_t)(y + ty + i * 8) * C + x];
    __syncthreads();
    int x2 = by * 32 + tx, y2 = bx * 32;
#pragma unroll
    for (int i = 0; i < 4; i++)
        dst[(size_t)(y2 + ty + i * 8) * R + x2] = __float2half(t[tx][ty + i * 8]);
}

// ---------------- LayerNorm (float4 in; half or float out) ---------------------
template<int HOUT>
__global__ __launch_bounds__(128) void ln_kernel(
    const float* __restrict__ x, const float* __restrict__ g,
    const float* __restrict__ b, void* __restrict__ outv)
{
    const int row = blockIdx.x;
    const int tid = threadIdx.x;
    float4 v = *(const float4*)(x + (size_t)row * DM + tid * 4);

    float s  = v.x + v.y + v.z + v.w;
    float s2 = v.x * v.x + v.y * v.y + v.z * v.z + v.w * v.w;
#pragma unroll
    for (int o = 16; o; o >>= 1) {
        s  += __shfl_down_sync(0xffffffffu, s,  o);
        s2 += __shfl_down_sync(0xffffffffu, s2, o);
    }
    __shared__ float rs[4], rs2[4];
    int wid = tid >> 5, lane = tid & 31;
    if (lane == 0) { rs[wid] = s; rs2[wid] = s2; }
    __syncthreads();
    if (tid == 0) {
        float a = rs[0] + rs[1] + rs[2] + rs[3];
        float a2 = rs2[0] + rs2[1] + rs2[2] + rs2[3];
        rs[0] = a; rs2[0] = a2;
    }
    __syncthreads();
    float mean = rs[0] * (1.0f / DM);
    float var  = rs2[0] * (1.0f / DM) - mean * mean;
    float inv  = rsqrtf(var + 1e-5f);

    float4 gg = *(const float4*)(g + tid * 4);
    float4 bb = *(const float4*)(b + tid * 4);
    float o0 = (v.x - mean) * inv * gg.x + bb.x;
    float o1 = (v.y - mean) * inv * gg.y + bb.y;
    float o2 = (v.z - mean) * inv * gg.z + bb.z;
    float o3 = (v.w - mean) * inv * gg.w + bb.w;
    if (HOUT) {
        __half* oh = (__half*)outv;
        __half2 h01 = __floats2half2_rn(o0, o1);
        __half2 h23 = __floats2half2_rn(o2, o3);
        uint2 u; u.x = *(uint32_t*)&h01; u.y = *(uint32_t*)&h23;
        *(uint2*)(oh + (size_t)row * DM + tid * 4) = u;
    } else {
        float* of = (float*)outv;
        *(float4*)(of + (size_t)row * DM + tid * 4) = make_float4(o0, o1, o2, o3);
    }
}

// ---------------- launch -------------------------------------------------------
extern "C" void kernel_launch(void* const* d_in, const int* in_sizes, int n_in,
                              void* d_out, int out_size)
{
    const float* tgt    = (const float*)d_in[0];
    const float* memory = (const float*)d_in[1];

    const size_t OW = (size_t)LAYER * DM * DM;
    const size_t OB = (size_t)LAYER * DM;
    const float* sa_wq = (const float*)d_in[4]  + OW;
    const float* sa_wk = (const float*)d_in[5]  + OW;
    const float* sa_wv = (const float*)d_in[6]  + OW;
    const float* sa_wo = (const float*)d_in[7]  + OW;
    const float* sa_bq = (const float*)d_in[8]  + OB;
    const float* sa_bk = (const float*)d_in[9]  + OB;
    const float* sa_bv = (const float*)d_in[10] + OB;
    const float* sa_bo = (const float*)d_in[11] + OB;
    const float* ca_wq = (const float*)d_in[12] + OW;
    const float* ca_wk = (const float*)d_in[13] + OW;
    const float* ca_wv = (const float*)d_in[14] + OW;
    const float* ca_wo = (const float*)d_in[15] + OW;
    const float* ca_bq = (const float*)d_in[16] + OB;
    const float* ca_bk = (const float*)d_in[17] + OB;
    const float* ca_bv = (const float*)d_in[18] + OB;
    const float* ca_bo = (const float*)d_in[19] + OB;
    const float* ff_w1 = (const float*)d_in[20] + (size_t)LAYER * DM * FFD;
    const float* ff_b1 = (const float*)d_in[21] + (size_t)LAYER * FFD;
    const float* ff_w2 = (const float*)d_in[22] + (size_t)LAYER * FFD * DM;
    const float* ff_b2 = (const float*)d_in[23] + OB;
    const float* ln_g  = (const float*)d_in[24];
    const float* ln_b  = (const float*)d_in[25];

    __half *nh_, *qh_, *qkvh_, *kvh_, *vth_, *vth2_, *ath_, *ffh_, *memh_, *wth_, *w1th_, *w2th_;
    float *x_, *bc1_, *bc2_;
    cudaGetSymbolAddress((void**)&nh_,   g_nh);
    cudaGetSymbolAddress((void**)&qh_,   g_qh);
    cudaGetSymbolAddress((void**)&qkvh_, g_qkvh);
    cudaGetSymbolAddress((void**)&kvh_,  g_kvh);
    cudaGetSymbolAddress((void**)&vth_,  g_vth);
    cudaGetSymbolAddress((void**)&vth2_, g_vth2);
    cudaGetSymbolAddress((void**)&ath_,  g_ath);
    cudaGetSymbolAddress((void**)&ffh_,  g_ffh);
    cudaGetSymbolAddress((void**)&memh_, g_memh);
    cudaGetSymbolAddress((void**)&wth_,  g_wth);
    cudaGetSymbolAddress((void**)&w1th_, g_w1th);
    cudaGetSymbolAddress((void**)&w2th_, g_w2th);
    cudaGetSymbolAddress((void**)&x_,    g_x);
    cudaGetSymbolAddress((void**)&bc1_,  g_bc1);
    cudaGetSymbolAddress((void**)&bc2_,  g_bc2);

    static cudaStream_t s_aux = nullptr;
    static cudaEvent_t evF = nullptr, evP = nullptr, evKV = nullptr;
    if (!s_aux) {
        cudaStreamCreateWithFlags(&s_aux, cudaStreamNonBlocking);
        cudaEventCreateWithFlags(&evF,  cudaEventDisableTiming);
        cudaEventCreateWithFlags(&evP,  cudaEventDisableTiming);
        cudaEventCreateWithFlags(&evKV, cudaEventDisableTiming);
    }

    const int S128 = 3 * (128 + 128) * 128;   // 98304
    const int S64  = 3 * (128 + 64)  * 128;   // 73728
    const int SFL  = 65536;
    cudaFuncSetAttribute(mma_gemm<128,0,1,1>, cudaFuncAttributeMaxDynamicSharedMemorySize, S128);
    cudaFuncSetAttribute(mma_gemm<128,1,1,0>, cudaFuncAttributeMaxDynamicSharedMemorySize, S128);
    cudaFuncSetAttribute(mma_gemm<64,0,1,0>,  cudaFuncAttributeMaxDynamicSharedMemorySize, S64);
    cudaFuncSetAttribute(mma_gemm<64,2,0,0>,  cudaFuncAttributeMaxDynamicSharedMemorySize, S64);
    cudaFuncSetAttribute(flash_attn<1>,       cudaFuncAttributeMaxDynamicSharedMemorySize, SFL);
    cudaFuncSetAttribute(flash_attn<0>,       cudaFuncAttributeMaxDynamicSharedMemorySize, SFL);

    const int M = BB * TT;   // 4096

    __half* wqkvT = wth_ + 0 * DM * DM;    // slots 0,1,2
    __half* woT   = wth_ + 3 * DM * DM;
    __half* cqT   = wth_ + 4 * DM * DM;
    __half* ckvT  = wth_ + 5 * DM * DM;    // slots 5,6
    __half* coT   = wth_ + 7 * DM * DM;

    PrepArgs pa;
    pa.s8[0]=sa_wq; pa.d8[0]=wth_ + 0*DM*DM;
    pa.s8[1]=sa_wk; pa.d8[1]=wth_ + 1*DM*DM;
    pa.s8[2]=sa_wv; pa.d8[2]=wth_ + 2*DM*DM;
    pa.s8[3]=sa_wo; pa.d8[3]=woT;
    pa.s8[4]=ca_wq; pa.d8[4]=cqT;
    pa.s8[5]=ca_wk; pa.d8[5]=wth_ + 5*DM*DM;
    pa.s8[6]=ca_wv; pa.d8[6]=wth_ + 6*DM*DM;
    pa.s8[7]=ca_wo; pa.d8[7]=coT;
    pa.w1 = ff_w1; pa.w1t = w1th_;
    pa.w2 = ff_w2; pa.w2t = w2th_;
    pa.bq = sa_bq; pa.bk = sa_bk; pa.bv = sa_bv;
    pa.cbk = ca_bk; pa.cbv = ca_bv;
    pa.b1 = bc1_; pa.b2 = bc2_;
    pa.mem = memory; pa.memh = memh_;

    // ---- fork: prep + CA-KV projection on aux stream ----
    cudaEventRecord(evF, 0);
    cudaStreamWaitEvent(s_aux, evF, 0);
    prep_all<<<4097 + (BB*SS*DM)/2048, dim3(32,8), 0, s_aux>>>(pa);
    cudaEventRecord(evP, s_aux);
    mma_gemm<128,0,1,1><<<dim3(8,64),256,S128,s_aux>>>(
        memh_,DM, ckvT,DM, bc2_,nullptr, kvh_,2*DM, DM, vth2_,512,BB*SS);
    cudaEventRecord(evKV, s_aux);

    // ---- main: self-attention: x = tgt + SA(LN(tgt)) ----
    ln_kernel<1><<<M, 128>>>(tgt, ln_g, ln_b, nh_);
    cudaStreamWaitEvent(0, evP, 0);
    mma_gemm<128,0,1,1><<<dim3(12,32),256,S128>>>(
        nh_,DM, wqkvT,DM, bc1_,nullptr, qkvh_,3*DM, DM, vth_,1024,M);
    flash_attn<1><<<dim3(4,64),256,SFL>>>(qkvh_,3*DM, qkvh_+DM,3*DM, vth_, ath_, TT);
    mma_gemm<64,2,0,0><<<dim3(8,32),256,S64>>>(
        ath_,DM, woT,DM, sa_bo,tgt, x_,DM, DM, nullptr,0,0);

    // ---- cross-attention: x += CA(LN(x), memory) ----
    ln_kernel<1><<<M, 128>>>(x_, ln_g, ln_b, nh_);
    mma_gemm<64,0,1,0><<<dim3(8,32),256,S64>>>(
        nh_,DM, cqT,DM, ca_bq,nullptr, qh_,DM, DM, nullptr,0,0);
    cudaStreamWaitEvent(0, evKV, 0);
    flash_attn<0><<<dim3(4,64),256,SFL>>>(qh_,DM, kvh_,2*DM, vth2_, ath_, SS);
    mma_gemm<64,2,0,0><<<dim3(8,32),256,S64>>>(
        ath_,DM, coT,DM, ca_bo,x_, x_,DM, DM, nullptr,0,0);

    // ---- FFN: x += W2 relu(W1 LN(x)) ----
    ln_kernel<1><<<M, 128>>>(x_, ln_g, ln_b, nh_);
    mma_gemm<128,1,1,0><<<dim3(16,32),256,S128>>>(
        nh_,DM,  w1th_,DM,  ff_b1,nullptr, ffh_,FFD, DM, nullptr,0,0);
    mma_gemm<64,2,0,0><<<dim3(8,32),256,S64>>>(
        ffh_,FFD, w2th_,FFD, ff_b2,x_, x_,DM, FFD, nullptr,0,0);

    // ---- final LN -> out ----
    ln_kernel<0><<<M, 128>>>(x_, ln_g, ln_b, (float*)d_out);
}